// round 7
// baseline (speedup 1.0000x reference)
#include <cuda_runtime.h>
#include <math.h>
#include <stdint.h>
#include <stddef.h>

typedef unsigned long long u64;

// Problem dims
#define BB    64
#define TT    512
#define EE    768
#define HH    512
#define G3    1536
#define NF    256
#define MALL  (BB*TT)          // 32768

// -------- recurrence persistent-kernel config --------
#define NBLK      128          // co-resident worker CTAs
#define REDS      784          // red stride: mod 32 == 16 -> conflict-free rd/wr
#define RSM_FLOATS (16*512 + 16*REDS)
#define RSM_BYTES  (RSM_FLOATS*4)   // 82944 B

// ----------------- device scratch (statics; no cudaMalloc allowed) ----------
__device__ float g_Gi[(size_t)MALL * G3];      // reused per GRU pass
__device__ float g_seq0[(size_t)MALL * HH];    // selector hist, later out1
__device__ float g_seq1[(size_t)MALL * HH];    // out0
__device__ float g_newemb[(size_t)MALL * EE];
__device__ float g_U[(size_t)MALL * (NF*5)];   // conv GEMM out (reused)
__device__ float g_WT[G3 * EE];                // transposed weights scratch
__device__ float g_h[2][BB * HH];              // hidden-state ping-pong
__device__ int   g_sel[BB * TT];
__device__ int   g_order[BB * TT];
__device__ int   g_nsel[BB];
__device__ float g_pooled[BB * 3 * NF];
__device__ unsigned g_bar4[4 * 32];            // per-b-tile barrier counters

// ----------------------------- f32x2 helpers --------------------------------
__device__ __forceinline__ void fma2(u64& d, u64 a, u64 b) {
    asm("fma.rn.f32x2 %0,%1,%2,%0;" : "+l"(d) : "l"(a), "l"(b));
}
__device__ __forceinline__ u64 add2(u64 a, u64 b) {
    u64 r; asm("add.rn.f32x2 %0,%1,%2;" : "=l"(r) : "l"(a), "l"(b)); return r;
}
__device__ __forceinline__ float2 unpk(u64 v) {
    float2 r; asm("mov.b64 {%0,%1},%2;" : "=f"(r.x), "=f"(r.y) : "l"(v)); return r;
}
__device__ __forceinline__ u64 dup2(unsigned v) {
    u64 r; asm("mov.b64 %0,{%1,%1};" : "=l"(r) : "r"(v)); return r;
}
__device__ __forceinline__ u64 shx16(u64 v) {
    unsigned lo = (unsigned)v, hi = (unsigned)(v >> 32);
    lo = __shfl_xor_sync(0xffffffffu, lo, 16);
    hi = __shfl_xor_sync(0xffffffffu, hi, 16);
    return ((u64)hi << 32) | (u64)lo;
}
// release/acquire barrier primitives
__device__ __forceinline__ unsigned ld_acq(const unsigned* p) {
    unsigned v;
    asm volatile("ld.acquire.gpu.global.u32 %0,[%1];" : "=r"(v) : "l"(p));
    return v;
}
__device__ __forceinline__ void red_rel(unsigned* p) {
    asm volatile("red.release.gpu.global.add.u32 [%0],1;" :: "l"(p));
}

// ---------------------------------------------------------------------------
__global__ void k_reset() {
    int i = blockIdx.x * blockDim.x + threadIdx.x;
    if (i < 4 * 32) g_bar4[i] = 0u;
    if (i < 2 * BB * HH) ((float*)g_h)[i] = 0.f;
}
__global__ void k_zero_pooled() {
    int i = blockIdx.x * blockDim.x + threadIdx.x;
    if (i < BB * 3 * NF) g_pooled[i] = 0.f;
}

// ---------------------------------------------------------------------------
// generic transpose: dst[C][R] = src[R][C]   (R, C multiples of 32)
// ---------------------------------------------------------------------------
__global__ void k_transpose(float* dst, const float* src, int R, int C) {
    __shared__ float tile[32][33];
    int c0 = blockIdx.x * 32, r0 = blockIdx.y * 32;
    int tx = threadIdx.x, ty = threadIdx.y;
    #pragma unroll
    for (int i = 0; i < 32; i += 8)
        tile[ty + i][tx] = src[(size_t)(r0 + ty + i) * C + c0 + tx];
    __syncthreads();
    #pragma unroll
    for (int i = 0; i < 32; i += 8)
        dst[(size_t)(c0 + ty + i) * R + r0 + tx] = tile[tx][ty + i];
}

// ---------------------------------------------------------------------------
// GEMM (f32x2): C[M][N] = A[M][K] @ BT[K][N] (+ bias[n]).
// 256x128 tile, 16-k slab, 256 threads, double-buffered smem.
// mode 0: always compute. mode 1: skip all-invalid tiles. mode 2: write zeros.
// ---------------------------------------------------------------------------
__global__ __launch_bounds__(256, 1)
void k_gemm(float* __restrict__ C, const float* __restrict__ A,
            const float* __restrict__ BT, const float* __restrict__ bias,
            int M, int N, int K, const int* __restrict__ nsel, int mode) {
    __shared__ float sA[2][16][256];
    __shared__ float sB[2][16][128];
    int tid = threadIdx.x;
    int bm = blockIdx.y * 256;
    int bn = blockIdx.x * 128;

    if (mode != 0) {
        int p0 = bm & 511;
        if (p0 >= nsel[bm >> 9]) {          // whole tile is zero-input
            if (mode == 2) {
                float4 z = make_float4(0.f, 0.f, 0.f, 0.f);
                for (int i = tid; i < 256 * 32; i += 256) {
                    int row = i >> 5, c4 = (i & 31) * 4;
                    *(float4*)(C + (size_t)(bm + row) * N + bn + c4) = z;
                }
            }
            return;
        }
    }

    int tm = (tid >> 4) * 16;
    int tn = tid & 15;

    float4 ra[4]; float4 rb[2];

    u64 acc[8][8];
    #pragma unroll
    for (int i = 0; i < 8; i++)
        #pragma unroll
        for (int s = 0; s < 8; s++) acc[i][s] = 0ull;

    #pragma unroll
    for (int i = 0; i < 4; i++) {
        int id = i * 256 + tid, r = id >> 2, kq = (id & 3) * 4;
        ra[i] = *(const float4*)(A + (size_t)(bm + r) * K + kq);
    }
    #pragma unroll
    for (int i = 0; i < 2; i++) {
        int id = i * 256 + tid, kk = id >> 5, nq = (id & 31) * 4;
        rb[i] = *(const float4*)(BT + (size_t)kk * N + bn + nq);
    }
    #pragma unroll
    for (int i = 0; i < 4; i++) {
        int id = i * 256 + tid, r = id >> 2, kq = (id & 3) * 4;
        sA[0][kq + 0][r] = ra[i].x; sA[0][kq + 1][r] = ra[i].y;
        sA[0][kq + 2][r] = ra[i].z; sA[0][kq + 3][r] = ra[i].w;
    }
    #pragma unroll
    for (int i = 0; i < 2; i++) {
        int id = i * 256 + tid, kk = id >> 5, nq = (id & 31) * 4;
        *(float4*)&sB[0][kk][nq] = rb[i];
    }
    __syncthreads();

    int nslab = K >> 4;
    for (int s = 0; s < nslab; s++) {
        int buf = s & 1;
        if (s + 1 < nslab) {
            int k0 = (s + 1) * 16;
            #pragma unroll
            for (int i = 0; i < 4; i++) {
                int id = i * 256 + tid, r = id >> 2, kq = (id & 3) * 4;
                ra[i] = *(const float4*)(A + (size_t)(bm + r) * K + k0 + kq);
            }
            #pragma unroll
            for (int i = 0; i < 2; i++) {
                int id = i * 256 + tid, kk = id >> 5, nq = (id & 31) * 4;
                rb[i] = *(const float4*)(BT + (size_t)(k0 + kk) * N + bn + nq);
            }
        }
        #pragma unroll
        for (int k = 0; k < 16; k++) {
            u64 a[8];
            *(ulonglong2*)&a[0] = *(const ulonglong2*)&sA[buf][k][tm];
            *(ulonglong2*)&a[2] = *(const ulonglong2*)&sA[buf][k][tm + 4];
            *(ulonglong2*)&a[4] = *(const ulonglong2*)&sA[buf][k][tm + 8];
            *(ulonglong2*)&a[6] = *(const ulonglong2*)&sA[buf][k][tm + 12];
            #pragma unroll
            for (int sn = 0; sn < 8; sn++) {
                unsigned bv = *(const unsigned*)&sB[buf][k][tn + 16 * sn];
                u64 b2 = dup2(bv);
                #pragma unroll
                for (int i = 0; i < 8; i++)
                    fma2(acc[i][sn], a[i], b2);
            }
        }
        if (s + 1 < nslab) {
            int nb = buf ^ 1;
            #pragma unroll
            for (int i = 0; i < 4; i++) {
                int id = i * 256 + tid, r = id >> 2, kq = (id & 3) * 4;
                sA[nb][kq + 0][r] = ra[i].x; sA[nb][kq + 1][r] = ra[i].y;
                sA[nb][kq + 2][r] = ra[i].z; sA[nb][kq + 3][r] = ra[i].w;
            }
            #pragma unroll
            for (int i = 0; i < 2; i++) {
                int id = i * 256 + tid, kk = id >> 5, nq = (id & 31) * 4;
                *(float4*)&sB[nb][kk][nq] = rb[i];
            }
            __syncthreads();
        }
    }
    #pragma unroll
    for (int i = 0; i < 8; i++) {
        size_t r0 = (size_t)(bm + tm + 2 * i) * N;
        size_t r1 = r0 + N;
        #pragma unroll
        for (int sn = 0; sn < 8; sn++) {
            int col = bn + tn + 16 * sn;
            float2 v = unpk(acc[i][sn]);
            float bv = bias ? bias[col] : 0.f;
            C[r0 + col] = v.x + bv;
            C[r1 + col] = v.y + bv;
        }
    }
}

// ---------------------------------------------------------------------------
// persistent GRU recurrence: 512 threads (4 warps/SMSP for latency hiding).
// grid = 128 CTAs (4 b-tiles x 32 j-tiles). Thread (jj=tid&15, kc=tid>>4)
// owns a 16-k chunk; weights register-resident (24 u64/thread).
// ---------------------------------------------------------------------------
__global__ __launch_bounds__(512, 1)
void k_recur(const float* __restrict__ Gi, float* __restrict__ hist,
             const float* __restrict__ Whh, const float* __restrict__ bhh,
             const int* __restrict__ nsel) {
    extern __shared__ float sm[];
    float* sh  = sm;               // [16 b][512]
    float* red = sm + 16 * 512;    // [16 b][REDS]: 16 warp x 3 gate x 16 jj
    int tid = threadIdx.x;
    int bt = blockIdx.x & 3, jt = blockIdx.x >> 2;
    int b0 = bt * 16, j0 = jt * 16;

    int jj = tid & 15;
    int kc = tid >> 4;             // 32 chunks of 16 k
    int k0 = kc * 16;
    int wi = tid >> 5;             // 16 warps
    int lane = tid & 31;
    int bb2 = tid >> 4;            // phase2 mapping (tid < 256)
    bool ph2 = tid < 256;
    int j2 = j0 + jj;
    int b2 = b0 + (bb2 & 15);

    // weights -> registers: 3 gates x 4 q x 2 u64 = 24 u64
    u64 w2[3][8];
    #pragma unroll
    for (int g = 0; g < 3; g++) {
        const float* wrow = Whh + (size_t)(g * 512 + j2) * 512;
        #pragma unroll
        for (int q = 0; q < 4; q++) {
            w2[g][2*q + 0] = *(const u64*)(wrow + k0 + 4*q);
            w2[g][2*q + 1] = *(const u64*)(wrow + k0 + 4*q + 2);
        }
    }
    float br = bhh[j2], bz = bhh[512 + j2], bn2 = bhh[1024 + j2];
    int lim = (nsel && ph2) ? nsel[b2] : TT;
    unsigned* barp = &g_bar4[bt * 32];

    for (int t = 0; t < TT; t++) {
        // prefetch Gi (independent of barrier; hides LDG behind poll)
        float gir = 0.f, giz = 0.f, gin = 0.f;
        if (ph2) {
            const float* gp = Gi + ((size_t)b2 * TT + t) * G3;
            gir = __ldcg(gp + j2);
            giz = __ldcg(gp + 512 + j2);
            gin = __ldcg(gp + 1024 + j2);
        }

        // wait for all 32 CTAs of this b-tile to have posted step t-1
        if (t > 0) {
            if (tid == 0) {
                unsigned tgt = 32u * (unsigned)t;
                while (ld_acq(barp) < tgt) { }
            }
            __syncthreads();
        }

        const float* hsrc = g_h[t & 1];
        #pragma unroll
        for (int i = 0; i < 4; i++) {
            int id = tid + i * 512;        // 0..2047 float4 slots
            int lb = id >> 7;
            int lk = (id & 127) * 4;
            float4 v = __ldcg((const float4*)(hsrc + (size_t)(b0 + lb) * HH + lk));
            *(float4*)&sh[lb * 512 + lk] = v;
        }
        __syncthreads();

        // phase1: partial dots over this thread's 16-k chunk, all 16 b
        #pragma unroll 1
        for (int b = 0; b < 16; b++) {
            const ulonglong2* hp = (const ulonglong2*)&sh[b * 512 + k0];
            u64 a0 = 0ull, a1 = 0ull, a2 = 0ull;
            #pragma unroll
            for (int q = 0; q < 4; q++) {
                ulonglong2 hv = hp[q];
                fma2(a0, hv.x, w2[0][2*q]); fma2(a0, hv.y, w2[0][2*q + 1]);
                fma2(a1, hv.x, w2[1][2*q]); fma2(a1, hv.y, w2[1][2*q + 1]);
                fma2(a2, hv.x, w2[2][2*q]); fma2(a2, hv.y, w2[2][2*q + 1]);
            }
            a0 = add2(a0, shx16(a0));
            a1 = add2(a1, shx16(a1));
            a2 = add2(a2, shx16(a2));
            if (lane < 16) {
                float2 f0 = unpk(a0), f1 = unpk(a1), f2 = unpk(a2);
                int base = b * REDS + wi * 48 + jj;
                red[base]      = f0.x + f0.y;
                red[base + 16] = f1.x + f1.y;
                red[base + 32] = f2.x + f2.y;
            }
        }
        __syncthreads();

        // phase2: gates for (b2, j2) by the first 256 threads
        float hn = 0.f, hold = 0.f;
        if (ph2) {
            float sr = br, sz = bz, sn = bn2;
            #pragma unroll
            for (int w = 0; w < 16; w++) {
                int base = (bb2 & 15) * REDS + w * 48 + jj;
                sr += red[base];
                sz += red[base + 16];
                sn += red[base + 32];
            }
            float r = 1.f / (1.f + expf(-(gir + sr)));
            float z = 1.f / (1.f + expf(-(giz + sz)));
            float n = tanhf(gin + r * sn);
            hold = sh[(bb2 & 15) * 512 + j2];
            float h1 = (1.f - z) * n + z * hold;
            bool valid = t < lim;
            hn = valid ? h1 : hold;
            g_h[(t + 1) & 1][b2 * HH + j2] = hn;
        }
        __syncthreads();
        if (tid == 0) red_rel(barp);   // release: covers all threads' stores

        // hist store off the inter-CTA critical path
        if (ph2) {
            bool valid = t < lim;
            hist[((size_t)b2 * TT + t) * HH + j2] = valid ? hn : 0.f;
        }
    }
}

// ---------------------------------------------------------------------------
__global__ void k_selargmax(const float* __restrict__ hist,
                            const float* __restrict__ Ws,
                            const float* __restrict__ bs) {
    int gw = (blockIdx.x * blockDim.x + threadIdx.x) >> 5;
    int lane = threadIdx.x & 31;
    if (gw >= BB * TT) return;
    const float* h = hist + (size_t)gw * HH;
    float l0 = 0.f, l1 = 0.f;
    #pragma unroll 4
    for (int jv = lane; jv < HH; jv += 32) {
        float hv = h[jv];
        l0 += hv * Ws[jv];
        l1 += hv * Ws[HH + jv];
    }
    #pragma unroll
    for (int o = 16; o; o >>= 1) {
        l0 += __shfl_down_sync(0xffffffffu, l0, o);
        l1 += __shfl_down_sync(0xffffffffu, l1, o);
    }
    if (lane == 0)
        g_sel[gw] = ((l1 + bs[1]) > (l0 + bs[0])) ? 1 : 0;
}

// ---------------------------------------------------------------------------
__global__ void k_fix(const int* __restrict__ mask) {
    int b = blockIdx.x;
    int lane = threadIdx.x;
    int len = 0;
    for (int t = lane; t < TT; t += 32) len += mask[b * TT + t];
    #pragma unroll
    for (int o = 16; o; o >>= 1) len += __shfl_down_sync(0xffffffffu, len, o);
    len = __shfl_sync(0xffffffffu, len, 0);
    int cnt = 0;
    for (int c = 0; c < TT; c += 32) {
        int t = c + lane;
        int s = g_sel[b * TT + t];
        if (t == 0) s = 1;
        if (t == len - 1) s = 1;
        if (t >= len) s = 0;
        unsigned bal = __ballot_sync(0xffffffffu, s);
        int pre = __popc(bal & ((1u << lane) - 1u));
        if (s) g_order[b * TT + cnt + pre] = t;
        cnt += __popc(bal);
    }
    if (lane == 0) g_nsel[b] = cnt;
}

// ---------------------------------------------------------------------------
__global__ void k_gather(const float* __restrict__ emb, float* __restrict__ dst) {
    int row = blockIdx.x;               // b*T + p
    int b = row >> 9, p = row & 511;
    float4 v = make_float4(0.f, 0.f, 0.f, 0.f);
    if (p < g_nsel[b]) {
        int t = g_order[row];
        v = ((const float4*)(emb + ((size_t)b * TT + t) * EE))[threadIdx.x];
    }
    ((float4*)(dst + (size_t)row * EE))[threadIdx.x] = v;
}

// ---------------------------------------------------------------------------
__global__ void k_pool(const float* __restrict__ U, const float* __restrict__ bc,
                       int kw, int Nn, int seg) {
    int b = blockIdx.x;
    int f = threadIdx.x;
    int tlim = TT - kw + 1;
    int t0 = blockIdx.y * 64;
    int t1 = t0 + 64 < tlim ? t0 + 64 : tlim;
    float bcv = bc[f];
    float m = 0.f;
    const float* Ub = U + (size_t)b * TT * Nn + (size_t)f * kw;
    for (int t = t0; t < t1; t++) {
        float s = bcv;
        #pragma unroll 5
        for (int dt = 0; dt < kw; dt++)
            s += Ub[(size_t)(t + dt) * Nn + dt];
        m = fmaxf(m, fmaxf(s, 0.f));
    }
    atomicMax((int*)&g_pooled[b * (3 * NF) + seg + f], __float_as_int(m));
}

// ---------------------------------------------------------------------------
__global__ void k_final(const float* __restrict__ Wo, const float* __restrict__ bo,
                        float* __restrict__ out) {
    __shared__ float redf[256];
    int b = blockIdx.x, tid = threadIdx.x;
    float s = 0.f;
    for (int f = tid; f < 3 * NF; f += 256)
        s += g_pooled[b * (3 * NF) + f] * Wo[f];
    redf[tid] = s;
    __syncthreads();
    for (int o = 128; o; o >>= 1) {
        if (tid < o) redf[tid] += redf[tid + o];
        __syncthreads();
    }
    if (tid == 0) out[b] = redf[0] + bo[0];
}

// ---------------------------------------------------------------------------
extern "C" void kernel_launch(void* const* d_in, const int* in_sizes, int n_in,
                              void* d_out, int out_size) {
    const float* emb   = (const float*)d_in[0];
    const int*   mask  = (const int*)  d_in[1];
    const float* Wih_c = (const float*)d_in[2];
    const float* Whh_c = (const float*)d_in[3];
    const float* bih_c = (const float*)d_in[4];
    const float* bhh_c = (const float*)d_in[5];
    const float* Ws    = (const float*)d_in[6];
    const float* bs    = (const float*)d_in[7];
    const float* Wih0  = (const float*)d_in[8];
    const float* Whh0  = (const float*)d_in[9];
    const float* bih0  = (const float*)d_in[10];
    const float* bhh0  = (const float*)d_in[11];
    const float* Wih1  = (const float*)d_in[12];
    const float* Whh1  = (const float*)d_in[13];
    const float* bih1  = (const float*)d_in[14];
    const float* bhh1  = (const float*)d_in[15];
    const float* Wc3   = (const float*)d_in[16];
    const float* bc3   = (const float*)d_in[17];
    const float* Wc4   = (const float*)d_in[18];
    const float* bc4   = (const float*)d_in[19];
    const float* Wc5   = (const float*)d_in[20];
    const float* bc5   = (const float*)d_in[21];
    const float* Wo    = (const float*)d_in[22];
    const float* bo    = (const float*)d_in[23];
    float* out = (float*)d_out;

    cudaFuncSetAttribute(k_recur, cudaFuncAttributeMaxDynamicSharedMemorySize,
                         RSM_BYTES);

    float *pGi, *pS0, *pS1, *pNe, *pU, *pWT;
    int* pNsel;
    cudaGetSymbolAddress((void**)&pGi,   g_Gi);
    cudaGetSymbolAddress((void**)&pS0,   g_seq0);
    cudaGetSymbolAddress((void**)&pS1,   g_seq1);
    cudaGetSymbolAddress((void**)&pNe,   g_newemb);
    cudaGetSymbolAddress((void**)&pU,    g_U);
    cudaGetSymbolAddress((void**)&pWT,   g_WT);
    cudaGetSymbolAddress((void**)&pNsel, g_nsel);

    dim3 t32x8(32, 8);

    // ---- selector GRU (exact fp32, full tiles) ----
    k_transpose<<<dim3(EE/32, G3/32), t32x8>>>(pWT, Wih_c, G3, EE);
    k_gemm<<<dim3(G3/128, MALL/256), 256>>>(pGi, emb, pWT, bih_c, MALL, G3, EE,
                                            nullptr, 0);
    k_reset<<<256, 256>>>();
    k_recur<<<NBLK, 512, RSM_BYTES>>>(pGi, pS0, Whh_c, bhh_c, nullptr);
    k_selargmax<<<(BB*TT*32 + 255)/256, 256>>>(pS0, Ws, bs);
    k_fix<<<BB, 32>>>(mask);
    k_gather<<<MALL, EE/4>>>(emb, pNe);

    // ---- layer 0 (skip all-invalid tiles, no write) ----
    k_transpose<<<dim3(EE/32, G3/32), t32x8>>>(pWT, Wih0, G3, EE);
    k_gemm<<<dim3(G3/128, MALL/256), 256>>>(pGi, pNe, pWT, bih0, MALL, G3, EE,
                                            pNsel, 1);
    k_reset<<<256, 256>>>();
    k_recur<<<NBLK, 512, RSM_BYTES>>>(pGi, pS1, Whh0, bhh0, pNsel);

    // ---- layer 1 ----
    k_transpose<<<dim3(HH/32, G3/32), t32x8>>>(pWT, Wih1, G3, HH);
    k_gemm<<<dim3(G3/128, MALL/256), 256>>>(pGi, pS1, pWT, bih1, MALL, G3, HH,
                                            pNsel, 1);
    k_reset<<<256, 256>>>();
    k_recur<<<NBLK, 512, RSM_BYTES>>>(pGi, pS0, Whh1, bhh1, pNsel);

    // ---- convs (GEMM + pool), kw = 3,4,5 (skip tiles -> zeros) ----
    k_zero_pooled<<<(BB*3*NF + 255)/256, 256>>>();

    k_transpose<<<dim3(HH/32, (NF*3)/32), t32x8>>>(pWT, Wc3, NF*3, HH);
    k_gemm<<<dim3((NF*3)/128, MALL/256), 256>>>(pU, pS0, pWT, nullptr, MALL,
                                                NF*3, HH, pNsel, 2);
    k_pool<<<dim3(BB, 8), NF>>>(pU, bc3, 3, NF*3, 0);

    k_transpose<<<dim3(HH/32, (NF*4)/32), t32x8>>>(pWT, Wc4, NF*4, HH);
    k_gemm<<<dim3((NF*4)/128, MALL/256), 256>>>(pU, pS0, pWT, nullptr, MALL,
                                                NF*4, HH, pNsel, 2);
    k_pool<<<dim3(BB, 8), NF>>>(pU, bc4, 4, NF*4, NF);

    k_transpose<<<dim3(HH/32, (NF*5)/32), t32x8>>>(pWT, Wc5, NF*5, HH);
    k_gemm<<<dim3((NF*5)/128, MALL/256), 256>>>(pU, pS0, pWT, nullptr, MALL,
                                                NF*5, HH, pNsel, 2);
    k_pool<<<dim3(BB, 8), NF>>>(pU, bc5, 5, NF*5, 2*NF);

    // ---- final projection ----
    k_final<<<BB, 256>>>(Wo, bo, out);
}

// round 8
// speedup vs baseline: 1.1850x; 1.1850x over previous
#include <cuda_runtime.h>
#include <math.h>
#include <stdint.h>
#include <stddef.h>

typedef unsigned long long u64;

// Problem dims
#define BB    64
#define TT    512
#define EE    768
#define HH    512
#define G3    1536
#define NF    256
#define MALL  (BB*TT)          // 32768

// -------- recurrence persistent-kernel config --------
#define NBLK      128          // co-resident worker CTAs
#define REDS      392          // red stride (mod 32 != 0 -> conflict-free)
#define RSM_FLOATS (16*512 + 16*REDS)
#define RSM_BYTES  (RSM_FLOATS*4)   // 57344 B

// ----------------- device scratch (statics; no cudaMalloc allowed) ----------
__device__ float g_Gi[(size_t)MALL * G3];      // reused per GRU pass
__device__ float g_seq0[(size_t)MALL * HH];    // selector hist, later out1
__device__ float g_seq1[(size_t)MALL * HH];    // out0
__device__ float g_newemb[(size_t)MALL * EE];
__device__ float g_U[(size_t)MALL * (NF*5)];   // conv GEMM out (reused)
__device__ float g_WT[G3 * EE];                // transposed weights scratch
__device__ float g_h[2][BB * HH];              // hidden-state ping-pong
__device__ int   g_sel[BB * TT];
__device__ int   g_order[BB * TT];
__device__ int   g_nsel[BB];
__device__ float g_pooled[BB * 3 * NF];
__device__ unsigned g_bar4[4 * 32];            // per-b-tile barrier counters

// ----------------------------- f32x2 helpers --------------------------------
__device__ __forceinline__ void fma2(u64& d, u64 a, u64 b) {
    asm("fma.rn.f32x2 %0,%1,%2,%0;" : "+l"(d) : "l"(a), "l"(b));
}
__device__ __forceinline__ u64 add2(u64 a, u64 b) {
    u64 r; asm("add.rn.f32x2 %0,%1,%2;" : "=l"(r) : "l"(a), "l"(b)); return r;
}
__device__ __forceinline__ float2 unpk(u64 v) {
    float2 r; asm("mov.b64 {%0,%1},%2;" : "=f"(r.x), "=f"(r.y) : "l"(v)); return r;
}
__device__ __forceinline__ u64 dup2(unsigned v) {
    u64 r; asm("mov.b64 %0,{%1,%1};" : "=l"(r) : "r"(v)); return r;
}
__device__ __forceinline__ u64 shx16(u64 v) {
    unsigned lo = (unsigned)v, hi = (unsigned)(v >> 32);
    lo = __shfl_xor_sync(0xffffffffu, lo, 16);
    hi = __shfl_xor_sync(0xffffffffu, hi, 16);
    return ((u64)hi << 32) | (u64)lo;
}
// release/acquire barrier primitives
__device__ __forceinline__ unsigned ld_acq(const unsigned* p) {
    unsigned v;
    asm volatile("ld.acquire.gpu.global.u32 %0,[%1];" : "=r"(v) : "l"(p));
    return v;
}
__device__ __forceinline__ void red_rel(unsigned* p) {
    asm volatile("red.release.gpu.global.add.u32 [%0],1;" :: "l"(p));
}

// ---------------------------------------------------------------------------
__global__ void k_reset() {
    int i = blockIdx.x * blockDim.x + threadIdx.x;
    if (i < 4 * 32) g_bar4[i] = 0u;
    if (i < 2 * BB * HH) ((float*)g_h)[i] = 0.f;
}
__global__ void k_zero_pooled() {
    int i = blockIdx.x * blockDim.x + threadIdx.x;
    if (i < BB * 3 * NF) g_pooled[i] = 0.f;
}

// ---------------------------------------------------------------------------
// generic transpose: dst[C][R] = src[R][C]   (R, C multiples of 32)
// ---------------------------------------------------------------------------
__global__ void k_transpose(float* dst, const float* src, int R, int C) {
    __shared__ float tile[32][33];
    int c0 = blockIdx.x * 32, r0 = blockIdx.y * 32;
    int tx = threadIdx.x, ty = threadIdx.y;
    #pragma unroll
    for (int i = 0; i < 32; i += 8)
        tile[ty + i][tx] = src[(size_t)(r0 + ty + i) * C + c0 + tx];
    __syncthreads();
    #pragma unroll
    for (int i = 0; i < 32; i += 8)
        dst[(size_t)(c0 + ty + i) * R + r0 + tx] = tile[tx][ty + i];
}

// ---------------------------------------------------------------------------
// GEMM (f32x2): C[M][N] = A[M][K] @ BT[K][N] (+ bias[n]).
// 256x128 tile, 16-k slab, 256 threads, double-buffered smem.
// mode 0: always compute. mode 1: skip all-invalid tiles. mode 2: write zeros.
// ---------------------------------------------------------------------------
__global__ __launch_bounds__(256, 1)
void k_gemm(float* __restrict__ C, const float* __restrict__ A,
            const float* __restrict__ BT, const float* __restrict__ bias,
            int M, int N, int K, const int* __restrict__ nsel, int mode) {
    __shared__ float sA[2][16][256];
    __shared__ float sB[2][16][128];
    int tid = threadIdx.x;
    int bm = blockIdx.y * 256;
    int bn = blockIdx.x * 128;

    if (mode != 0) {
        int p0 = bm & 511;
        if (p0 >= nsel[bm >> 9]) {          // whole tile is zero-input
            if (mode == 2) {
                float4 z = make_float4(0.f, 0.f, 0.f, 0.f);
                for (int i = tid; i < 256 * 32; i += 256) {
                    int row = i >> 5, c4 = (i & 31) * 4;
                    *(float4*)(C + (size_t)(bm + row) * N + bn + c4) = z;
                }
            }
            return;
        }
    }

    int tm = (tid >> 4) * 16;
    int tn = tid & 15;

    float4 ra[4]; float4 rb[2];

    u64 acc[8][8];
    #pragma unroll
    for (int i = 0; i < 8; i++)
        #pragma unroll
        for (int s = 0; s < 8; s++) acc[i][s] = 0ull;

    #pragma unroll
    for (int i = 0; i < 4; i++) {
        int id = i * 256 + tid, r = id >> 2, kq = (id & 3) * 4;
        ra[i] = *(const float4*)(A + (size_t)(bm + r) * K + kq);
    }
    #pragma unroll
    for (int i = 0; i < 2; i++) {
        int id = i * 256 + tid, kk = id >> 5, nq = (id & 31) * 4;
        rb[i] = *(const float4*)(BT + (size_t)kk * N + bn + nq);
    }
    #pragma unroll
    for (int i = 0; i < 4; i++) {
        int id = i * 256 + tid, r = id >> 2, kq = (id & 3) * 4;
        sA[0][kq + 0][r] = ra[i].x; sA[0][kq + 1][r] = ra[i].y;
        sA[0][kq + 2][r] = ra[i].z; sA[0][kq + 3][r] = ra[i].w;
    }
    #pragma unroll
    for (int i = 0; i < 2; i++) {
        int id = i * 256 + tid, kk = id >> 5, nq = (id & 31) * 4;
        *(float4*)&sB[0][kk][nq] = rb[i];
    }
    __syncthreads();

    int nslab = K >> 4;
    for (int s = 0; s < nslab; s++) {
        int buf = s & 1;
        if (s + 1 < nslab) {
            int k0 = (s + 1) * 16;
            #pragma unroll
            for (int i = 0; i < 4; i++) {
                int id = i * 256 + tid, r = id >> 2, kq = (id & 3) * 4;
                ra[i] = *(const float4*)(A + (size_t)(bm + r) * K + k0 + kq);
            }
            #pragma unroll
            for (int i = 0; i < 2; i++) {
                int id = i * 256 + tid, kk = id >> 5, nq = (id & 31) * 4;
                rb[i] = *(const float4*)(BT + (size_t)(k0 + kk) * N + bn + nq);
            }
        }
        #pragma unroll
        for (int k = 0; k < 16; k++) {
            u64 a[8];
            *(ulonglong2*)&a[0] = *(const ulonglong2*)&sA[buf][k][tm];
            *(ulonglong2*)&a[2] = *(const ulonglong2*)&sA[buf][k][tm + 4];
            *(ulonglong2*)&a[4] = *(const ulonglong2*)&sA[buf][k][tm + 8];
            *(ulonglong2*)&a[6] = *(const ulonglong2*)&sA[buf][k][tm + 12];
            #pragma unroll
            for (int sn = 0; sn < 8; sn++) {
                unsigned bv = *(const unsigned*)&sB[buf][k][tn + 16 * sn];
                u64 b2 = dup2(bv);
                #pragma unroll
                for (int i = 0; i < 8; i++)
                    fma2(acc[i][sn], a[i], b2);
            }
        }
        if (s + 1 < nslab) {
            int nb = buf ^ 1;
            #pragma unroll
            for (int i = 0; i < 4; i++) {
                int id = i * 256 + tid, r = id >> 2, kq = (id & 3) * 4;
                sA[nb][kq + 0][r] = ra[i].x; sA[nb][kq + 1][r] = ra[i].y;
                sA[nb][kq + 2][r] = ra[i].z; sA[nb][kq + 3][r] = ra[i].w;
            }
            #pragma unroll
            for (int i = 0; i < 2; i++) {
                int id = i * 256 + tid, kk = id >> 5, nq = (id & 31) * 4;
                *(float4*)&sB[nb][kk][nq] = rb[i];
            }
            __syncthreads();
        }
    }
    #pragma unroll
    for (int i = 0; i < 8; i++) {
        size_t r0 = (size_t)(bm + tm + 2 * i) * N;
        size_t r1 = r0 + N;
        #pragma unroll
        for (int sn = 0; sn < 8; sn++) {
            int col = bn + tn + 16 * sn;
            float2 v = unpk(acc[i][sn]);
            float bv = bias ? bias[col] : 0.f;
            C[r0 + col] = v.x + bv;
            C[r1 + col] = v.y + bv;
        }
    }
}

// ---------------------------------------------------------------------------
// persistent GRU recurrence (R5 structure) + maxlim early exit.
// grid = 128 CTAs (4 b-tiles x 32 j-tiles), 256 threads.
// All CTAs of a b-tile group compute the same maxlim from nsel, run only
// maxlim steps, then bulk-zero hist for t in [maxlim, TT).
// ---------------------------------------------------------------------------
__global__ __launch_bounds__(256, 1)
void k_recur(const float* __restrict__ Gi, float* __restrict__ hist,
             const float* __restrict__ Whh, const float* __restrict__ bhh,
             const int* __restrict__ nsel) {
    extern __shared__ float sm[];
    float* sh  = sm;               // [16 b][512]
    float* red = sm + 16 * 512;    // [16 b][REDS]: 8 warp x 3 gate x 16 jj
    int tid = threadIdx.x;
    int bt = blockIdx.x & 3, jt = blockIdx.x >> 2;
    int b0 = bt * 16, j0 = jt * 16;

    int jj = tid & 15;
    int kc = tid >> 4;             // 16 chunks of 32 k
    int k0 = kc * 32;
    int qx = (kc & 1) << 2;        // bank-conflict-avoiding permutation
    int wi = tid >> 5;
    int lane = tid & 31;
    int bb2 = tid >> 4;
    int j2 = j0 + jj;
    int b2 = b0 + bb2;

    // weights -> registers, ordered to match permuted h-read sequence
    u64 w2[3][16];
    #pragma unroll
    for (int g = 0; g < 3; g++) {
        const float* wrow = Whh + (size_t)(g * 512 + j0 + jj) * 512;
        #pragma unroll
        for (int q = 0; q < 8; q++) {
            int keff = k0 + 4 * (q ^ qx);
            w2[g][2*q + 0] = *(const u64*)(wrow + keff);
            w2[g][2*q + 1] = *(const u64*)(wrow + keff + 2);
        }
    }
    float br = bhh[j2], bz = bhh[512 + j2], bn2 = bhh[1024 + j2];
    int lim = TT, maxlim = TT;
    if (nsel) {
        lim = nsel[b2];
        maxlim = 0;
        #pragma unroll
        for (int b = 0; b < 16; b++) {
            int v = nsel[b0 + b];
            maxlim = v > maxlim ? v : maxlim;
        }
    }
    unsigned* barp = &g_bar4[bt * 32];

    for (int t = 0; t < maxlim; t++) {
        // prefetch Gi (independent of barrier; hides LDG behind poll)
        const float* gp = Gi + ((size_t)b2 * TT + t) * G3;
        float gir = __ldcg(gp + j2);
        float giz = __ldcg(gp + 512 + j2);
        float gin = __ldcg(gp + 1024 + j2);

        // wait for all 32 CTAs of this b-tile to have posted step t-1
        if (t > 0) {
            if (tid == 0) {
                unsigned tgt = 32u * (unsigned)t;
                while (ld_acq(barp) < tgt) { }
            }
            __syncthreads();
        }

        const float* hsrc = g_h[t & 1];
        #pragma unroll
        for (int i = 0; i < 8; i++) {
            int id = tid + i * 256;
            int lb = id >> 7;
            int lk = (id & 127) * 4;
            float4 v = __ldcg((const float4*)(hsrc + (size_t)(b0 + lb) * HH + lk));
            *(float4*)&sh[lb * 512 + lk] = v;
        }
        __syncthreads();

        // phase1: partial dots over this thread's 32-k chunk, all 16 b
        #pragma unroll 1
        for (int b = 0; b < 16; b++) {
            const ulonglong2* hp = (const ulonglong2*)&sh[b * 512 + k0];
            u64 a0 = 0ull, a1 = 0ull, a2 = 0ull;
            #pragma unroll
            for (int q = 0; q < 8; q++) {
                ulonglong2 hv = hp[q ^ qx];
                fma2(a0, hv.x, w2[0][2*q]); fma2(a0, hv.y, w2[0][2*q + 1]);
                fma2(a1, hv.x, w2[1][2*q]); fma2(a1, hv.y, w2[1][2*q + 1]);
                fma2(a2, hv.x, w2[2][2*q]); fma2(a2, hv.y, w2[2][2*q + 1]);
            }
            a0 = add2(a0, shx16(a0));
            a1 = add2(a1, shx16(a1));
            a2 = add2(a2, shx16(a2));
            if (lane < 16) {
                float2 f0 = unpk(a0), f1 = unpk(a1), f2 = unpk(a2);
                int base = b * REDS + wi * 48 + jj;
                red[base]      = f0.x + f0.y;
                red[base + 16] = f1.x + f1.y;
                red[base + 32] = f2.x + f2.y;
            }
        }
        __syncthreads();

        // phase2: gates for (b2, j2)
        float sr = br, sz = bz, sn = bn2;
        #pragma unroll
        for (int w = 0; w < 8; w++) {
            int base = bb2 * REDS + w * 48 + jj;
            sr += red[base];
            sz += red[base + 16];
            sn += red[base + 32];
        }
        float r = 1.f / (1.f + expf(-(gir + sr)));
        float z = 1.f / (1.f + expf(-(giz + sz)));
        float n = tanhf(gin + r * sn);
        float hold = sh[bb2 * 512 + j2];
        float hn = (1.f - z) * n + z * hold;
        bool valid = t < lim;
        g_h[(t + 1) & 1][b2 * HH + j2] = valid ? hn : hold;
        hist[((size_t)b2 * TT + t) * HH + j2] = valid ? hn : 0.f;

        __syncthreads();
        if (tid == 0) red_rel(barp);   // release: covers all threads' stores
    }

    // bulk-zero hist for the skipped steps t in [maxlim, TT)
    for (int t = maxlim; t < TT; t++)
        hist[((size_t)b2 * TT + t) * HH + j2] = 0.f;
}

// ---------------------------------------------------------------------------
__global__ void k_selargmax(const float* __restrict__ hist,
                            const float* __restrict__ Ws,
                            const float* __restrict__ bs) {
    int gw = (blockIdx.x * blockDim.x + threadIdx.x) >> 5;
    int lane = threadIdx.x & 31;
    if (gw >= BB * TT) return;
    const float* h = hist + (size_t)gw * HH;
    float l0 = 0.f, l1 = 0.f;
    #pragma unroll 4
    for (int jv = lane; jv < HH; jv += 32) {
        float hv = h[jv];
        l0 += hv * Ws[jv];
        l1 += hv * Ws[HH + jv];
    }
    #pragma unroll
    for (int o = 16; o; o >>= 1) {
        l0 += __shfl_down_sync(0xffffffffu, l0, o);
        l1 += __shfl_down_sync(0xffffffffu, l1, o);
    }
    if (lane == 0)
        g_sel[gw] = ((l1 + bs[1]) > (l0 + bs[0])) ? 1 : 0;
}

// ---------------------------------------------------------------------------
__global__ void k_fix(const int* __restrict__ mask) {
    int b = blockIdx.x;
    int lane = threadIdx.x;
    int len = 0;
    for (int t = lane; t < TT; t += 32) len += mask[b * TT + t];
    #pragma unroll
    for (int o = 16; o; o >>= 1) len += __shfl_down_sync(0xffffffffu, len, o);
    len = __shfl_sync(0xffffffffu, len, 0);
    int cnt = 0;
    for (int c = 0; c < TT; c += 32) {
        int t = c + lane;
        int s = g_sel[b * TT + t];
        if (t == 0) s = 1;
        if (t == len - 1) s = 1;
        if (t >= len) s = 0;
        unsigned bal = __ballot_sync(0xffffffffu, s);
        int pre = __popc(bal & ((1u << lane) - 1u));
        if (s) g_order[b * TT + cnt + pre] = t;
        cnt += __popc(bal);
    }
    if (lane == 0) g_nsel[b] = cnt;
}

// ---------------------------------------------------------------------------
__global__ void k_gather(const float* __restrict__ emb, float* __restrict__ dst) {
    int row = blockIdx.x;               // b*T + p
    int b = row >> 9, p = row & 511;
    float4 v = make_float4(0.f, 0.f, 0.f, 0.f);
    if (p < g_nsel[b]) {
        int t = g_order[row];
        v = ((const float4*)(emb + ((size_t)b * TT + t) * EE))[threadIdx.x];
    }
    ((float4*)(dst + (size_t)row * EE))[threadIdx.x] = v;
}

// ---------------------------------------------------------------------------
__global__ void k_pool(const float* __restrict__ U, const float* __restrict__ bc,
                       int kw, int Nn, int seg) {
    int b = blockIdx.x;
    int f = threadIdx.x;
    int tlim = TT - kw + 1;
    int t0 = blockIdx.y * 64;
    int t1 = t0 + 64 < tlim ? t0 + 64 : tlim;
    float bcv = bc[f];
    float m = 0.f;
    const float* Ub = U + (size_t)b * TT * Nn + (size_t)f * kw;
    for (int t = t0; t < t1; t++) {
        float s = bcv;
        #pragma unroll 5
        for (int dt = 0; dt < kw; dt++)
            s += Ub[(size_t)(t + dt) * Nn + dt];
        m = fmaxf(m, fmaxf(s, 0.f));
    }
    atomicMax((int*)&g_pooled[b * (3 * NF) + seg + f], __float_as_int(m));
}

// ---------------------------------------------------------------------------
__global__ void k_final(const float* __restrict__ Wo, const float* __restrict__ bo,
                        float* __restrict__ out) {
    __shared__ float redf[256];
    int b = blockIdx.x, tid = threadIdx.x;
    float s = 0.f;
    for (int f = tid; f < 3 * NF; f += 256)
        s += g_pooled[b * (3 * NF) + f] * Wo[f];
    redf[tid] = s;
    __syncthreads();
    for (int o = 128; o; o >>= 1) {
        if (tid < o) redf[tid] += redf[tid + o];
        __syncthreads();
    }
    if (tid == 0) out[b] = redf[0] + bo[0];
}

// ---------------------------------------------------------------------------
extern "C" void kernel_launch(void* const* d_in, const int* in_sizes, int n_in,
                              void* d_out, int out_size) {
    const float* emb   = (const float*)d_in[0];
    const int*   mask  = (const int*)  d_in[1];
    const float* Wih_c = (const float*)d_in[2];
    const float* Whh_c = (const float*)d_in[3];
    const float* bih_c = (const float*)d_in[4];
    const float* bhh_c = (const float*)d_in[5];
    const float* Ws    = (const float*)d_in[6];
    const float* bs    = (const float*)d_in[7];
    const float* Wih0  = (const float*)d_in[8];
    const float* Whh0  = (const float*)d_in[9];
    const float* bih0  = (const float*)d_in[10];
    const float* bhh0  = (const float*)d_in[11];
    const float* Wih1  = (const float*)d_in[12];
    const float* Whh1  = (const float*)d_in[13];
    const float* bih1  = (const float*)d_in[14];
    const float* bhh1  = (const float*)d_in[15];
    const float* Wc3   = (const float*)d_in[16];
    const float* bc3   = (const float*)d_in[17];
    const float* Wc4   = (const float*)d_in[18];
    const float* bc4   = (const float*)d_in[19];
    const float* Wc5   = (const float*)d_in[20];
    const float* bc5   = (const float*)d_in[21];
    const float* Wo    = (const float*)d_in[22];
    const float* bo    = (const float*)d_in[23];
    float* out = (float*)d_out;

    cudaFuncSetAttribute(k_recur, cudaFuncAttributeMaxDynamicSharedMemorySize,
                         RSM_BYTES);

    float *pGi, *pS0, *pS1, *pNe, *pU, *pWT;
    int* pNsel;
    cudaGetSymbolAddress((void**)&pGi,   g_Gi);
    cudaGetSymbolAddress((void**)&pS0,   g_seq0);
    cudaGetSymbolAddress((void**)&pS1,   g_seq1);
    cudaGetSymbolAddress((void**)&pNe,   g_newemb);
    cudaGetSymbolAddress((void**)&pU,    g_U);
    cudaGetSymbolAddress((void**)&pWT,   g_WT);
    cudaGetSymbolAddress((void**)&pNsel, g_nsel);

    dim3 t32x8(32, 8);

    // ---- selector GRU (exact fp32, full tiles) ----
    k_transpose<<<dim3(EE/32, G3/32), t32x8>>>(pWT, Wih_c, G3, EE);
    k_gemm<<<dim3(G3/128, MALL/256), 256>>>(pGi, emb, pWT, bih_c, MALL, G3, EE,
                                            nullptr, 0);
    k_reset<<<256, 256>>>();
    k_recur<<<NBLK, 256, RSM_BYTES>>>(pGi, pS0, Whh_c, bhh_c, nullptr);
    k_selargmax<<<(BB*TT*32 + 255)/256, 256>>>(pS0, Ws, bs);
    k_fix<<<BB, 32>>>(mask);
    k_gather<<<MALL, EE/4>>>(emb, pNe);

    // ---- layer 0 (skip all-invalid tiles; recur stops at maxlim) ----
    k_transpose<<<dim3(EE/32, G3/32), t32x8>>>(pWT, Wih0, G3, EE);
    k_gemm<<<dim3(G3/128, MALL/256), 256>>>(pGi, pNe, pWT, bih0, MALL, G3, EE,
                                            pNsel, 1);
    k_reset<<<256, 256>>>();
    k_recur<<<NBLK, 256, RSM_BYTES>>>(pGi, pS1, Whh0, bhh0, pNsel);

    // ---- layer 1 ----
    k_transpose<<<dim3(HH/32, G3/32), t32x8>>>(pWT, Wih1, G3, HH);
    k_gemm<<<dim3(G3/128, MALL/256), 256>>>(pGi, pS1, pWT, bih1, MALL, G3, HH,
                                            pNsel, 1);
    k_reset<<<256, 256>>>();
    k_recur<<<NBLK, 256, RSM_BYTES>>>(pGi, pS0, Whh1, bhh1, pNsel);

    // ---- convs (GEMM + pool), kw = 3,4,5 (skip tiles -> zeros) ----
    k_zero_pooled<<<(BB*3*NF + 255)/256, 256>>>();

    k_transpose<<<dim3(HH/32, (NF*3)/32), t32x8>>>(pWT, Wc3, NF*3, HH);
    k_gemm<<<dim3((NF*3)/128, MALL/256), 256>>>(pU, pS0, pWT, nullptr, MALL,
                                                NF*3, HH, pNsel, 2);
    k_pool<<<dim3(BB, 8), NF>>>(pU, bc3, 3, NF*3, 0);

    k_transpose<<<dim3(HH/32, (NF*4)/32), t32x8>>>(pWT, Wc4, NF*4, HH);
    k_gemm<<<dim3((NF*4)/128, MALL/256), 256>>>(pU, pS0, pWT, nullptr, MALL,
                                                NF*4, HH, pNsel, 2);
    k_pool<<<dim3(BB, 8), NF>>>(pU, bc4, 4, NF*4, NF);

    k_transpose<<<dim3(HH/32, (NF*5)/32), t32x8>>>(pWT, Wc5, NF*5, HH);
    k_gemm<<<dim3((NF*5)/128, MALL/256), 256>>>(pU, pS0, pWT, nullptr, MALL,
                                                NF*5, HH, pNsel, 2);
    k_pool<<<dim3(BB, 8), NF>>>(pU, bc5, 5, NF*5, 2*NF);

    // ---- final projection ----
    k_final<<<BB, 256>>>(Wo, bo, out);
}

// round 9
// speedup vs baseline: 1.5099x; 1.2742x over previous
#include <cuda_runtime.h>
#include <cuda_bf16.h>
#include <math.h>
#include <stdint.h>
#include <stddef.h>

typedef unsigned long long u64;

// Problem dims
#define BB    64
#define TT    512
#define EE    768
#define HH    512
#define G3    1536
#define NF    256
#define MALL  (BB*TT)          // 32768

// -------- recurrence persistent-kernel config --------
#define NBLK      128
#define REDS      392
#define RSM_FLOATS (16*512 + 16*REDS)
#define RSM_BYTES  (RSM_FLOATS*4)   // 57344 B

// -------- bf16 tensor GEMM config --------
#define SAS   40                  // smem row stride in bf16 (80 B, ldmatrix conflict-free)
#define OPSZ  (128*SAS*2)         // bytes per operand plane (10240)
#define BSM_BYTES (8*OPSZ)        // 2 bufs x 4 planes = 81920 B

// ----------------- device scratch (statics; no cudaMalloc allowed) ----------
__device__ float g_Gi[(size_t)MALL * G3];
__device__ float g_seq0[(size_t)MALL * HH];
__device__ float g_seq1[(size_t)MALL * HH];
__device__ float g_newemb[(size_t)MALL * EE];
__device__ float g_U[(size_t)MALL * (NF*5)];
__device__ float g_WT[G3 * EE];                // selector transpose only
__device__ float g_h[2][BB * HH];
__device__ int   g_sel[BB * TT];
__device__ int   g_order[BB * TT];
__device__ int   g_nsel[BB];
__device__ float g_pooled[BB * 3 * NF];
__device__ unsigned g_bar4[4 * 32];
// bf16 split buffers
__device__ __nv_bfloat16 g_Ah[(size_t)MALL * EE];
__device__ __nv_bfloat16 g_Al[(size_t)MALL * EE];
__device__ __nv_bfloat16 g_Wh[G3 * EE];
__device__ __nv_bfloat16 g_Wl[G3 * EE];

// ----------------------------- f32x2 helpers --------------------------------
__device__ __forceinline__ void fma2(u64& d, u64 a, u64 b) {
    asm("fma.rn.f32x2 %0,%1,%2,%0;" : "+l"(d) : "l"(a), "l"(b));
}
__device__ __forceinline__ u64 add2(u64 a, u64 b) {
    u64 r; asm("add.rn.f32x2 %0,%1,%2;" : "=l"(r) : "l"(a), "l"(b)); return r;
}
__device__ __forceinline__ float2 unpk(u64 v) {
    float2 r; asm("mov.b64 {%0,%1},%2;" : "=f"(r.x), "=f"(r.y) : "l"(v)); return r;
}
__device__ __forceinline__ u64 dup2(unsigned v) {
    u64 r; asm("mov.b64 %0,{%1,%1};" : "=l"(r) : "r"(v)); return r;
}
__device__ __forceinline__ u64 shx16(u64 v) {
    unsigned lo = (unsigned)v, hi = (unsigned)(v >> 32);
    lo = __shfl_xor_sync(0xffffffffu, lo, 16);
    hi = __shfl_xor_sync(0xffffffffu, hi, 16);
    return ((u64)hi << 32) | (u64)lo;
}
__device__ __forceinline__ unsigned ld_acq(const unsigned* p) {
    unsigned v;
    asm volatile("ld.acquire.gpu.global.u32 %0,[%1];" : "=r"(v) : "l"(p));
    return v;
}
__device__ __forceinline__ void red_rel(unsigned* p) {
    asm volatile("red.release.gpu.global.add.u32 [%0],1;" :: "l"(p));
}
// ----------------------------- mma helpers ----------------------------------
__device__ __forceinline__ void ldm4(unsigned* r, unsigned addr) {
    asm volatile("ldmatrix.sync.aligned.m8n8.x4.shared.b16 {%0,%1,%2,%3}, [%4];"
                 : "=r"(r[0]), "=r"(r[1]), "=r"(r[2]), "=r"(r[3]) : "r"(addr));
}
__device__ __forceinline__ void mma16816(float* c, const unsigned* a,
                                         unsigned b0, unsigned b1) {
    asm volatile("mma.sync.aligned.m16n8k16.row.col.f32.bf16.bf16.f32 "
                 "{%0,%1,%2,%3}, {%4,%5,%6,%7}, {%8,%9}, {%0,%1,%2,%3};"
                 : "+f"(c[0]), "+f"(c[1]), "+f"(c[2]), "+f"(c[3])
                 : "r"(a[0]), "r"(a[1]), "r"(a[2]), "r"(a[3]), "r"(b0), "r"(b1));
}

// ---------------------------------------------------------------------------
__global__ void k_reset() {
    int i = blockIdx.x * blockDim.x + threadIdx.x;
    if (i < 4 * 32) g_bar4[i] = 0u;
    if (i < 2 * BB * HH) ((float*)g_h)[i] = 0.f;
}
__global__ void k_zero_pooled() {
    int i = blockIdx.x * blockDim.x + threadIdx.x;
    if (i < BB * 3 * NF) g_pooled[i] = 0.f;
}
// split fp32 -> bf16 hi + bf16 lo (residual)
__global__ void k_split(const float* __restrict__ src,
                        __nv_bfloat16* __restrict__ hi,
                        __nv_bfloat16* __restrict__ lo, size_t n) {
    size_t i = (size_t)blockIdx.x * blockDim.x + threadIdx.x;
    if (i >= n) return;
    float x = src[i];
    __nv_bfloat16 h = __float2bfloat16(x);
    hi[i] = h;
    lo[i] = __float2bfloat16(x - __bfloat162float(h));
}

// ---------------------------------------------------------------------------
// generic transpose (selector weights only)
// ---------------------------------------------------------------------------
__global__ void k_transpose(float* dst, const float* src, int R, int C) {
    __shared__ float tile[32][33];
    int c0 = blockIdx.x * 32, r0 = blockIdx.y * 32;
    int tx = threadIdx.x, ty = threadIdx.y;
    #pragma unroll
    for (int i = 0; i < 32; i += 8)
        tile[ty + i][tx] = src[(size_t)(r0 + ty + i) * C + c0 + tx];
    __syncthreads();
    #pragma unroll
    for (int i = 0; i < 32; i += 8)
        dst[(size_t)(c0 + ty + i) * R + r0 + tx] = tile[tx][ty + i];
}

// ---------------------------------------------------------------------------
// fp32 f32x2 GEMM (selector only): C = A @ BT + bias. 256x128 tile.
// ---------------------------------------------------------------------------
__global__ __launch_bounds__(256, 1)
void k_gemm(float* __restrict__ C, const float* __restrict__ A,
            const float* __restrict__ BT, const float* __restrict__ bias,
            int M, int N, int K) {
    __shared__ float sA[2][16][256];
    __shared__ float sB[2][16][128];
    int tid = threadIdx.x;
    int bm = blockIdx.y * 256;
    int bn = blockIdx.x * 128;
    int tm = (tid >> 4) * 16;
    int tn = tid & 15;

    float4 ra[4]; float4 rb[2];
    u64 acc[8][8];
    #pragma unroll
    for (int i = 0; i < 8; i++)
        #pragma unroll
        for (int s = 0; s < 8; s++) acc[i][s] = 0ull;

    #pragma unroll
    for (int i = 0; i < 4; i++) {
        int id = i * 256 + tid, r = id >> 2, kq = (id & 3) * 4;
        ra[i] = *(const float4*)(A + (size_t)(bm + r) * K + kq);
    }
    #pragma unroll
    for (int i = 0; i < 2; i++) {
        int id = i * 256 + tid, kk = id >> 5, nq = (id & 31) * 4;
        rb[i] = *(const float4*)(BT + (size_t)kk * N + bn + nq);
    }
    #pragma unroll
    for (int i = 0; i < 4; i++) {
        int id = i * 256 + tid, r = id >> 2, kq = (id & 3) * 4;
        sA[0][kq + 0][r] = ra[i].x; sA[0][kq + 1][r] = ra[i].y;
        sA[0][kq + 2][r] = ra[i].z; sA[0][kq + 3][r] = ra[i].w;
    }
    #pragma unroll
    for (int i = 0; i < 2; i++) {
        int id = i * 256 + tid, kk = id >> 5, nq = (id & 31) * 4;
        *(float4*)&sB[0][kk][nq] = rb[i];
    }
    __syncthreads();

    int nslab = K >> 4;
    for (int s = 0; s < nslab; s++) {
        int buf = s & 1;
        if (s + 1 < nslab) {
            int k0 = (s + 1) * 16;
            #pragma unroll
            for (int i = 0; i < 4; i++) {
                int id = i * 256 + tid, r = id >> 2, kq = (id & 3) * 4;
                ra[i] = *(const float4*)(A + (size_t)(bm + r) * K + k0 + kq);
            }
            #pragma unroll
            for (int i = 0; i < 2; i++) {
                int id = i * 256 + tid, kk = id >> 5, nq = (id & 31) * 4;
                rb[i] = *(const float4*)(BT + (size_t)(k0 + kk) * N + bn + nq);
            }
        }
        #pragma unroll
        for (int k = 0; k < 16; k++) {
            u64 a[8];
            *(ulonglong2*)&a[0] = *(const ulonglong2*)&sA[buf][k][tm];
            *(ulonglong2*)&a[2] = *(const ulonglong2*)&sA[buf][k][tm + 4];
            *(ulonglong2*)&a[4] = *(const ulonglong2*)&sA[buf][k][tm + 8];
            *(ulonglong2*)&a[6] = *(const ulonglong2*)&sA[buf][k][tm + 12];
            #pragma unroll
            for (int sn = 0; sn < 8; sn++) {
                unsigned bv = *(const unsigned*)&sB[buf][k][tn + 16 * sn];
                u64 b2 = dup2(bv);
                #pragma unroll
                for (int i = 0; i < 8; i++)
                    fma2(acc[i][sn], a[i], b2);
            }
        }
        if (s + 1 < nslab) {
            int nb = buf ^ 1;
            #pragma unroll
            for (int i = 0; i < 4; i++) {
                int id = i * 256 + tid, r = id >> 2, kq = (id & 3) * 4;
                sA[nb][kq + 0][r] = ra[i].x; sA[nb][kq + 1][r] = ra[i].y;
                sA[nb][kq + 2][r] = ra[i].z; sA[nb][kq + 3][r] = ra[i].w;
            }
            #pragma unroll
            for (int i = 0; i < 2; i++) {
                int id = i * 256 + tid, kk = id >> 5, nq = (id & 31) * 4;
                *(float4*)&sB[nb][kk][nq] = rb[i];
            }
            __syncthreads();
        }
    }
    #pragma unroll
    for (int i = 0; i < 8; i++) {
        size_t r0 = (size_t)(bm + tm + 2 * i) * N;
        size_t r1 = r0 + N;
        #pragma unroll
        for (int sn = 0; sn < 8; sn++) {
            int col = bn + tn + 16 * sn;
            float2 v = unpk(acc[i][sn]);
            float bv = bias ? bias[col] : 0.f;
            C[r0 + col] = v.x + bv;
            C[r1 + col] = v.y + bv;
        }
    }
}

// ---------------------------------------------------------------------------
// split-bf16 tensor-core GEMM: C[M][N] = (Ah+Al)[M][K] @ (Bh+Bl)[N][K]^T + bias
// 3-term: Ah*Bh + Ah*Bl + Al*Bh (fp32 accum). 128x128 tile, 8 warps
// (4m x 2n, warp tile 32x64), k-slab 32, double-buffered smem.
// mode 0 compute always; 1 skip all-invalid 128-row tiles; 2 write zeros.
// ---------------------------------------------------------------------------
__global__ __launch_bounds__(256, 1)
void k_bgemm(float* __restrict__ C,
             const __nv_bfloat16* __restrict__ Ah, const __nv_bfloat16* __restrict__ Al,
             const __nv_bfloat16* __restrict__ Bh, const __nv_bfloat16* __restrict__ Bl,
             const float* __restrict__ bias,
             int M, int N, int K, const int* __restrict__ nsel, int mode) {
    extern __shared__ __nv_bfloat16 sdyn[];   // [buf][plane][128*SAS]
    int tid = threadIdx.x;
    int bm = blockIdx.y * 128;
    int bn = blockIdx.x * 128;

    if (mode != 0) {
        int p0 = bm & 511;
        if (p0 >= nsel[bm >> 9]) {
            if (mode == 2) {
                float4 z = make_float4(0.f, 0.f, 0.f, 0.f);
                for (int i = tid; i < 128 * 32; i += 256) {
                    int row = i >> 5, c4 = (i & 31) * 4;
                    *(float4*)(C + (size_t)(bm + row) * N + bn + c4) = z;
                }
            }
            return;
        }
    }

    int wid = tid >> 5, lane = tid & 31;
    int m0 = (wid & 3) * 32, n0 = (wid >> 2) * 64;
    unsigned sbase = (unsigned)__cvta_generic_to_shared(sdyn);

    const __nv_bfloat16* gp[4];
    gp[0] = Ah; gp[1] = Al; gp[2] = Bh; gp[3] = Bl;
    int rbase[4] = {bm, bm, bn, bn};
    int id0 = tid * 2, id1 = tid * 2 + 1;
    int row0 = id0 >> 2, seg0 = (id0 & 3) * 8;
    int row1 = id1 >> 2, seg1 = (id1 & 3) * 8;

    float acc[2][8][4];
    #pragma unroll
    for (int i = 0; i < 2; i++)
        #pragma unroll
        for (int j = 0; j < 8; j++)
            #pragma unroll
            for (int c = 0; c < 4; c++) acc[i][j][c] = 0.f;

    uint4 rg[4][2];
    #pragma unroll
    for (int p = 0; p < 4; p++) {
        rg[p][0] = *(const uint4*)(gp[p] + (size_t)(rbase[p] + row0) * K + seg0);
        rg[p][1] = *(const uint4*)(gp[p] + (size_t)(rbase[p] + row1) * K + seg1);
    }
    #pragma unroll
    for (int p = 0; p < 4; p++) {
        __nv_bfloat16* sp = sdyn + (size_t)p * (128 * SAS);
        *(uint4*)&sp[row0 * SAS + seg0] = rg[p][0];
        *(uint4*)&sp[row1 * SAS + seg1] = rg[p][1];
    }
    __syncthreads();

    // ldmatrix lane-address components
    int alr = lane & 15, alh = (lane >> 4) * 16;                  // A
    int bro = ((lane >> 4) & 1) * 8 + (lane & 7);                 // B row in n16
    int bko = ((lane >> 3) & 1) * 16;                             // B k byte off

    int nslab = K >> 5;
    for (int sl = 0; sl < nslab; sl++) {
        int buf = sl & 1;
        if (sl + 1 < nslab) {
            int k0 = (sl + 1) * 32;
            #pragma unroll
            for (int p = 0; p < 4; p++) {
                rg[p][0] = *(const uint4*)(gp[p] + (size_t)(rbase[p] + row0) * K + k0 + seg0);
                rg[p][1] = *(const uint4*)(gp[p] + (size_t)(rbase[p] + row1) * K + k0 + seg1);
            }
        }
        unsigned base = sbase + (unsigned)buf * (4 * OPSZ);
        #pragma unroll
        for (int kk = 0; kk < 32; kk += 16) {
            unsigned ah[2][4], al[2][4], bh[4][4], bl[4][4];
            #pragma unroll
            for (int i = 0; i < 2; i++) {
                unsigned ra = base + ((m0 + 16 * i + alr) * SAS + kk) * 2 + alh;
                ldm4(ah[i], ra);
                ldm4(al[i], ra + OPSZ);
            }
            #pragma unroll
            for (int g = 0; g < 4; g++) {
                unsigned rb = base + 2 * OPSZ + ((n0 + 16 * g + bro) * SAS + kk) * 2 + bko;
                ldm4(bh[g], rb);
                ldm4(bl[g], rb + OPSZ);
            }
            #pragma unroll
            for (int i = 0; i < 2; i++)
                #pragma unroll
                for (int g = 0; g < 4; g++)
                    #pragma unroll
                    for (int h = 0; h < 2; h++) {
                        int j = 2 * g + h;
                        mma16816(acc[i][j], ah[i], bh[g][2*h], bh[g][2*h + 1]);
                        mma16816(acc[i][j], ah[i], bl[g][2*h], bl[g][2*h + 1]);
                        mma16816(acc[i][j], al[i], bh[g][2*h], bh[g][2*h + 1]);
                    }
        }
        if (sl + 1 < nslab) {
            int nb = buf ^ 1;
            #pragma unroll
            for (int p = 0; p < 4; p++) {
                __nv_bfloat16* sp = sdyn + (size_t)(nb * 4 + p) * (128 * SAS);
                *(uint4*)&sp[row0 * SAS + seg0] = rg[p][0];
                *(uint4*)&sp[row1 * SAS + seg1] = rg[p][1];
            }
            __syncthreads();
        }
    }
    // epilogue
    #pragma unroll
    for (int i = 0; i < 2; i++) {
        int rA = bm + m0 + 16 * i + (lane >> 2);
        #pragma unroll
        for (int j = 0; j < 8; j++) {
            int col = bn + n0 + 8 * j + 2 * (lane & 3);
            float b0v = 0.f, b1v = 0.f;
            if (bias) { b0v = bias[col]; b1v = bias[col + 1]; }
            *(float2*)(C + (size_t)rA * N + col) =
                make_float2(acc[i][j][0] + b0v, acc[i][j][1] + b1v);
            *(float2*)(C + (size_t)(rA + 8) * N + col) =
                make_float2(acc[i][j][2] + b0v, acc[i][j][3] + b1v);
        }
    }
}

// ---------------------------------------------------------------------------
// persistent GRU recurrence (unchanged from R7: 256 thr + maxlim early exit)
// ---------------------------------------------------------------------------
__global__ __launch_bounds__(256, 1)
void k_recur(const float* __restrict__ Gi, float* __restrict__ hist,
             const float* __restrict__ Whh, const float* __restrict__ bhh,
             const int* __restrict__ nsel) {
    extern __shared__ float sm[];
    float* sh  = sm;
    float* red = sm + 16 * 512;
    int tid = threadIdx.x;
    int bt = blockIdx.x & 3, jt = blockIdx.x >> 2;
    int b0 = bt * 16, j0 = jt * 16;

    int jj = tid & 15;
    int kc = tid >> 4;
    int k0 = kc * 32;
    int qx = (kc & 1) << 2;
    int wi = tid >> 5;
    int lane = tid & 31;
    int bb2 = tid >> 4;
    int j2 = j0 + jj;
    int b2 = b0 + bb2;

    u64 w2[3][16];
    #pragma unroll
    for (int g = 0; g < 3; g++) {
        const float* wrow = Whh + (size_t)(g * 512 + j0 + jj) * 512;
        #pragma unroll
        for (int q = 0; q < 8; q++) {
            int keff = k0 + 4 * (q ^ qx);
            w2[g][2*q + 0] = *(const u64*)(wrow + keff);
            w2[g][2*q + 1] = *(const u64*)(wrow + keff + 2);
        }
    }
    float br = bhh[j2], bz = bhh[512 + j2], bn2 = bhh[1024 + j2];
    int lim = TT, maxlim = TT;
    if (nsel) {
        lim = nsel[b2];
        maxlim = 0;
        #pragma unroll
        for (int b = 0; b < 16; b++) {
            int v = nsel[b0 + b];
            maxlim = v > maxlim ? v : maxlim;
        }
    }
    unsigned* barp = &g_bar4[bt * 32];

    for (int t = 0; t < maxlim; t++) {
        const float* gp = Gi + ((size_t)b2 * TT + t) * G3;
        float gir = __ldcg(gp + j2);
        float giz = __ldcg(gp + 512 + j2);
        float gin = __ldcg(gp + 1024 + j2);

        if (t > 0) {
            if (tid == 0) {
                unsigned tgt = 32u * (unsigned)t;
                while (ld_acq(barp) < tgt) { }
            }
            __syncthreads();
        }

        const float* hsrc = g_h[t & 1];
        #pragma unroll
        for (int i = 0; i < 8; i++) {
            int id = tid + i * 256;
            int lb = id >> 7;
            int lk = (id & 127) * 4;
            float4 v = __ldcg((const float4*)(hsrc + (size_t)(b0 + lb) * HH + lk));
            *(float4*)&sh[lb * 512 + lk] = v;
        }
        __syncthreads();

        #pragma unroll 1
        for (int b = 0; b < 16; b++) {
            const ulonglong2* hp = (const ulonglong2*)&sh[b * 512 + k0];
            u64 a0 = 0ull, a1 = 0ull, a2 = 0ull;
            #pragma unroll
            for (int q = 0; q < 8; q++) {
                ulonglong2 hv = hp[q ^ qx];
                fma2(a0, hv.x, w2[0][2*q]); fma2(a0, hv.y, w2[0][2*q + 1]);
                fma2(a1, hv.x, w2[1][2*q]); fma2(a1, hv.y, w2[1][2*q + 1]);
                fma2(a2, hv.x, w2[2][2*q]); fma2(a2, hv.y, w2[2][2*q + 1]);
            }
            a0 = add2(a0, shx16(a0));
            a1 = add2(a1, shx16(a1));
            a2 = add2(a2, shx16(a2));
            if (lane < 16) {
                float2 f0 = unpk(a0), f1 = unpk(a1), f2 = unpk(a2);
                int base = b * REDS + wi * 48 + jj;
                red[base]      = f0.x + f0.y;
                red[base + 16] = f1.x + f1.y;
                red[base + 32] = f2.x + f2.y;
            }
        }
        __syncthreads();

        float sr = br, sz = bz, sn = bn2;
        #pragma unroll
        for (int w = 0; w < 8; w++) {
            int base = bb2 * REDS + w * 48 + jj;
            sr += red[base];
            sz += red[base + 16];
            sn += red[base + 32];
        }
        float r = 1.f / (1.f + expf(-(gir + sr)));
        float z = 1.f / (1.f + expf(-(giz + sz)));
        float n = tanhf(gin + r * sn);
        float hold = sh[bb2 * 512 + j2];
        float hn = (1.f - z) * n + z * hold;
        bool valid = t < lim;
        g_h[(t + 1) & 1][b2 * HH + j2] = valid ? hn : hold;
        hist[((size_t)b2 * TT + t) * HH + j2] = valid ? hn : 0.f;

        __syncthreads();
        if (tid == 0) red_rel(barp);
    }

    for (int t = maxlim; t < TT; t++)
        hist[((size_t)b2 * TT + t) * HH + j2] = 0.f;
}

// ---------------------------------------------------------------------------
__global__ void k_selargmax(const float* __restrict__ hist,
                            const float* __restrict__ Ws,
                            const float* __restrict__ bs) {
    int gw = (blockIdx.x * blockDim.x + threadIdx.x) >> 5;
    int lane = threadIdx.x & 31;
    if (gw >= BB * TT) return;
    const float* h = hist + (size_t)gw * HH;
    float l0 = 0.f, l1 = 0.f;
    #pragma unroll 4
    for (int jv = lane; jv < HH; jv += 32) {
        float hv = h[jv];
        l0 += hv * Ws[jv];
        l1 += hv * Ws[HH + jv];
    }
    #pragma unroll
    for (int o = 16; o; o >>= 1) {
        l0 += __shfl_down_sync(0xffffffffu, l0, o);
        l1 += __shfl_down_sync(0xffffffffu, l1, o);
    }
    if (lane == 0)
        g_sel[gw] = ((l1 + bs[1]) > (l0 + bs[0])) ? 1 : 0;
}

// ---------------------------------------------------------------------------
__global__ void k_fix(const int* __restrict__ mask) {
    int b = blockIdx.x;
    int lane = threadIdx.x;
    int len = 0;
    for (int t = lane; t < TT; t += 32) len += mask[b * TT + t];
    #pragma unroll
    for (int o = 16; o; o >>= 1) len += __shfl_down_sync(0xffffffffu, len, o);
    len = __shfl_sync(0xffffffffu, len, 0);
    int cnt = 0;
    for (int c = 0; c < TT; c += 32) {
        int t = c + lane;
        int s = g_sel[b * TT + t];
        if (t == 0) s = 1;
        if (t == len - 1) s = 1;
        if (t >= len) s = 0;
        unsigned bal = __ballot_sync(0xffffffffu, s);
        int pre = __popc(bal & ((1u << lane) - 1u));
        if (s) g_order[b * TT + cnt + pre] = t;
        cnt += __popc(bal);
    }
    if (lane == 0) g_nsel[b] = cnt;
}

// ---------------------------------------------------------------------------
__global__ void k_gather(const float* __restrict__ emb, float* __restrict__ dst) {
    int row = blockIdx.x;
    int b = row >> 9, p = row & 511;
    float4 v = make_float4(0.f, 0.f, 0.f, 0.f);
    if (p < g_nsel[b]) {
        int t = g_order[row];
        v = ((const float4*)(emb + ((size_t)b * TT + t) * EE))[threadIdx.x];
    }
    ((float4*)(dst + (size_t)row * EE))[threadIdx.x] = v;
}

// ---------------------------------------------------------------------------
__global__ void k_pool(const float* __restrict__ U, const float* __restrict__ bc,
                       int kw, int Nn, int seg) {
    int b = blockIdx.x;
    int f = threadIdx.x;
    int tlim = TT - kw + 1;
    int t0 = blockIdx.y * 64;
    int t1 = t0 + 64 < tlim ? t0 + 64 : tlim;
    float bcv = bc[f];
    float m = 0.f;
    const float* Ub = U + (size_t)b * TT * Nn + (size_t)f * kw;
    for (int t = t0; t < t1; t++) {
        float s = bcv;
        #pragma unroll 5
        for (int dt = 0; dt < kw; dt++)
            s += Ub[(size_t)(t + dt) * Nn + dt];
        m = fmaxf(m, fmaxf(s, 0.f));
    }
    atomicMax((int*)&g_pooled[b * (3 * NF) + seg + f], __float_as_int(m));
}

// ---------------------------------------------------------------------------
__global__ void k_final(const float* __restrict__ Wo, const float* __restrict__ bo,
                        float* __restrict__ out) {
    __shared__ float redf[256];
    int b = blockIdx.x, tid = threadIdx.x;
    float s = 0.f;
    for (int f = tid; f < 3 * NF; f += 256)
        s += g_pooled[b * (3 * NF) + f] * Wo[f];
    redf[tid] = s;
    __syncthreads();
    for (int o = 128; o; o >>= 1) {
        if (tid < o) redf[tid] += redf[tid + o];
        __syncthreads();
    }
    if (tid == 0) out[b] = redf[0] + bo[0];
}

// ---------------------------------------------------------------------------
extern "C" void kernel_launch(void* const* d_in, const int* in_sizes, int n_in,
                              void* d_out, int out_size) {
    const float* emb   = (const float*)d_in[0];
    const int*   mask  = (const int*)  d_in[1];
    const float* Wih_c = (const float*)d_in[2];
    const float* Whh_c = (const float*)d_in[3];
    const float* bih_c = (const float*)d_in[4];
    const float* bhh_c = (const float*)d_in[5];
    const float* Ws    = (const float*)d_in[6];
    const float* bs    = (const float*)d_in[7];
    const float* Wih0  = (const float*)d_in[8];
    const float* Whh0  = (const float*)d_in[9];
    const float* bih0  = (const float*)d_in[10];
    const float* bhh0  = (const float*)d_in[11];
    const float* Wih1  = (const float*)d_in[12];
    const float* Whh1  = (const float*)d_in[13];
    const float* bih1  = (const float*)d_in[14];
    const float* bhh1  = (const float*)d_in[15];
    const float* Wc3   = (const float*)d_in[16];
    const float* bc3   = (const float*)d_in[17];
    const float* Wc4   = (const float*)d_in[18];
    const float* bc4   = (const float*)d_in[19];
    const float* Wc5   = (const float*)d_in[20];
    const float* bc5   = (const float*)d_in[21];
    const float* Wo    = (const float*)d_in[22];
    const float* bo    = (const float*)d_in[23];
    float* out = (float*)d_out;

    cudaFuncSetAttribute(k_recur, cudaFuncAttributeMaxDynamicSharedMemorySize,
                         RSM_BYTES);
    cudaFuncSetAttribute(k_bgemm, cudaFuncAttributeMaxDynamicSharedMemorySize,
                         BSM_BYTES);

    float *pGi, *pS0, *pS1, *pNe, *pU, *pWT;
    int* pNsel;
    __nv_bfloat16 *pAh, *pAl, *pWh, *pWl;
    cudaGetSymbolAddress((void**)&pGi,   g_Gi);
    cudaGetSymbolAddress((void**)&pS0,   g_seq0);
    cudaGetSymbolAddress((void**)&pS1,   g_seq1);
    cudaGetSymbolAddress((void**)&pNe,   g_newemb);
    cudaGetSymbolAddress((void**)&pU,    g_U);
    cudaGetSymbolAddress((void**)&pWT,   g_WT);
    cudaGetSymbolAddress((void**)&pNsel, g_nsel);
    cudaGetSymbolAddress((void**)&pAh,   g_Ah);
    cudaGetSymbolAddress((void**)&pAl,   g_Al);
    cudaGetSymbolAddress((void**)&pWh,   g_Wh);
    cudaGetSymbolAddress((void**)&pWl,   g_Wl);

    dim3 t32x8(32, 8);
    const size_t nAE = (size_t)MALL * EE;
    const size_t nAH = (size_t)MALL * HH;

    // ---- selector GRU (exact fp32 f32x2 path) ----
    k_transpose<<<dim3(EE/32, G3/32), t32x8>>>(pWT, Wih_c, G3, EE);
    k_gemm<<<dim3(G3/128, MALL/256), 256>>>(pGi, emb, pWT, bih_c, MALL, G3, EE);
    k_reset<<<256, 256>>>();
    k_recur<<<NBLK, 256, RSM_BYTES>>>(pGi, pS0, Whh_c, bhh_c, nullptr);
    k_selargmax<<<(BB*TT*32 + 255)/256, 256>>>(pS0, Ws, bs);
    k_fix<<<BB, 32>>>(mask);
    k_gather<<<MALL, EE/4>>>(emb, pNe);

    // ---- layer 0 (split-bf16 tensor GEMM, tile-skip) ----
    k_split<<<(int)((nAE + 255)/256), 256>>>(pNe, pAh, pAl, nAE);
    k_split<<<(G3*EE + 255)/256, 256>>>(Wih0, pWh, pWl, (size_t)G3*EE);
    k_bgemm<<<dim3(G3/128, MALL/128), 256, BSM_BYTES>>>(
        pGi, pAh, pAl, pWh, pWl, bih0, MALL, G3, EE, pNsel, 1);
    k_reset<<<256, 256>>>();
    k_recur<<<NBLK, 256, RSM_BYTES>>>(pGi, pS1, Whh0, bhh0, pNsel);

    // ---- layer 1 ----
    k_split<<<(int)((nAH + 255)/256), 256>>>(pS1, pAh, pAl, nAH);
    k_split<<<(G3*HH + 255)/256, 256>>>(Wih1, pWh, pWl, (size_t)G3*HH);
    k_bgemm<<<dim3(G3/128, MALL/128), 256, BSM_BYTES>>>(
        pGi, pAh, pAl, pWh, pWl, bih1, MALL, G3, HH, pNsel, 1);
    k_reset<<<256, 256>>>();
    k_recur<<<NBLK, 256, RSM_BYTES>>>(pGi, pS0, Whh1, bhh1, pNsel);

    // ---- convs (split-bf16 GEMM + pool) ----
    k_zero_pooled<<<(BB*3*NF + 255)/256, 256>>>();
    k_split<<<(int)((nAH + 255)/256), 256>>>(pS0, pAh, pAl, nAH);

    k_split<<<(NF*3*HH + 255)/256, 256>>>(Wc3, pWh, pWl, (size_t)NF*3*HH);
    k_bgemm<<<dim3((NF*3)/128, MALL/128), 256, BSM_BYTES>>>(
        pU, pAh, pAl, pWh, pWl, nullptr, MALL, NF*3, HH, pNsel, 2);
    k_pool<<<dim3(BB, 8), NF>>>(pU, bc3, 3, NF*3, 0);

    k_split<<<(NF*4*HH + 255)/256, 256>>>(Wc4, pWh, pWl, (size_t)NF*4*HH);
    k_bgemm<<<dim3((NF*4)/128, MALL/128), 256, BSM_BYTES>>>(
        pU, pAh, pAl, pWh, pWl, nullptr, MALL, NF*4, HH, pNsel, 2);
    k_pool<<<dim3(BB, 8), NF>>>(pU, bc4, 4, NF*4, NF);

    k_split<<<(NF*5*HH + 255)/256, 256>>>(Wc5, pWh, pWl, (size_t)NF*5*HH);
    k_bgemm<<<dim3((NF*5)/128, MALL/128), 256, BSM_BYTES>>>(
        pU, pAh, pAl, pWh, pWl, nullptr, MALL, NF*5, HH, pNsel, 2);
    k_pool<<<dim3(BB, 8), NF>>>(pU, bc5, 5, NF*5, 2*NF);

    // ---- final projection ----
    k_final<<<BB, 256>>>(Wo, bo, out);
}

// round 10
// speedup vs baseline: 1.7064x; 1.1301x over previous
#include <cuda_runtime.h>
#include <cuda_bf16.h>
#include <math.h>
#include <stdint.h>
#include <stddef.h>

typedef unsigned long long u64;

// Problem dims
#define BB    64
#define TT    512
#define EE    768
#define HH    512
#define G3    1536
#define NF    256
#define MALL  (BB*TT)          // 32768

// -------- recurrence persistent-kernel config (selector, f32x2 path) --------
#define NBLK      128
#define REDS      392
#define RSM_FLOATS (16*512 + 16*REDS)
#define RSM_BYTES  (RSM_FLOATS*4)   // 57344 B

// -------- mma recurrence config --------
#define SWS     520                 // smem row stride in bf16 (1040 B)
#define MSM_W   0                   // Wh slice [48][SWS]
#define MSM_WL  (48*SWS)
#define MSM_HH  (96*SWS)
#define MSM_HL  (112*SWS)
#define MSM_BF  (128*SWS)           // total bf16 elems (66560)
#define MRED_STR 52
#define MSM_BYTES (MSM_BF*2 + 4*16*MRED_STR*4)   // 146432 B

// -------- bf16 tensor GEMM config --------
#define SAS   40
#define OPSZ  (128*SAS*2)
#define BSM_BYTES (8*OPSZ)          // 81920 B

// ----------------- device scratch (statics; no cudaMalloc allowed) ----------
__device__ float g_Gi[(size_t)MALL * G3];
__device__ float g_seq0[(size_t)MALL * HH];
__device__ float g_seq1[(size_t)MALL * HH];
__device__ float g_newemb[(size_t)MALL * EE];
__device__ float g_U[(size_t)MALL * (NF*5)];
__device__ float g_WT[G3 * EE];                // selector transpose only
__device__ float g_h[2][BB * HH];
__device__ int   g_sel[BB * TT];
__device__ int   g_order[BB * TT];
__device__ int   g_nsel[BB];
__device__ float g_pooled[BB * 3 * NF];
__device__ unsigned g_bar4[4 * 32];
// bf16 split buffers
__device__ __nv_bfloat16 g_Ah[(size_t)MALL * EE];
__device__ __nv_bfloat16 g_Al[(size_t)MALL * EE];
__device__ __nv_bfloat16 g_Wh[G3 * EE];
__device__ __nv_bfloat16 g_Wl[G3 * EE];

// ----------------------------- f32x2 helpers --------------------------------
__device__ __forceinline__ void fma2(u64& d, u64 a, u64 b) {
    asm("fma.rn.f32x2 %0,%1,%2,%0;" : "+l"(d) : "l"(a), "l"(b));
}
__device__ __forceinline__ u64 add2(u64 a, u64 b) {
    u64 r; asm("add.rn.f32x2 %0,%1,%2;" : "=l"(r) : "l"(a), "l"(b)); return r;
}
__device__ __forceinline__ float2 unpk(u64 v) {
    float2 r; asm("mov.b64 {%0,%1},%2;" : "=f"(r.x), "=f"(r.y) : "l"(v)); return r;
}
__device__ __forceinline__ u64 dup2(unsigned v) {
    u64 r; asm("mov.b64 %0,{%1,%1};" : "=l"(r) : "r"(v)); return r;
}
__device__ __forceinline__ u64 shx16(u64 v) {
    unsigned lo = (unsigned)v, hi = (unsigned)(v >> 32);
    lo = __shfl_xor_sync(0xffffffffu, lo, 16);
    hi = __shfl_xor_sync(0xffffffffu, hi, 16);
    return ((u64)hi << 32) | (u64)lo;
}
__device__ __forceinline__ unsigned ld_acq(const unsigned* p) {
    unsigned v;
    asm volatile("ld.acquire.gpu.global.u32 %0,[%1];" : "=r"(v) : "l"(p));
    return v;
}
__device__ __forceinline__ void red_rel(unsigned* p) {
    asm volatile("red.release.gpu.global.add.u32 [%0],1;" :: "l"(p));
}
// ----------------------------- mma helpers ----------------------------------
__device__ __forceinline__ void ldm4(unsigned* r, unsigned addr) {
    asm volatile("ldmatrix.sync.aligned.m8n8.x4.shared.b16 {%0,%1,%2,%3}, [%4];"
                 : "=r"(r[0]), "=r"(r[1]), "=r"(r[2]), "=r"(r[3]) : "r"(addr));
}
__device__ __forceinline__ void mma16816(float* c, const unsigned* a,
                                         unsigned b0, unsigned b1) {
    asm volatile("mma.sync.aligned.m16n8k16.row.col.f32.bf16.bf16.f32 "
                 "{%0,%1,%2,%3}, {%4,%5,%6,%7}, {%8,%9}, {%0,%1,%2,%3};"
                 : "+f"(c[0]), "+f"(c[1]), "+f"(c[2]), "+f"(c[3])
                 : "r"(a[0]), "r"(a[1]), "r"(a[2]), "r"(a[3]), "r"(b0), "r"(b1));
}

// ---------------------------------------------------------------------------
__global__ void k_reset() {
    int i = blockIdx.x * blockDim.x + threadIdx.x;
    if (i < 4 * 32) g_bar4[i] = 0u;
    if (i < 2 * BB * HH) ((float*)g_h)[i] = 0.f;
}
__global__ void k_zero_pooled() {
    int i = blockIdx.x * blockDim.x + threadIdx.x;
    if (i < BB * 3 * NF) g_pooled[i] = 0.f;
}
// split fp32 -> bf16 hi + bf16 lo (residual)
__global__ void k_split(const float* __restrict__ src,
                        __nv_bfloat16* __restrict__ hi,
                        __nv_bfloat16* __restrict__ lo, size_t n) {
    size_t i = (size_t)blockIdx.x * blockDim.x + threadIdx.x;
    if (i >= n) return;
    float x = src[i];
    __nv_bfloat16 h = __float2bfloat16(x);
    hi[i] = h;
    lo[i] = __float2bfloat16(x - __bfloat162float(h));
}

// ---------------------------------------------------------------------------
// generic transpose (selector weights only)
// ---------------------------------------------------------------------------
__global__ void k_transpose(float* dst, const float* src, int R, int C) {
    __shared__ float tile[32][33];
    int c0 = blockIdx.x * 32, r0 = blockIdx.y * 32;
    int tx = threadIdx.x, ty = threadIdx.y;
    #pragma unroll
    for (int i = 0; i < 32; i += 8)
        tile[ty + i][tx] = src[(size_t)(r0 + ty + i) * C + c0 + tx];
    __syncthreads();
    #pragma unroll
    for (int i = 0; i < 32; i += 8)
        dst[(size_t)(c0 + ty + i) * R + r0 + tx] = tile[tx][ty + i];
}

// ---------------------------------------------------------------------------
// fp32 f32x2 GEMM (selector only): C = A @ BT + bias. 256x128 tile.
// ---------------------------------------------------------------------------
__global__ __launch_bounds__(256, 1)
void k_gemm(float* __restrict__ C, const float* __restrict__ A,
            const float* __restrict__ BT, const float* __restrict__ bias,
            int M, int N, int K) {
    __shared__ float sA[2][16][256];
    __shared__ float sB[2][16][128];
    int tid = threadIdx.x;
    int bm = blockIdx.y * 256;
    int bn = blockIdx.x * 128;
    int tm = (tid >> 4) * 16;
    int tn = tid & 15;

    float4 ra[4]; float4 rb[2];
    u64 acc[8][8];
    #pragma unroll
    for (int i = 0; i < 8; i++)
        #pragma unroll
        for (int s = 0; s < 8; s++) acc[i][s] = 0ull;

    #pragma unroll
    for (int i = 0; i < 4; i++) {
        int id = i * 256 + tid, r = id >> 2, kq = (id & 3) * 4;
        ra[i] = *(const float4*)(A + (size_t)(bm + r) * K + kq);
    }
    #pragma unroll
    for (int i = 0; i < 2; i++) {
        int id = i * 256 + tid, kk = id >> 5, nq = (id & 31) * 4;
        rb[i] = *(const float4*)(BT + (size_t)kk * N + bn + nq);
    }
    #pragma unroll
    for (int i = 0; i < 4; i++) {
        int id = i * 256 + tid, r = id >> 2, kq = (id & 3) * 4;
        sA[0][kq + 0][r] = ra[i].x; sA[0][kq + 1][r] = ra[i].y;
        sA[0][kq + 2][r] = ra[i].z; sA[0][kq + 3][r] = ra[i].w;
    }
    #pragma unroll
    for (int i = 0; i < 2; i++) {
        int id = i * 256 + tid, kk = id >> 5, nq = (id & 31) * 4;
        *(float4*)&sB[0][kk][nq] = rb[i];
    }
    __syncthreads();

    int nslab = K >> 4;
    for (int s = 0; s < nslab; s++) {
        int buf = s & 1;
        if (s + 1 < nslab) {
            int k0 = (s + 1) * 16;
            #pragma unroll
            for (int i = 0; i < 4; i++) {
                int id = i * 256 + tid, r = id >> 2, kq = (id & 3) * 4;
                ra[i] = *(const float4*)(A + (size_t)(bm + r) * K + k0 + kq);
            }
            #pragma unroll
            for (int i = 0; i < 2; i++) {
                int id = i * 256 + tid, kk = id >> 5, nq = (id & 31) * 4;
                rb[i] = *(const float4*)(BT + (size_t)(k0 + kk) * N + bn + nq);
            }
        }
        #pragma unroll
        for (int k = 0; k < 16; k++) {
            u64 a[8];
            *(ulonglong2*)&a[0] = *(const ulonglong2*)&sA[buf][k][tm];
            *(ulonglong2*)&a[2] = *(const ulonglong2*)&sA[buf][k][tm + 4];
            *(ulonglong2*)&a[4] = *(const ulonglong2*)&sA[buf][k][tm + 8];
            *(ulonglong2*)&a[6] = *(const ulonglong2*)&sA[buf][k][tm + 12];
            #pragma unroll
            for (int sn = 0; sn < 8; sn++) {
                unsigned bv = *(const unsigned*)&sB[buf][k][tn + 16 * sn];
                u64 b2 = dup2(bv);
                #pragma unroll
                for (int i = 0; i < 8; i++)
                    fma2(acc[i][sn], a[i], b2);
            }
        }
        if (s + 1 < nslab) {
            int nb = buf ^ 1;
            #pragma unroll
            for (int i = 0; i < 4; i++) {
                int id = i * 256 + tid, r = id >> 2, kq = (id & 3) * 4;
                sA[nb][kq + 0][r] = ra[i].x; sA[nb][kq + 1][r] = ra[i].y;
                sA[nb][kq + 2][r] = ra[i].z; sA[nb][kq + 3][r] = ra[i].w;
            }
            #pragma unroll
            for (int i = 0; i < 2; i++) {
                int id = i * 256 + tid, kk = id >> 5, nq = (id & 31) * 4;
                *(float4*)&sB[nb][kk][nq] = rb[i];
            }
            __syncthreads();
        }
    }
    #pragma unroll
    for (int i = 0; i < 8; i++) {
        size_t r0 = (size_t)(bm + tm + 2 * i) * N;
        size_t r1 = r0 + N;
        #pragma unroll
        for (int sn = 0; sn < 8; sn++) {
            int col = bn + tn + 16 * sn;
            float2 v = unpk(acc[i][sn]);
            float bv = bias ? bias[col] : 0.f;
            C[r0 + col] = v.x + bv;
            C[r1 + col] = v.y + bv;
        }
    }
}

// ---------------------------------------------------------------------------
// split-bf16 tensor-core GEMM (unchanged from R8)
// ---------------------------------------------------------------------------
__global__ __launch_bounds__(256, 1)
void k_bgemm(float* __restrict__ C,
             const __nv_bfloat16* __restrict__ Ah, const __nv_bfloat16* __restrict__ Al,
             const __nv_bfloat16* __restrict__ Bh, const __nv_bfloat16* __restrict__ Bl,
             const float* __restrict__ bias,
             int M, int N, int K, const int* __restrict__ nsel, int mode) {
    extern __shared__ __nv_bfloat16 sdyn[];
    int tid = threadIdx.x;
    int bm = blockIdx.y * 128;
    int bn = blockIdx.x * 128;

    if (mode != 0) {
        int p0 = bm & 511;
        if (p0 >= nsel[bm >> 9]) {
            if (mode == 2) {
                float4 z = make_float4(0.f, 0.f, 0.f, 0.f);
                for (int i = tid; i < 128 * 32; i += 256) {
                    int row = i >> 5, c4 = (i & 31) * 4;
                    *(float4*)(C + (size_t)(bm + row) * N + bn + c4) = z;
                }
            }
            return;
        }
    }

    int wid = tid >> 5, lane = tid & 31;
    int m0 = (wid & 3) * 32, n0 = (wid >> 2) * 64;
    unsigned sbase = (unsigned)__cvta_generic_to_shared(sdyn);

    const __nv_bfloat16* gp[4];
    gp[0] = Ah; gp[1] = Al; gp[2] = Bh; gp[3] = Bl;
    int rbase[4] = {bm, bm, bn, bn};
    int id0 = tid * 2, id1 = tid * 2 + 1;
    int row0 = id0 >> 2, seg0 = (id0 & 3) * 8;
    int row1 = id1 >> 2, seg1 = (id1 & 3) * 8;

    float acc[2][8][4];
    #pragma unroll
    for (int i = 0; i < 2; i++)
        #pragma unroll
        for (int j = 0; j < 8; j++)
            #pragma unroll
            for (int c = 0; c < 4; c++) acc[i][j][c] = 0.f;

    uint4 rg[4][2];
    #pragma unroll
    for (int p = 0; p < 4; p++) {
        rg[p][0] = *(const uint4*)(gp[p] + (size_t)(rbase[p] + row0) * K + seg0);
        rg[p][1] = *(const uint4*)(gp[p] + (size_t)(rbase[p] + row1) * K + seg1);
    }
    #pragma unroll
    for (int p = 0; p < 4; p++) {
        __nv_bfloat16* sp = sdyn + (size_t)p * (128 * SAS);
        *(uint4*)&sp[row0 * SAS + seg0] = rg[p][0];
        *(uint4*)&sp[row1 * SAS + seg1] = rg[p][1];
    }
    __syncthreads();

    int alr = lane & 15, alh = (lane >> 4) * 16;
    int bro = ((lane >> 4) & 1) * 8 + (lane & 7);
    int bko = ((lane >> 3) & 1) * 16;

    int nslab = K >> 5;
    for (int sl = 0; sl < nslab; sl++) {
        int buf = sl & 1;
        if (sl + 1 < nslab) {
            int k0 = (sl + 1) * 32;
            #pragma unroll
            for (int p = 0; p < 4; p++) {
                rg[p][0] = *(const uint4*)(gp[p] + (size_t)(rbase[p] + row0) * K + k0 + seg0);
                rg[p][1] = *(const uint4*)(gp[p] + (size_t)(rbase[p] + row1) * K + k0 + seg1);
            }
        }
        unsigned base = sbase + (unsigned)buf * (4 * OPSZ);
        #pragma unroll
        for (int kk = 0; kk < 32; kk += 16) {
            unsigned ah[2][4], al[2][4], bh[4][4], bl[4][4];
            #pragma unroll
            for (int i = 0; i < 2; i++) {
                unsigned ra = base + ((m0 + 16 * i + alr) * SAS + kk) * 2 + alh;
                ldm4(ah[i], ra);
                ldm4(al[i], ra + OPSZ);
            }
            #pragma unroll
            for (int g = 0; g < 4; g++) {
                unsigned rb = base + 2 * OPSZ + ((n0 + 16 * g + bro) * SAS + kk) * 2 + bko;
                ldm4(bh[g], rb);
                ldm4(bl[g], rb + OPSZ);
            }
            #pragma unroll
            for (int i = 0; i < 2; i++)
                #pragma unroll
                for (int g = 0; g < 4; g++)
                    #pragma unroll
                    for (int h = 0; h < 2; h++) {
                        int j = 2 * g + h;
                        mma16816(acc[i][j], ah[i], bh[g][2*h], bh[g][2*h + 1]);
                        mma16816(acc[i][j], ah[i], bl[g][2*h], bl[g][2*h + 1]);
                        mma16816(acc[i][j], al[i], bh[g][2*h], bh[g][2*h + 1]);
                    }
        }
        if (sl + 1 < nslab) {
            int nb = buf ^ 1;
            #pragma unroll
            for (int p = 0; p < 4; p++) {
                __nv_bfloat16* sp = sdyn + (size_t)(nb * 4 + p) * (128 * SAS);
                *(uint4*)&sp[row0 * SAS + seg0] = rg[p][0];
                *(uint4*)&sp[row1 * SAS + seg1] = rg[p][1];
            }
            __syncthreads();
        }
    }
    #pragma unroll
    for (int i = 0; i < 2; i++) {
        int rA = bm + m0 + 16 * i + (lane >> 2);
        #pragma unroll
        for (int j = 0; j < 8; j++) {
            int col = bn + n0 + 8 * j + 2 * (lane & 3);
            float b0v = 0.f, b1v = 0.f;
            if (bias) { b0v = bias[col]; b1v = bias[col + 1]; }
            *(float2*)(C + (size_t)rA * N + col) =
                make_float2(acc[i][j][0] + b0v, acc[i][j][1] + b1v);
            *(float2*)(C + (size_t)(rA + 8) * N + col) =
                make_float2(acc[i][j][2] + b0v, acc[i][j][3] + b1v);
        }
    }
}

// ---------------------------------------------------------------------------
// selector GRU recurrence (exact f32x2; unchanged from R7/R8)
// ---------------------------------------------------------------------------
__global__ __launch_bounds__(256, 1)
void k_recur(const float* __restrict__ Gi, float* __restrict__ hist,
             const float* __restrict__ Whh, const float* __restrict__ bhh,
             const int* __restrict__ nsel) {
    extern __shared__ float sm[];
    float* sh  = sm;
    float* red = sm + 16 * 512;
    int tid = threadIdx.x;
    int bt = blockIdx.x & 3, jt = blockIdx.x >> 2;
    int b0 = bt * 16, j0 = jt * 16;

    int jj = tid & 15;
    int kc = tid >> 4;
    int k0 = kc * 32;
    int qx = (kc & 1) << 2;
    int wi = tid >> 5;
    int lane = tid & 31;
    int bb2 = tid >> 4;
    int j2 = j0 + jj;
    int b2 = b0 + bb2;

    u64 w2[3][16];
    #pragma unroll
    for (int g = 0; g < 3; g++) {
        const float* wrow = Whh + (size_t)(g * 512 + j0 + jj) * 512;
        #pragma unroll
        for (int q = 0; q < 8; q++) {
            int keff = k0 + 4 * (q ^ qx);
            w2[g][2*q + 0] = *(const u64*)(wrow + keff);
            w2[g][2*q + 1] = *(const u64*)(wrow + keff + 2);
        }
    }
    float br = bhh[j2], bz = bhh[512 + j2], bn2 = bhh[1024 + j2];
    int lim = TT, maxlim = TT;
    if (nsel) {
        lim = nsel[b2];
        maxlim = 0;
        #pragma unroll
        for (int b = 0; b < 16; b++) {
            int v = nsel[b0 + b];
            maxlim = v > maxlim ? v : maxlim;
        }
    }
    unsigned* barp = &g_bar4[bt * 32];

    for (int t = 0; t < maxlim; t++) {
        const float* gp = Gi + ((size_t)b2 * TT + t) * G3;
        float gir = __ldcg(gp + j2);
        float giz = __ldcg(gp + 512 + j2);
        float gin = __ldcg(gp + 1024 + j2);

        if (t > 0) {
            if (tid == 0) {
                unsigned tgt = 32u * (unsigned)t;
                while (ld_acq(barp) < tgt) { }
            }
            __syncthreads();
        }

        const float* hsrc = g_h[t & 1];
        #pragma unroll
        for (int i = 0; i < 8; i++) {
            int id = tid + i * 256;
            int lb = id >> 7;
            int lk = (id & 127) * 4;
            float4 v = __ldcg((const float4*)(hsrc + (size_t)(b0 + lb) * HH + lk));
            *(float4*)&sh[lb * 512 + lk] = v;
        }
        __syncthreads();

        #pragma unroll 1
        for (int b = 0; b < 16; b++) {
            const ulonglong2* hp = (const ulonglong2*)&sh[b * 512 + k0];
            u64 a0 = 0ull, a1 = 0ull, a2 = 0ull;
            #pragma unroll
            for (int q = 0; q < 8; q++) {
                ulonglong2 hv = hp[q ^ qx];
                fma2(a0, hv.x, w2[0][2*q]); fma2(a0, hv.y, w2[0][2*q + 1]);
                fma2(a1, hv.x, w2[1][2*q]); fma2(a1, hv.y, w2[1][2*q + 1]);
                fma2(a2, hv.x, w2[2][2*q]); fma2(a2, hv.y, w2[2][2*q + 1]);
            }
            a0 = add2(a0, shx16(a0));
            a1 = add2(a1, shx16(a1));
            a2 = add2(a2, shx16(a2));
            if (lane < 16) {
                float2 f0 = unpk(a0), f1 = unpk(a1), f2 = unpk(a2);
                int base = b * REDS + wi * 48 + jj;
                red[base]      = f0.x + f0.y;
                red[base + 16] = f1.x + f1.y;
                red[base + 32] = f2.x + f2.y;
            }
        }
        __syncthreads();

        float sr = br, sz = bz, sn = bn2;
        #pragma unroll
        for (int w = 0; w < 8; w++) {
            int base = bb2 * REDS + w * 48 + jj;
            sr += red[base];
            sz += red[base + 16];
            sn += red[base + 32];
        }
        float r = 1.f / (1.f + expf(-(gir + sr)));
        float z = 1.f / (1.f + expf(-(giz + sz)));
        float n = tanhf(gin + r * sn);
        float hold = sh[bb2 * 512 + j2];
        float hn = (1.f - z) * n + z * hold;
        bool valid = t < lim;
        g_h[(t + 1) & 1][b2 * HH + j2] = valid ? hn : hold;
        hist[((size_t)b2 * TT + t) * HH + j2] = valid ? hn : 0.f;

        __syncthreads();
        if (tid == 0) red_rel(barp);
    }

    for (int t = maxlim; t < TT; t++)
        hist[((size_t)b2 * TT + t) * HH + j2] = 0.f;
}

// ---------------------------------------------------------------------------
// tensor-core GRU recurrence (layers 0/1): split-bf16 mma per step.
// grid = 128 CTAs (4 b-tiles x 32 j-tiles), 256 threads (8 warps).
// Whh slice (48 rows) pre-split to bf16 hi/lo, resident in smem.
// Per step: stage+split h (fp32 master in global), m16n48k512 mma over
// 12 units (3 gates x 4 k-quarters) across 8 warps, smem-reduce 4 partials,
// exact fp32 gate math (hold read exact from global).
// ---------------------------------------------------------------------------
__global__ __launch_bounds__(256, 1)
void k_recur_mma(const float* __restrict__ Gi, float* __restrict__ hist,
                 const __nv_bfloat16* __restrict__ Wh,
                 const __nv_bfloat16* __restrict__ Wl,
                 const float* __restrict__ bhh, const int* __restrict__ nsel) {
    extern __shared__ __nv_bfloat16 smb[];
    float* red = (float*)(smb + MSM_BF);   // [4 kq][16 b][MRED_STR]
    int tid = threadIdx.x;
    int bt = blockIdx.x & 3, jt = blockIdx.x >> 2;
    int b0 = bt * 16, j0 = jt * 16;
    int wid = tid >> 5, lane = tid & 31;
    int jj = tid & 15, bb2 = tid >> 4;
    int j2 = j0 + jj, b2 = b0 + bb2;

    // load W slice (48 rows x 512) both planes into smem (once)
    for (int idx = tid; idx < 48 * 512; idx += 256) {
        int r = idx >> 9, k = idx & 511;
        int g = r >> 4, jl = r & 15;
        size_t grow = (size_t)(g * 512 + j0 + jl) * 512 + k;
        smb[MSM_W  + r * SWS + k] = Wh[grow];
        smb[MSM_WL + r * SWS + k] = Wl[grow];
    }
    float br = bhh[j2], bz = bhh[512 + j2], bn2 = bhh[1024 + j2];
    int lim = nsel[b2];
    int maxlim = 0;
    #pragma unroll
    for (int b = 0; b < 16; b++) {
        int v = nsel[b0 + b];
        maxlim = v > maxlim ? v : maxlim;
    }
    unsigned* barp = &g_bar4[bt * 32];
    unsigned sbase = (unsigned)__cvta_generic_to_shared(smb);

    // ldmatrix lane components (same convention as k_bgemm)
    int alr = lane & 15, alh = (lane >> 4) * 16;
    int bro = ((lane >> 4) & 1) * 8 + (lane & 7);
    int bko = ((lane >> 3) & 1) * 16;

    __syncthreads();   // W slice ready

    for (int t = 0; t < maxlim; t++) {
        // Gi prefetch (barrier-independent)
        const float* gp = Gi + ((size_t)b2 * TT + t) * G3;
        float gir = __ldcg(gp + j2);
        float giz = __ldcg(gp + 512 + j2);
        float gin = __ldcg(gp + 1024 + j2);

        if (t > 0) {
            if (tid == 0) {
                unsigned tgt = 32u * (unsigned)t;
                while (ld_acq(barp) < tgt) { }
            }
            __syncthreads();
        }

        // stage h: fp32 global -> bf16 hi/lo planes in smem
        const float* hsrc = g_h[t & 1];
        float hold = __ldcg(hsrc + (size_t)b2 * HH + j2);   // exact
        #pragma unroll
        for (int i = 0; i < 8; i++) {
            int id = tid + i * 256;
            int lb = id >> 7;
            int lk = (id & 127) * 4;
            float4 v = __ldcg((const float4*)(hsrc + (size_t)(b0 + lb) * HH + lk));
            __nv_bfloat162 h01 = __floats2bfloat162_rn(v.x, v.y);
            __nv_bfloat162 h23 = __floats2bfloat162_rn(v.z, v.w);
            __nv_bfloat162 l01 = __floats2bfloat162_rn(v.x - __low2float(h01),
                                                       v.y - __high2float(h01));
            __nv_bfloat162 l23 = __floats2bfloat162_rn(v.z - __low2float(h23),
                                                       v.w - __high2float(h23));
            int off = lb * SWS + lk;
            *(__nv_bfloat162*)&smb[MSM_HH + off]     = h01;
            *(__nv_bfloat162*)&smb[MSM_HH + off + 2] = h23;
            *(__nv_bfloat162*)&smb[MSM_HL + off]     = l01;
            *(__nv_bfloat162*)&smb[MSM_HL + off + 2] = l23;
        }
        __syncthreads();

        // mma phase: units (gate gt, k-quarter kq); warps 0..7 take u=wid, wid+8
        for (int u = wid; u < 12; u += 8) {
            int gt = u % 3, kq = u / 3;
            float acc0[4] = {0.f, 0.f, 0.f, 0.f};
            float acc1[4] = {0.f, 0.f, 0.f, 0.f};
            #pragma unroll
            for (int ks = 0; ks < 8; ks++) {
                int kk = kq * 128 + ks * 16;
                unsigned ah[4], al[4], bh[4], bl[4];
                unsigned ra = sbase + (unsigned)(MSM_HH + alr * SWS + kk) * 2 + alh;
                ldm4(ah, ra);
                ldm4(al, ra + (MSM_HL - MSM_HH) * 2);
                unsigned rb = sbase + (unsigned)((gt * 16 + bro) * SWS + kk) * 2 + bko;
                ldm4(bh, rb);
                ldm4(bl, rb + MSM_WL * 2);
                mma16816(acc0, ah, bh[0], bh[1]);
                mma16816(acc0, ah, bl[0], bl[1]);
                mma16816(acc0, al, bh[0], bh[1]);
                mma16816(acc1, ah, bh[2], bh[3]);
                mma16816(acc1, ah, bl[2], bl[3]);
                mma16816(acc1, al, bh[2], bh[3]);
            }
            int r = lane >> 2, c2 = 2 * (lane & 3);
            float* rp = red + (kq * 16 + r) * MRED_STR + gt * 16;
            *(float2*)(rp + c2)                    = make_float2(acc0[0], acc0[1]);
            *(float2*)(rp + 8 * MRED_STR + c2)     = make_float2(acc0[2], acc0[3]);
            *(float2*)(rp + 8 + c2)                = make_float2(acc1[0], acc1[1]);
            *(float2*)(rp + 8 * MRED_STR + 8 + c2) = make_float2(acc1[2], acc1[3]);
        }
        __syncthreads();

        // gate math for (b2, j2)
        float sr = br, sz = bz, sn = bn2;
        #pragma unroll
        for (int kq = 0; kq < 4; kq++) {
            const float* rp = red + (kq * 16 + bb2) * MRED_STR;
            sr += rp[jj];
            sz += rp[16 + jj];
            sn += rp[32 + jj];
        }
        float r_ = 1.f / (1.f + expf(-(gir + sr)));
        float z  = 1.f / (1.f + expf(-(giz + sz)));
        float n  = tanhf(gin + r_ * sn);
        float hn = (1.f - z) * n + z * hold;
        bool valid = t < lim;
        g_h[(t + 1) & 1][b2 * HH + j2] = valid ? hn : hold;
        hist[((size_t)b2 * TT + t) * HH + j2] = valid ? hn : 0.f;

        __syncthreads();
        if (tid == 0) red_rel(barp);
    }

    for (int t = maxlim; t < TT; t++)
        hist[((size_t)b2 * TT + t) * HH + j2] = 0.f;
}

// ---------------------------------------------------------------------------
__global__ void k_selargmax(const float* __restrict__ hist,
                            const float* __restrict__ Ws,
                            const float* __restrict__ bs) {
    int gw = (blockIdx.x * blockDim.x + threadIdx.x) >> 5;
    int lane = threadIdx.x & 31;
    if (gw >= BB * TT) return;
    const float* h = hist + (size_t)gw * HH;
    float l0 = 0.f, l1 = 0.f;
    #pragma unroll 4
    for (int jv = lane; jv < HH; jv += 32) {
        float hv = h[jv];
        l0 += hv * Ws[jv];
        l1 += hv * Ws[HH + jv];
    }
    #pragma unroll
    for (int o = 16; o; o >>= 1) {
        l0 += __shfl_down_sync(0xffffffffu, l0, o);
        l1 += __shfl_down_sync(0xffffffffu, l1, o);
    }
    if (lane == 0)
        g_sel[gw] = ((l1 + bs[1]) > (l0 + bs[0])) ? 1 : 0;
}

// ---------------------------------------------------------------------------
__global__ void k_fix(const int* __restrict__ mask) {
    int b = blockIdx.x;
    int lane = threadIdx.x;
    int len = 0;
    for (int t = lane; t < TT; t += 32) len += mask[b * TT + t];
    #pragma unroll
    for (int o = 16; o; o >>= 1) len += __shfl_down_sync(0xffffffffu, len, o);
    len = __shfl_sync(0xffffffffu, len, 0);
    int cnt = 0;
    for (int c = 0; c < TT; c += 32) {
        int t = c + lane;
        int s = g_sel[b * TT + t];
        if (t == 0) s = 1;
        if (t == len - 1) s = 1;
        if (t >= len) s = 0;
        unsigned bal = __ballot_sync(0xffffffffu, s);
        int pre = __popc(bal & ((1u << lane) - 1u));
        if (s) g_order[b * TT + cnt + pre] = t;
        cnt += __popc(bal);
    }
    if (lane == 0) g_nsel[b] = cnt;
}

// ---------------------------------------------------------------------------
__global__ void k_gather(const float* __restrict__ emb, float* __restrict__ dst) {
    int row = blockIdx.x;
    int b = row >> 9, p = row & 511;
    float4 v = make_float4(0.f, 0.f, 0.f, 0.f);
    if (p < g_nsel[b]) {
        int t = g_order[row];
        v = ((const float4*)(emb + ((size_t)b * TT + t) * EE))[threadIdx.x];
    }
    ((float4*)(dst + (size_t)row * EE))[threadIdx.x] = v;
}

// ---------------------------------------------------------------------------
__global__ void k_pool(const float* __restrict__ U, const float* __restrict__ bc,
                       int kw, int Nn, int seg) {
    int b = blockIdx.x;
    int f = threadIdx.x;
    int tlim = TT - kw + 1;
    int t0 = blockIdx.y * 64;
    int t1 = t0 + 64 < tlim ? t0 + 64 : tlim;
    float bcv = bc[f];
    float m = 0.f;
    const float* Ub = U + (size_t)b * TT * Nn + (size_t)f * kw;
    for (int t = t0; t < t1; t++) {
        float s = bcv;
        #pragma unroll 5
        for (int dt = 0; dt < kw; dt++)
            s += Ub[(size_t)(t + dt) * Nn + dt];
        m = fmaxf(m, fmaxf(s, 0.f));
    }
    atomicMax((int*)&g_pooled[b * (3 * NF) + seg + f], __float_as_int(m));
}

// ---------------------------------------------------------------------------
__global__ void k_final(const float* __restrict__ Wo, const float* __restrict__ bo,
                        float* __restrict__ out) {
    __shared__ float redf[256];
    int b = blockIdx.x, tid = threadIdx.x;
    float s = 0.f;
    for (int f = tid; f < 3 * NF; f += 256)
        s += g_pooled[b * (3 * NF) + f] * Wo[f];
    redf[tid] = s;
    __syncthreads();
    for (int o = 128; o; o >>= 1) {
        if (tid < o) redf[tid] += redf[tid + o];
        __syncthreads();
    }
    if (tid == 0) out[b] = redf[0] + bo[0];
}

// ---------------------------------------------------------------------------
extern "C" void kernel_launch(void* const* d_in, const int* in_sizes, int n_in,
                              void* d_out, int out_size) {
    const float* emb   = (const float*)d_in[0];
    const int*   mask  = (const int*)  d_in[1];
    const float* Wih_c = (const float*)d_in[2];
    const float* Whh_c = (const float*)d_in[3];
    const float* bih_c = (const float*)d_in[4];
    const float* bhh_c = (const float*)d_in[5];
    const float* Ws    = (const float*)d_in[6];
    const float* bs    = (const float*)d_in[7];
    const float* Wih0  = (const float*)d_in[8];
    const float* Whh0  = (const float*)d_in[9];
    const float* bih0  = (const float*)d_in[10];
    const float* bhh0  = (const float*)d_in[11];
    const float* Wih1  = (const float*)d_in[12];
    const float* Whh1  = (const float*)d_in[13];
    const float* bih1  = (const float*)d_in[14];
    const float* bhh1  = (const float*)d_in[15];
    const float* Wc3   = (const float*)d_in[16];
    const float* bc3   = (const float*)d_in[17];
    const float* Wc4   = (const float*)d_in[18];
    const float* bc4   = (const float*)d_in[19];
    const float* Wc5   = (const float*)d_in[20];
    const float* bc5   = (const float*)d_in[21];
    const float* Wo    = (const float*)d_in[22];
    const float* bo    = (const float*)d_in[23];
    float* out = (float*)d_out;

    cudaFuncSetAttribute(k_recur, cudaFuncAttributeMaxDynamicSharedMemorySize,
                         RSM_BYTES);
    cudaFuncSetAttribute(k_recur_mma, cudaFuncAttributeMaxDynamicSharedMemorySize,
                         MSM_BYTES);
    cudaFuncSetAttribute(k_bgemm, cudaFuncAttributeMaxDynamicSharedMemorySize,
                         BSM_BYTES);

    float *pGi, *pS0, *pS1, *pNe, *pU, *pWT;
    int* pNsel;
    __nv_bfloat16 *pAh, *pAl, *pWh, *pWl;
    cudaGetSymbolAddress((void**)&pGi,   g_Gi);
    cudaGetSymbolAddress((void**)&pS0,   g_seq0);
    cudaGetSymbolAddress((void**)&pS1,   g_seq1);
    cudaGetSymbolAddress((void**)&pNe,   g_newemb);
    cudaGetSymbolAddress((void**)&pU,    g_U);
    cudaGetSymbolAddress((void**)&pWT,   g_WT);
    cudaGetSymbolAddress((void**)&pNsel, g_nsel);
    cudaGetSymbolAddress((void**)&pAh,   g_Ah);
    cudaGetSymbolAddress((void**)&pAl,   g_Al);
    cudaGetSymbolAddress((void**)&pWh,   g_Wh);
    cudaGetSymbolAddress((void**)&pWl,   g_Wl);

    dim3 t32x8(32, 8);
    const size_t nAE = (size_t)MALL * EE;
    const size_t nAH = (size_t)MALL * HH;

    // ---- selector GRU (exact fp32 f32x2 path throughout) ----
    k_transpose<<<dim3(EE/32, G3/32), t32x8>>>(pWT, Wih_c, G3, EE);
    k_gemm<<<dim3(G3/128, MALL/256), 256>>>(pGi, emb, pWT, bih_c, MALL, G3, EE);
    k_reset<<<256, 256>>>();
    k_recur<<<NBLK, 256, RSM_BYTES>>>(pGi, pS0, Whh_c, bhh_c, nullptr);
    k_selargmax<<<(BB*TT*32 + 255)/256, 256>>>(pS0, Ws, bs);
    k_fix<<<BB, 32>>>(mask);
    k_gather<<<MALL, EE/4>>>(emb, pNe);

    // ---- layer 0: split-bf16 GEMM + mma recurrence ----
    k_split<<<(int)((nAE + 255)/256), 256>>>(pNe, pAh, pAl, nAE);
    k_split<<<(G3*EE + 255)/256, 256>>>(Wih0, pWh, pWl, (size_t)G3*EE);
    k_bgemm<<<dim3(G3/128, MALL/128), 256, BSM_BYTES>>>(
        pGi, pAh, pAl, pWh, pWl, bih0, MALL, G3, EE, pNsel, 1);
    k_split<<<(G3*HH + 255)/256, 256>>>(Whh0, pWh, pWl, (size_t)G3*HH);
    k_reset<<<256, 256>>>();
    k_recur_mma<<<NBLK, 256, MSM_BYTES>>>(pGi, pS1, pWh, pWl, bhh0, pNsel);

    // ---- layer 1 ----
    k_split<<<(int)((nAH + 255)/256), 256>>>(pS1, pAh, pAl, nAH);
    k_split<<<(G3*HH + 255)/256, 256>>>(Wih1, pWh, pWl, (size_t)G3*HH);
    k_bgemm<<<dim3(G3/128, MALL/128), 256, BSM_BYTES>>>(
        pGi, pAh, pAl, pWh, pWl, bih1, MALL, G3, HH, pNsel, 1);
    k_split<<<(G3*HH + 255)/256, 256>>>(Whh1, pWh, pWl, (size_t)G3*HH);
    k_reset<<<256, 256>>>();
    k_recur_mma<<<NBLK, 256, MSM_BYTES>>>(pGi, pS0, pWh, pWl, bhh1, pNsel);

    // ---- convs (split-bf16 GEMM + pool) ----
    k_zero_pooled<<<(BB*3*NF + 255)/256, 256>>>();
    k_split<<<(int)((nAH + 255)/256), 256>>>(pS0, pAh, pAl, nAH);

    k_split<<<(NF*3*HH + 255)/256, 256>>>(Wc3, pWh, pWl, (size_t)NF*3*HH);
    k_bgemm<<<dim3((NF*3)/128, MALL/128), 256, BSM_BYTES>>>(
        pU, pAh, pAl, pWh, pWl, nullptr, MALL, NF*3, HH, pNsel, 2);
    k_pool<<<dim3(BB, 8), NF>>>(pU, bc3, 3, NF*3, 0);

    k_split<<<(NF*4*HH + 255)/256, 256>>>(Wc4, pWh, pWl, (size_t)NF*4*HH);
    k_bgemm<<<dim3((NF*4)/128, MALL/128), 256, BSM_BYTES>>>(
        pU, pAh, pAl, pWh, pWl, nullptr, MALL, NF*4, HH, pNsel, 2);
    k_pool<<<dim3(BB, 8), NF>>>(pU, bc4, 4, NF*4, NF);

    k_split<<<(NF*5*HH + 255)/256, 256>>>(Wc5, pWh, pWl, (size_t)NF*5*HH);
    k_bgemm<<<dim3((NF*5)/128, MALL/128), 256, BSM_BYTES>>>(
        pU, pAh, pAl, pWh, pWl, nullptr, MALL, NF*5, HH, pNsel, 2);
    k_pool<<<dim3(BB, 8), NF>>>(pU, bc5, 5, NF*5, 2*NF);

    // ---- final projection ----
    k_final<<<BB, 256>>>(Wo, bo, out);
}

// round 11
// speedup vs baseline: 1.9224x; 1.1266x over previous
#include <cuda_runtime.h>
#include <cuda_bf16.h>
#include <math.h>
#include <stdint.h>
#include <stddef.h>

typedef unsigned long long u64;

// Problem dims
#define BB    64
#define TT    512
#define EE    768
#define HH    512
#define G3    1536
#define NF    256
#define MALL  (BB*TT)          // 32768

#define NBLK      128

// -------- mma recurrence config (2-plane, layers) --------
#define SWS     520
#define MSM_W   0
#define MSM_WL  (48*SWS)
#define MSM_HH  (96*SWS)
#define MSM_HL  (112*SWS)
#define MSM_BF  (128*SWS)
#define MRED_STR 52
#define MSM_BYTES (MSM_BF*2 + 4*16*MRED_STR*4)   // 146432 B

// -------- mma recurrence config (3-plane, selector) --------
#define M3_W1  0
#define M3_W2  (48*SWS)
#define M3_W3  (96*SWS)
#define M3_H1  (144*SWS)
#define M3_H2  (160*SWS)
#define M3_H3  (176*SWS)
#define M3_BF  (192*SWS)
#define M3_BYTES (M3_BF*2 + 4*16*MRED_STR*4)     // 212992 B

// -------- bf16 tensor GEMM config --------
#define SAS   40
#define OPSZ  (128*SAS*2)
#define BSM_BYTES  (8*OPSZ)          // 2-plane: 2 bufs x 4 planes = 81920 B
#define BSM3_BYTES (12*OPSZ)         // 3-plane: 2 bufs x 6 planes = 122880 B

// ----------------- device scratch (statics; no cudaMalloc allowed) ----------
__device__ float g_Gi[(size_t)MALL * G3];
__device__ float g_seq0[(size_t)MALL * HH];
__device__ float g_seq1[(size_t)MALL * HH];
__device__ float g_newemb[(size_t)MALL * EE];
__device__ float g_U[(size_t)MALL * (NF*5)];
__device__ float g_h[2][BB * HH];
__device__ int   g_sel[BB * TT];
__device__ int   g_order[BB * TT];
__device__ int   g_nsel[BB];
__device__ float g_pooled[BB * 3 * NF];
__device__ unsigned g_bar4[4 * 32];
// bf16 split buffers (3rd plane used by selector path only)
__device__ __nv_bfloat16 g_Ah[(size_t)MALL * EE];
__device__ __nv_bfloat16 g_Al[(size_t)MALL * EE];
__device__ __nv_bfloat16 g_A3[(size_t)MALL * EE];
__device__ __nv_bfloat16 g_Wh[G3 * EE];
__device__ __nv_bfloat16 g_Wl[G3 * EE];
__device__ __nv_bfloat16 g_W3[G3 * EE];

// ----------------------------- sync helpers ---------------------------------
__device__ __forceinline__ unsigned ld_acq(const unsigned* p) {
    unsigned v;
    asm volatile("ld.acquire.gpu.global.u32 %0,[%1];" : "=r"(v) : "l"(p));
    return v;
}
__device__ __forceinline__ void red_rel(unsigned* p) {
    asm volatile("red.release.gpu.global.add.u32 [%0],1;" :: "l"(p));
}
// ----------------------------- mma helpers ----------------------------------
__device__ __forceinline__ void ldm4(unsigned* r, unsigned addr) {
    asm volatile("ldmatrix.sync.aligned.m8n8.x4.shared.b16 {%0,%1,%2,%3}, [%4];"
                 : "=r"(r[0]), "=r"(r[1]), "=r"(r[2]), "=r"(r[3]) : "r"(addr));
}
__device__ __forceinline__ void mma16816(float* c, const unsigned* a,
                                         unsigned b0, unsigned b1) {
    asm volatile("mma.sync.aligned.m16n8k16.row.col.f32.bf16.bf16.f32 "
                 "{%0,%1,%2,%3}, {%4,%5,%6,%7}, {%8,%9}, {%0,%1,%2,%3};"
                 : "+f"(c[0]), "+f"(c[1]), "+f"(c[2]), "+f"(c[3])
                 : "r"(a[0]), "r"(a[1]), "r"(a[2]), "r"(a[3]), "r"(b0), "r"(b1));
}

// ---------------------------------------------------------------------------
__global__ void k_reset() {
    int i = blockIdx.x * blockDim.x + threadIdx.x;
    if (i < 4 * 32) g_bar4[i] = 0u;
    if (i < 2 * BB * HH) ((float*)g_h)[i] = 0.f;
}
__global__ void k_zero_pooled() {
    int i = blockIdx.x * blockDim.x + threadIdx.x;
    if (i < BB * 3 * NF) g_pooled[i] = 0.f;
}
// split fp32 -> 2 bf16 planes
__global__ void k_split(const float* __restrict__ src,
                        __nv_bfloat16* __restrict__ p1,
                        __nv_bfloat16* __restrict__ p2, size_t n) {
    size_t i = (size_t)blockIdx.x * blockDim.x + threadIdx.x;
    if (i >= n) return;
    float x = src[i];
    __nv_bfloat16 h = __float2bfloat16(x);
    p1[i] = h;
    p2[i] = __float2bfloat16(x - __bfloat162float(h));
}
// split fp32 -> 3 bf16 planes (residual chain; combined error ~2^-24)
__global__ void k_split3(const float* __restrict__ src,
                         __nv_bfloat16* __restrict__ p1,
                         __nv_bfloat16* __restrict__ p2,
                         __nv_bfloat16* __restrict__ p3, size_t n) {
    size_t i = (size_t)blockIdx.x * blockDim.x + threadIdx.x;
    if (i >= n) return;
    float x = src[i];
    __nv_bfloat16 h1 = __float2bfloat16(x);
    float r = x - __bfloat162float(h1);
    __nv_bfloat16 h2 = __float2bfloat16(r);
    float r2 = r - __bfloat162float(h2);
    p1[i] = h1;
    p2[i] = h2;
    p3[i] = __float2bfloat16(r2);
}

// ---------------------------------------------------------------------------
// split-bf16 tensor-core GEMM, 2-plane / 3-term (layers + convs; from R8)
// ---------------------------------------------------------------------------
__global__ __launch_bounds__(256, 1)
void k_bgemm(float* __restrict__ C,
             const __nv_bfloat16* __restrict__ Ah, const __nv_bfloat16* __restrict__ Al,
             const __nv_bfloat16* __restrict__ Bh, const __nv_bfloat16* __restrict__ Bl,
             const float* __restrict__ bias,
             int M, int N, int K, const int* __restrict__ nsel, int mode) {
    extern __shared__ __nv_bfloat16 sdyn[];
    int tid = threadIdx.x;
    int bm = blockIdx.y * 128;
    int bn = blockIdx.x * 128;

    if (mode != 0) {
        int p0 = bm & 511;
        if (p0 >= nsel[bm >> 9]) {
            if (mode == 2) {
                float4 z = make_float4(0.f, 0.f, 0.f, 0.f);
                for (int i = tid; i < 128 * 32; i += 256) {
                    int row = i >> 5, c4 = (i & 31) * 4;
                    *(float4*)(C + (size_t)(bm + row) * N + bn + c4) = z;
                }
            }
            return;
        }
    }

    int wid = tid >> 5, lane = tid & 31;
    int m0 = (wid & 3) * 32, n0 = (wid >> 2) * 64;
    unsigned sbase = (unsigned)__cvta_generic_to_shared(sdyn);

    const __nv_bfloat16* gp[4];
    gp[0] = Ah; gp[1] = Al; gp[2] = Bh; gp[3] = Bl;
    int rbase[4] = {bm, bm, bn, bn};
    int id0 = tid * 2, id1 = tid * 2 + 1;
    int row0 = id0 >> 2, seg0 = (id0 & 3) * 8;
    int row1 = id1 >> 2, seg1 = (id1 & 3) * 8;

    float acc[2][8][4];
    #pragma unroll
    for (int i = 0; i < 2; i++)
        #pragma unroll
        for (int j = 0; j < 8; j++)
            #pragma unroll
            for (int c = 0; c < 4; c++) acc[i][j][c] = 0.f;

    uint4 rg[4][2];
    #pragma unroll
    for (int p = 0; p < 4; p++) {
        rg[p][0] = *(const uint4*)(gp[p] + (size_t)(rbase[p] + row0) * K + seg0);
        rg[p][1] = *(const uint4*)(gp[p] + (size_t)(rbase[p] + row1) * K + seg1);
    }
    #pragma unroll
    for (int p = 0; p < 4; p++) {
        __nv_bfloat16* sp = sdyn + (size_t)p * (128 * SAS);
        *(uint4*)&sp[row0 * SAS + seg0] = rg[p][0];
        *(uint4*)&sp[row1 * SAS + seg1] = rg[p][1];
    }
    __syncthreads();

    int alr = lane & 15, alh = (lane >> 4) * 16;
    int bro = ((lane >> 4) & 1) * 8 + (lane & 7);
    int bko = ((lane >> 3) & 1) * 16;

    int nslab = K >> 5;
    for (int sl = 0; sl < nslab; sl++) {
        int buf = sl & 1;
        if (sl + 1 < nslab) {
            int k0 = (sl + 1) * 32;
            #pragma unroll
            for (int p = 0; p < 4; p++) {
                rg[p][0] = *(const uint4*)(gp[p] + (size_t)(rbase[p] + row0) * K + k0 + seg0);
                rg[p][1] = *(const uint4*)(gp[p] + (size_t)(rbase[p] + row1) * K + k0 + seg1);
            }
        }
        unsigned base = sbase + (unsigned)buf * (4 * OPSZ);
        #pragma unroll
        for (int kk = 0; kk < 32; kk += 16) {
            unsigned ah[2][4], al[2][4], bh[4][4], bl[4][4];
            #pragma unroll
            for (int i = 0; i < 2; i++) {
                unsigned ra = base + ((m0 + 16 * i + alr) * SAS + kk) * 2 + alh;
                ldm4(ah[i], ra);
                ldm4(al[i], ra + OPSZ);
            }
            #pragma unroll
            for (int g = 0; g < 4; g++) {
                unsigned rb = base + 2 * OPSZ + ((n0 + 16 * g + bro) * SAS + kk) * 2 + bko;
                ldm4(bh[g], rb);
                ldm4(bl[g], rb + OPSZ);
            }
            #pragma unroll
            for (int i = 0; i < 2; i++)
                #pragma unroll
                for (int g = 0; g < 4; g++)
                    #pragma unroll
                    for (int h = 0; h < 2; h++) {
                        int j = 2 * g + h;
                        mma16816(acc[i][j], ah[i], bh[g][2*h], bh[g][2*h + 1]);
                        mma16816(acc[i][j], ah[i], bl[g][2*h], bl[g][2*h + 1]);
                        mma16816(acc[i][j], al[i], bh[g][2*h], bh[g][2*h + 1]);
                    }
        }
        if (sl + 1 < nslab) {
            int nb = buf ^ 1;
            #pragma unroll
            for (int p = 0; p < 4; p++) {
                __nv_bfloat16* sp = sdyn + (size_t)(nb * 4 + p) * (128 * SAS);
                *(uint4*)&sp[row0 * SAS + seg0] = rg[p][0];
                *(uint4*)&sp[row1 * SAS + seg1] = rg[p][1];
            }
            __syncthreads();
        }
    }
    #pragma unroll
    for (int i = 0; i < 2; i++) {
        int rA = bm + m0 + 16 * i + (lane >> 2);
        #pragma unroll
        for (int j = 0; j < 8; j++) {
            int col = bn + n0 + 8 * j + 2 * (lane & 3);
            float b0v = 0.f, b1v = 0.f;
            if (bias) { b0v = bias[col]; b1v = bias[col + 1]; }
            *(float2*)(C + (size_t)rA * N + col) =
                make_float2(acc[i][j][0] + b0v, acc[i][j][1] + b1v);
            *(float2*)(C + (size_t)(rA + 8) * N + col) =
                make_float2(acc[i][j][2] + b0v, acc[i][j][3] + b1v);
        }
    }
}

// ---------------------------------------------------------------------------
// split-bf16 GEMM, 3-plane / 6-term (selector; error ~2^-23, near-fp32)
// ---------------------------------------------------------------------------
__global__ __launch_bounds__(256, 1)
void k_bgemm3(float* __restrict__ C,
              const __nv_bfloat16* __restrict__ A1, const __nv_bfloat16* __restrict__ A2,
              const __nv_bfloat16* __restrict__ A3,
              const __nv_bfloat16* __restrict__ B1, const __nv_bfloat16* __restrict__ B2,
              const __nv_bfloat16* __restrict__ B3,
              const float* __restrict__ bias, int M, int N, int K) {
    extern __shared__ __nv_bfloat16 sdyn[];
    int tid = threadIdx.x;
    int bm = blockIdx.y * 128;
    int bn = blockIdx.x * 128;
    int wid = tid >> 5, lane = tid & 31;
    int m0 = (wid & 3) * 32, n0 = (wid >> 2) * 64;
    unsigned sbase = (unsigned)__cvta_generic_to_shared(sdyn);

    const __nv_bfloat16* gp[6];
    gp[0] = A1; gp[1] = A2; gp[2] = A3; gp[3] = B1; gp[4] = B2; gp[5] = B3;
    int rbase[6] = {bm, bm, bm, bn, bn, bn};
    int id0 = tid * 2, id1 = tid * 2 + 1;
    int row0 = id0 >> 2, seg0 = (id0 & 3) * 8;
    int row1 = id1 >> 2, seg1 = (id1 & 3) * 8;

    float acc[2][8][4];
    #pragma unroll
    for (int i = 0; i < 2; i++)
        #pragma unroll
        for (int j = 0; j < 8; j++)
            #pragma unroll
            for (int c = 0; c < 4; c++) acc[i][j][c] = 0.f;

    uint4 rg[6][2];
    #pragma unroll
    for (int p = 0; p < 6; p++) {
        rg[p][0] = *(const uint4*)(gp[p] + (size_t)(rbase[p] + row0) * K + seg0);
        rg[p][1] = *(const uint4*)(gp[p] + (size_t)(rbase[p] + row1) * K + seg1);
    }
    #pragma unroll
    for (int p = 0; p < 6; p++) {
        __nv_bfloat16* sp = sdyn + (size_t)p * (128 * SAS);
        *(uint4*)&sp[row0 * SAS + seg0] = rg[p][0];
        *(uint4*)&sp[row1 * SAS + seg1] = rg[p][1];
    }
    __syncthreads();

    int alr = lane & 15, alh = (lane >> 4) * 16;
    int bro = ((lane >> 4) & 1) * 8 + (lane & 7);
    int bko = ((lane >> 3) & 1) * 16;

    int nslab = K >> 5;
    for (int sl = 0; sl < nslab; sl++) {
        int buf = sl & 1;
        if (sl + 1 < nslab) {
            int k0 = (sl + 1) * 32;
            #pragma unroll
            for (int p = 0; p < 6; p++) {
                rg[p][0] = *(const uint4*)(gp[p] + (size_t)(rbase[p] + row0) * K + k0 + seg0);
                rg[p][1] = *(const uint4*)(gp[p] + (size_t)(rbase[p] + row1) * K + k0 + seg1);
            }
        }
        unsigned base = sbase + (unsigned)buf * (6 * OPSZ);
        #pragma unroll
        for (int kk = 0; kk < 32; kk += 16) {
            unsigned a1[2][4], a2[2][4], a3[2][4];
            unsigned b1[4][4], b2[4][4], b3[4][4];
            #pragma unroll
            for (int i = 0; i < 2; i++) {
                unsigned ra = base + ((m0 + 16 * i + alr) * SAS + kk) * 2 + alh;
                ldm4(a1[i], ra);
                ldm4(a2[i], ra + OPSZ);
                ldm4(a3[i], ra + 2 * OPSZ);
            }
            #pragma unroll
            for (int g = 0; g < 4; g++) {
                unsigned rb = base + 3 * OPSZ + ((n0 + 16 * g + bro) * SAS + kk) * 2 + bko;
                ldm4(b1[g], rb);
                ldm4(b2[g], rb + OPSZ);
                ldm4(b3[g], rb + 2 * OPSZ);
            }
            #pragma unroll
            for (int i = 0; i < 2; i++)
                #pragma unroll
                for (int g = 0; g < 4; g++)
                    #pragma unroll
                    for (int h = 0; h < 2; h++) {
                        int j = 2 * g + h;
                        mma16816(acc[i][j], a1[i], b1[g][2*h], b1[g][2*h + 1]);
                        mma16816(acc[i][j], a1[i], b2[g][2*h], b2[g][2*h + 1]);
                        mma16816(acc[i][j], a2[i], b1[g][2*h], b1[g][2*h + 1]);
                        mma16816(acc[i][j], a1[i], b3[g][2*h], b3[g][2*h + 1]);
                        mma16816(acc[i][j], a2[i], b2[g][2*h], b2[g][2*h + 1]);
                        mma16816(acc[i][j], a3[i], b1[g][2*h], b1[g][2*h + 1]);
                    }
        }
        if (sl + 1 < nslab) {
            int nb = buf ^ 1;
            #pragma unroll
            for (int p = 0; p < 6; p++) {
                __nv_bfloat16* sp = sdyn + (size_t)(nb * 6 + p) * (128 * SAS);
                *(uint4*)&sp[row0 * SAS + seg0] = rg[p][0];
                *(uint4*)&sp[row1 * SAS + seg1] = rg[p][1];
            }
            __syncthreads();
        }
    }
    #pragma unroll
    for (int i = 0; i < 2; i++) {
        int rA = bm + m0 + 16 * i + (lane >> 2);
        #pragma unroll
        for (int j = 0; j < 8; j++) {
            int col = bn + n0 + 8 * j + 2 * (lane & 3);
            float b0v = 0.f, b1v = 0.f;
            if (bias) { b0v = bias[col]; b1v = bias[col + 1]; }
            *(float2*)(C + (size_t)rA * N + col) =
                make_float2(acc[i][j][0] + b0v, acc[i][j][1] + b1v);
            *(float2*)(C + (size_t)(rA + 8) * N + col) =
                make_float2(acc[i][j][2] + b0v, acc[i][j][3] + b1v);
        }
    }
}

// ---------------------------------------------------------------------------
// tensor-core GRU recurrence, 2-plane / 3-term (layers 0/1; from R9)
// ---------------------------------------------------------------------------
__global__ __launch_bounds__(256, 1)
void k_recur_mma(const float* __restrict__ Gi, float* __restrict__ hist,
                 const __nv_bfloat16* __restrict__ Wh,
                 const __nv_bfloat16* __restrict__ Wl,
                 const float* __restrict__ bhh, const int* __restrict__ nsel) {
    extern __shared__ __nv_bfloat16 smb[];
    float* red = (float*)(smb + MSM_BF);
    int tid = threadIdx.x;
    int bt = blockIdx.x & 3, jt = blockIdx.x >> 2;
    int b0 = bt * 16, j0 = jt * 16;
    int wid = tid >> 5, lane = tid & 31;
    int jj = tid & 15, bb2 = tid >> 4;
    int j2 = j0 + jj, b2 = b0 + bb2;

    for (int idx = tid; idx < 48 * 512; idx += 256) {
        int r = idx >> 9, k = idx & 511;
        int g = r >> 4, jl = r & 15;
        size_t grow = (size_t)(g * 512 + j0 + jl) * 512 + k;
        smb[MSM_W  + r * SWS + k] = Wh[grow];
        smb[MSM_WL + r * SWS + k] = Wl[grow];
    }
    float br = bhh[j2], bz = bhh[512 + j2], bn2 = bhh[1024 + j2];
    int lim = nsel[b2];
    int maxlim = 0;
    #pragma unroll
    for (int b = 0; b < 16; b++) {
        int v = nsel[b0 + b];
        maxlim = v > maxlim ? v : maxlim;
    }
    unsigned* barp = &g_bar4[bt * 32];
    unsigned sbase = (unsigned)__cvta_generic_to_shared(smb);

    int alr = lane & 15, alh = (lane >> 4) * 16;
    int bro = ((lane >> 4) & 1) * 8 + (lane & 7);
    int bko = ((lane >> 3) & 1) * 16;

    __syncthreads();

    for (int t = 0; t < maxlim; t++) {
        const float* gp = Gi + ((size_t)b2 * TT + t) * G3;
        float gir = __ldcg(gp + j2);
        float giz = __ldcg(gp + 512 + j2);
        float gin = __ldcg(gp + 1024 + j2);

        if (t > 0) {
            if (tid == 0) {
                unsigned tgt = 32u * (unsigned)t;
                while (ld_acq(barp) < tgt) { }
            }
            __syncthreads();
        }

        const float* hsrc = g_h[t & 1];
        float hold = __ldcg(hsrc + (size_t)b2 * HH + j2);
        #pragma unroll
        for (int i = 0; i < 8; i++) {
            int id = tid + i * 256;
            int lb = id >> 7;
            int lk = (id & 127) * 4;
            float4 v = __ldcg((const float4*)(hsrc + (size_t)(b0 + lb) * HH + lk));
            __nv_bfloat162 h01 = __floats2bfloat162_rn(v.x, v.y);
            __nv_bfloat162 h23 = __floats2bfloat162_rn(v.z, v.w);
            __nv_bfloat162 l01 = __floats2bfloat162_rn(v.x - __low2float(h01),
                                                       v.y - __high2float(h01));
            __nv_bfloat162 l23 = __floats2bfloat162_rn(v.z - __low2float(h23),
                                                       v.w - __high2float(h23));
            int off = lb * SWS + lk;
            *(__nv_bfloat162*)&smb[MSM_HH + off]     = h01;
            *(__nv_bfloat162*)&smb[MSM_HH + off + 2] = h23;
            *(__nv_bfloat162*)&smb[MSM_HL + off]     = l01;
            *(__nv_bfloat162*)&smb[MSM_HL + off + 2] = l23;
        }
        __syncthreads();

        for (int u = wid; u < 12; u += 8) {
            int gt = u % 3, kq = u / 3;
            float acc0[4] = {0.f, 0.f, 0.f, 0.f};
            float acc1[4] = {0.f, 0.f, 0.f, 0.f};
            #pragma unroll
            for (int ks = 0; ks < 8; ks++) {
                int kk = kq * 128 + ks * 16;
                unsigned ah[4], al[4], bh[4], bl[4];
                unsigned ra = sbase + (unsigned)(MSM_HH + alr * SWS + kk) * 2 + alh;
                ldm4(ah, ra);
                ldm4(al, ra + (MSM_HL - MSM_HH) * 2);
                unsigned rb = sbase + (unsigned)((gt * 16 + bro) * SWS + kk) * 2 + bko;
                ldm4(bh, rb);
                ldm4(bl, rb + MSM_WL * 2);
                mma16816(acc0, ah, bh[0], bh[1]);
                mma16816(acc0, ah, bl[0], bl[1]);
                mma16816(acc0, al, bh[0], bh[1]);
                mma16816(acc1, ah, bh[2], bh[3]);
                mma16816(acc1, ah, bl[2], bl[3]);
                mma16816(acc1, al, bh[2], bh[3]);
            }
            int r = lane >> 2, c2 = 2 * (lane & 3);
            float* rp = red + (kq * 16 + r) * MRED_STR + gt * 16;
            *(float2*)(rp + c2)                    = make_float2(acc0[0], acc0[1]);
            *(float2*)(rp + 8 * MRED_STR + c2)     = make_float2(acc0[2], acc0[3]);
            *(float2*)(rp + 8 + c2)                = make_float2(acc1[0], acc1[1]);
            *(float2*)(rp + 8 * MRED_STR + 8 + c2) = make_float2(acc1[2], acc1[3]);
        }
        __syncthreads();

        float sr = br, sz = bz, sn = bn2;
        #pragma unroll
        for (int kq = 0; kq < 4; kq++) {
            const float* rp = red + (kq * 16 + bb2) * MRED_STR;
            sr += rp[jj];
            sz += rp[16 + jj];
            sn += rp[32 + jj];
        }
        float r_ = 1.f / (1.f + expf(-(gir + sr)));
        float z  = 1.f / (1.f + expf(-(giz + sz)));
        float n  = tanhf(gin + r_ * sn);
        float hn = (1.f - z) * n + z * hold;
        bool valid = t < lim;
        g_h[(t + 1) & 1][b2 * HH + j2] = valid ? hn : hold;
        hist[((size_t)b2 * TT + t) * HH + j2] = valid ? hn : 0.f;

        __syncthreads();
        if (tid == 0) red_rel(barp);
    }

    for (int t = maxlim; t < TT; t++)
        hist[((size_t)b2 * TT + t) * HH + j2] = 0.f;
}

// ---------------------------------------------------------------------------
// tensor-core GRU recurrence, 3-plane / 6-term (selector; near-fp32 exact)
// ---------------------------------------------------------------------------
__global__ __launch_bounds__(256, 1)
void k_recur_mma3(const float* __restrict__ Gi, float* __restrict__ hist,
                  const __nv_bfloat16* __restrict__ W1,
                  const __nv_bfloat16* __restrict__ W2,
                  const __nv_bfloat16* __restrict__ W3,
                  const float* __restrict__ bhh) {
    extern __shared__ __nv_bfloat16 smb[];
    float* red = (float*)(smb + M3_BF);
    int tid = threadIdx.x;
    int bt = blockIdx.x & 3, jt = blockIdx.x >> 2;
    int b0 = bt * 16, j0 = jt * 16;
    int wid = tid >> 5, lane = tid & 31;
    int jj = tid & 15, bb2 = tid >> 4;
    int j2 = j0 + jj, b2 = b0 + bb2;

    for (int idx = tid; idx < 48 * 512; idx += 256) {
        int r = idx >> 9, k = idx & 511;
        int g = r >> 4, jl = r & 15;
        size_t grow = (size_t)(g * 512 + j0 + jl) * 512 + k;
        smb[M3_W1 + r * SWS + k] = W1[grow];
        smb[M3_W2 + r * SWS + k] = W2[grow];
        smb[M3_W3 + r * SWS + k] = W3[grow];
    }
    float br = bhh[j2], bz = bhh[512 + j2], bn2 = bhh[1024 + j2];
    unsigned* barp = &g_bar4[bt * 32];
    unsigned sbase = (unsigned)__cvta_generic_to_shared(smb);

    int alr = lane & 15, alh = (lane >> 4) * 16;
    int bro = ((lane >> 4) & 1) * 8 + (lane & 7);
    int bko = ((lane >> 3) & 1) * 16;

    __syncthreads();

    for (int t = 0; t < TT; t++) {
        const float* gp = Gi + ((size_t)b2 * TT + t) * G3;
        float gir = __ldcg(gp + j2);
        float giz = __ldcg(gp + 512 + j2);
        float gin = __ldcg(gp + 1024 + j2);

        if (t > 0) {
            if (tid == 0) {
                unsigned tgt = 32u * (unsigned)t;
                while (ld_acq(barp) < tgt) { }
            }
            __syncthreads();
        }

        // stage h: fp32 -> 3 bf16 planes
        const float* hsrc = g_h[t & 1];
        float hold = __ldcg(hsrc + (size_t)b2 * HH + j2);
        #pragma unroll
        for (int i = 0; i < 8; i++) {
            int id = tid + i * 256;
            int lb = id >> 7;
            int lk = (id & 127) * 4;
            float4 v = __ldcg((const float4*)(hsrc + (size_t)(b0 + lb) * HH + lk));
            float xs[4] = {v.x, v.y, v.z, v.w};
            __nv_bfloat16 h1[4], h2[4], h3[4];
            #pragma unroll
            for (int c = 0; c < 4; c++) {
                h1[c] = __float2bfloat16(xs[c]);
                float r = xs[c] - __bfloat162float(h1[c]);
                h2[c] = __float2bfloat16(r);
                float r2 = r - __bfloat162float(h2[c]);
                h3[c] = __float2bfloat16(r2);
            }
            int off = lb * SWS + lk;
            *(__nv_bfloat162*)&smb[M3_H1 + off]     = *(__nv_bfloat162*)&h1[0];
            *(__nv_bfloat162*)&smb[M3_H1 + off + 2] = *(__nv_bfloat162*)&h1[2];
            *(__nv_bfloat162*)&smb[M3_H2 + off]     = *(__nv_bfloat162*)&h2[0];
            *(__nv_bfloat162*)&smb[M3_H2 + off + 2] = *(__nv_bfloat162*)&h2[2];
            *(__nv_bfloat162*)&smb[M3_H3 + off]     = *(__nv_bfloat162*)&h3[0];
            *(__nv_bfloat162*)&smb[M3_H3 + off + 2] = *(__nv_bfloat162*)&h3[2];
        }
        __syncthreads();

        for (int u = wid; u < 12; u += 8) {
            int gt = u % 3, kq = u / 3;
            float acc0[4] = {0.f, 0.f, 0.f, 0.f};
            float acc1[4] = {0.f, 0.f, 0.f, 0.f};
            #pragma unroll
            for (int ks = 0; ks < 8; ks++) {
                int kk = kq * 128 + ks * 16;
                unsigned a1[4], a2[4], a3[4], b1[4], b2[4], b3[4];
                unsigned ra = sbase + (unsigned)(M3_H1 + alr * SWS + kk) * 2 + alh;
                ldm4(a1, ra);
                ldm4(a2, ra + (M3_H2 - M3_H1) * 2);
                ldm4(a3, ra + (M3_H3 - M3_H1) * 2);
                unsigned rb = sbase + (unsigned)((gt * 16 + bro) * SWS + kk) * 2 + bko;
                ldm4(b1, rb);
                ldm4(b2, rb + M3_W2 * 2);
                ldm4(b3, rb + M3_W3 * 2);
                mma16816(acc0, a1, b1[0], b1[1]);
                mma16816(acc0, a1, b2[0], b2[1]);
                mma16816(acc0, a2, b1[0], b1[1]);
                mma16816(acc0, a1, b3[0], b3[1]);
                mma16816(acc0, a2, b2[0], b2[1]);
                mma16816(acc0, a3, b1[0], b1[1]);
                mma16816(acc1, a1, b1[2], b1[3]);
                mma16816(acc1, a1, b2[2], b2[3]);
                mma16816(acc1, a2, b1[2], b1[3]);
                mma16816(acc1, a1, b3[2], b3[3]);
                mma16816(acc1, a2, b2[2], b2[3]);
                mma16816(acc1, a3, b1[2], b1[3]);
            }
            int r = lane >> 2, c2 = 2 * (lane & 3);
            float* rp = red + (kq * 16 + r) * MRED_STR + gt * 16;
            *(float2*)(rp + c2)                    = make_float2(acc0[0], acc0[1]);
            *(float2*)(rp + 8 * MRED_STR + c2)     = make_float2(acc0[2], acc0[3]);
            *(float2*)(rp + 8 + c2)                = make_float2(acc1[0], acc1[1]);
            *(float2*)(rp + 8 * MRED_STR + 8 + c2) = make_float2(acc1[2], acc1[3]);
        }
        __syncthreads();

        float sr = br, sz = bz, sn = bn2;
        #pragma unroll
        for (int kq = 0; kq < 4; kq++) {
            const float* rp = red + (kq * 16 + bb2) * MRED_STR;
            sr += rp[jj];
            sz += rp[16 + jj];
            sn += rp[32 + jj];
        }
        float r_ = 1.f / (1.f + expf(-(gir + sr)));
        float z  = 1.f / (1.f + expf(-(giz + sz)));
        float n  = tanhf(gin + r_ * sn);
        float hn = (1.f - z) * n + z * hold;
        g_h[(t + 1) & 1][b2 * HH + j2] = hn;
        hist[((size_t)b2 * TT + t) * HH + j2] = hn;

        __syncthreads();
        if (tid == 0) red_rel(barp);
    }
}

// ---------------------------------------------------------------------------
__global__ void k_selargmax(const float* __restrict__ hist,
                            const float* __restrict__ Ws,
                            const float* __restrict__ bs) {
    int gw = (blockIdx.x * blockDim.x + threadIdx.x) >> 5;
    int lane = threadIdx.x & 31;
    if (gw >= BB * TT) return;
    const float* h = hist + (size_t)gw * HH;
    float l0 = 0.f, l1 = 0.f;
    #pragma unroll 4
    for (int jv = lane; jv < HH; jv += 32) {
        float hv = h[jv];
        l0 += hv * Ws[jv];
        l1 += hv * Ws[HH + jv];
    }
    #pragma unroll
    for (int o = 16; o; o >>= 1) {
        l0 += __shfl_down_sync(0xffffffffu, l0, o);
        l1 += __shfl_down_sync(0xffffffffu, l1, o);
    }
    if (lane == 0)
        g_sel[gw] = ((l1 + bs[1]) > (l0 + bs[0])) ? 1 : 0;
}

// ---------------------------------------------------------------------------
__global__ void k_fix(const int* __restrict__ mask) {
    int b = blockIdx.x;
    int lane = threadIdx.x;
    int len = 0;
    for (int t = lane; t < TT; t += 32) len += mask[b * TT + t];
    #pragma unroll
    for (int o = 16; o; o >>= 1) len += __shfl_down_sync(0xffffffffu, len, o);
    len = __shfl_sync(0xffffffffu, len, 0);
    int cnt = 0;
    for (int c = 0; c < TT; c += 32) {
        int t = c + lane;
        int s = g_sel[b * TT + t];
        if (t == 0) s = 1;
        if (t == len - 1) s = 1;
        if (t >= len) s = 0;
        unsigned bal = __ballot_sync(0xffffffffu, s);
        int pre = __popc(bal & ((1u << lane) - 1u));
        if (s) g_order[b * TT + cnt + pre] = t;
        cnt += __popc(bal);
    }
    if (lane == 0) g_nsel[b] = cnt;
}

// ---------------------------------------------------------------------------
__global__ void k_gather(const float* __restrict__ emb, float* __restrict__ dst) {
    int row = blockIdx.x;
    int b = row >> 9, p = row & 511;
    float4 v = make_float4(0.f, 0.f, 0.f, 0.f);
    if (p < g_nsel[b]) {
        int t = g_order[row];
        v = ((const float4*)(emb + ((size_t)b * TT + t) * EE))[threadIdx.x];
    }
    ((float4*)(dst + (size_t)row * EE))[threadIdx.x] = v;
}

// ---------------------------------------------------------------------------
__global__ void k_pool(const float* __restrict__ U, const float* __restrict__ bc,
                       int kw, int Nn, int seg) {
    int b = blockIdx.x;
    int f = threadIdx.x;
    int tlim = TT - kw + 1;
    int t0 = blockIdx.y * 64;
    int t1 = t0 + 64 < tlim ? t0 + 64 : tlim;
    float bcv = bc[f];
    float m = 0.f;
    const float* Ub = U + (size_t)b * TT * Nn + (size_t)f * kw;
    for (int t = t0; t < t1; t++) {
        float s = bcv;
        #pragma unroll 5
        for (int dt = 0; dt < kw; dt++)
            s += Ub[(size_t)(t + dt) * Nn + dt];
        m = fmaxf(m, fmaxf(s, 0.f));
    }
    atomicMax((int*)&g_pooled[b * (3 * NF) + seg + f], __float_as_int(m));
}

// ---------------------------------------------------------------------------
__global__ void k_final(const float* __restrict__ Wo, const float* __restrict__ bo,
                        float* __restrict__ out) {
    __shared__ float redf[256];
    int b = blockIdx.x, tid = threadIdx.x;
    float s = 0.f;
    for (int f = tid; f < 3 * NF; f += 256)
        s += g_pooled[b * (3 * NF) + f] * Wo[f];
    redf[tid] = s;
    __syncthreads();
    for (int o = 128; o; o >>= 1) {
        if (tid < o) redf[tid] += redf[tid + o];
        __syncthreads();
    }
    if (tid == 0) out[b] = redf[0] + bo[0];
}

// ---------------------------------------------------------------------------
extern "C" void kernel_launch(void* const* d_in, const int* in_sizes, int n_in,
                              void* d_out, int out_size) {
    const float* emb   = (const float*)d_in[0];
    const int*   mask  = (const int*)  d_in[1];
    const float* Wih_c = (const float*)d_in[2];
    const float* Whh_c = (const float*)d_in[3];
    const float* bih_c = (const float*)d_in[4];
    const float* bhh_c = (const float*)d_in[5];
    const float* Ws    = (const float*)d_in[6];
    const float* bs    = (const float*)d_in[7];
    const float* Wih0  = (const float*)d_in[8];
    const float* Whh0  = (const float*)d_in[9];
    const float* bih0  = (const float*)d_in[10];
    const float* bhh0  = (const float*)d_in[11];
    const float* Wih1  = (const float*)d_in[12];
    const float* Whh1  = (const float*)d_in[13];
    const float* bih1  = (const float*)d_in[14];
    const float* bhh1  = (const float*)d_in[15];
    const float* Wc3   = (const float*)d_in[16];
    const float* bc3   = (const float*)d_in[17];
    const float* Wc4   = (const float*)d_in[18];
    const float* bc4   = (const float*)d_in[19];
    const float* Wc5   = (const float*)d_in[20];
    const float* bc5   = (const float*)d_in[21];
    const float* Wo    = (const float*)d_in[22];
    const float* bo    = (const float*)d_in[23];
    float* out = (float*)d_out;

    cudaFuncSetAttribute(k_recur_mma, cudaFuncAttributeMaxDynamicSharedMemorySize,
                         MSM_BYTES);
    cudaFuncSetAttribute(k_recur_mma3, cudaFuncAttributeMaxDynamicSharedMemorySize,
                         M3_BYTES);
    cudaFuncSetAttribute(k_bgemm, cudaFuncAttributeMaxDynamicSharedMemorySize,
                         BSM_BYTES);
    cudaFuncSetAttribute(k_bgemm3, cudaFuncAttributeMaxDynamicSharedMemorySize,
                         BSM3_BYTES);

    float *pGi, *pS0, *pS1, *pNe, *pU;
    int* pNsel;
    __nv_bfloat16 *pAh, *pAl, *pA3, *pWh, *pWl, *pW3;
    cudaGetSymbolAddress((void**)&pGi,   g_Gi);
    cudaGetSymbolAddress((void**)&pS0,   g_seq0);
    cudaGetSymbolAddress((void**)&pS1,   g_seq1);
    cudaGetSymbolAddress((void**)&pNe,   g_newemb);
    cudaGetSymbolAddress((void**)&pU,    g_U);
    cudaGetSymbolAddress((void**)&pNsel, g_nsel);
    cudaGetSymbolAddress((void**)&pAh,   g_Ah);
    cudaGetSymbolAddress((void**)&pAl,   g_Al);
    cudaGetSymbolAddress((void**)&pA3,   g_A3);
    cudaGetSymbolAddress((void**)&pWh,   g_Wh);
    cudaGetSymbolAddress((void**)&pWl,   g_Wl);
    cudaGetSymbolAddress((void**)&pW3,   g_W3);

    const size_t nAE = (size_t)MALL * EE;
    const size_t nAH = (size_t)MALL * HH;

    // ---- selector GRU: 3-plane/6-term bf16 tensor path (near-fp32 exact) ----
    k_split3<<<(int)((nAE + 255)/256), 256>>>(emb, pAh, pAl, pA3, nAE);
    k_split3<<<(G3*EE + 255)/256, 256>>>(Wih_c, pWh, pWl, pW3, (size_t)G3*EE);
    k_bgemm3<<<dim3(G3/128, MALL/128), 256, BSM3_BYTES>>>(
        pGi, pAh, pAl, pA3, pWh, pWl, pW3, bih_c, MALL, G3, EE);
    k_split3<<<(G3*HH + 255)/256, 256>>>(Whh_c, pWh, pWl, pW3, (size_t)G3*HH);
    k_reset<<<256, 256>>>();
    k_recur_mma3<<<NBLK, 256, M3_BYTES>>>(pGi, pS0, pWh, pWl, pW3, bhh_c);
    k_selargmax<<<(BB*TT*32 + 255)/256, 256>>>(pS0, Ws, bs);
    k_fix<<<BB, 32>>>(mask);
    k_gather<<<MALL, EE/4>>>(emb, pNe);

    // ---- layer 0: 2-plane split-bf16 GEMM + mma recurrence ----
    k_split<<<(int)((nAE + 255)/256), 256>>>(pNe, pAh, pAl, nAE);
    k_split<<<(G3*EE + 255)/256, 256>>>(Wih0, pWh, pWl, (size_t)G3*EE);
    k_bgemm<<<dim3(G3/128, MALL/128), 256, BSM_BYTES>>>(
        pGi, pAh, pAl, pWh, pWl, bih0, MALL, G3, EE, pNsel, 1);
    k_split<<<(G3*HH + 255)/256, 256>>>(Whh0, pWh, pWl, (size_t)G3*HH);
    k_reset<<<256, 256>>>();
    k_recur_mma<<<NBLK, 256, MSM_BYTES>>>(pGi, pS1, pWh, pWl, bhh0, pNsel);

    // ---- layer 1 ----
    k_split<<<(int)((nAH + 255)/256), 256>>>(pS1, pAh, pAl, nAH);
    k_split<<<(G3*HH + 255)/256, 256>>>(Wih1, pWh, pWl, (size_t)G3*HH);
    k_bgemm<<<dim3(G3/128, MALL/128), 256, BSM_BYTES>>>(
        pGi, pAh, pAl, pWh, pWl, bih1, MALL, G3, HH, pNsel, 1);
    k_split<<<(G3*HH + 255)/256, 256>>>(Whh1, pWh, pWl, (size_t)G3*HH);
    k_reset<<<256, 256>>>();
    k_recur_mma<<<NBLK, 256, MSM_BYTES>>>(pGi, pS0, pWh, pWl, bhh1, pNsel);

    // ---- convs (2-plane split-bf16 GEMM + pool) ----
    k_zero_pooled<<<(BB*3*NF + 255)/256, 256>>>();
    k_split<<<(int)((nAH + 255)/256), 256>>>(pS0, pAh, pAl, nAH);

    k_split<<<(NF*3*HH + 255)/256, 256>>>(Wc3, pWh, pWl, (size_t)NF*3*HH);
    k_bgemm<<<dim3((NF*3)/128, MALL/128), 256, BSM_BYTES>>>(
        pU, pAh, pAl, pWh, pWl, nullptr, MALL, NF*3, HH, pNsel, 2);
    k_pool<<<dim3(BB, 8), NF>>>(pU, bc3, 3, NF*3, 0);

    k_split<<<(NF*4*HH + 255)/256, 256>>>(Wc4, pWh, pWl, (size_t)NF*4*HH);
    k_bgemm<<<dim3((NF*4)/128, MALL/128), 256, BSM_BYTES>>>(
        pU, pAh, pAl, pWh, pWl, nullptr, MALL, NF*4, HH, pNsel, 2);
    k_pool<<<dim3(BB, 8), NF>>>(pU, bc4, 4, NF*4, NF);

    k_split<<<(NF*5*HH + 255)/256, 256>>>(Wc5, pWh, pWl, (size_t)NF*5*HH);
    k_bgemm<<<dim3((NF*5)/128, MALL/128), 256, BSM_BYTES>>>(
        pU, pAh, pAl, pWh, pWl, nullptr, MALL, NF*5, HH, pNsel, 2);
    k_pool<<<dim3(BB, 8), NF>>>(pU, bc5, 5, NF*5, 2*NF);

    // ---- final projection ----
    k_final<<<BB, 256>>>(Wo, bo, out);
}

// round 12
// speedup vs baseline: 1.9707x; 1.0252x over previous
#include <cuda_runtime.h>
#include <cuda_bf16.h>
#include <math.h>
#include <stdint.h>
#include <stddef.h>

typedef unsigned long long u64;

// Problem dims
#define BB    64
#define TT    512
#define EE    768
#define HH    512
#define G3    1536
#define NF    256
#define MALL  (BB*TT)          // 32768

#define NBLK      128

// -------- mma recurrence config (2-plane, layers) --------
#define SWS     520
#define MSM_W   0
#define MSM_WL  (48*SWS)
#define MSM_HH  (96*SWS)
#define MSM_HL  (112*SWS)
#define MSM_BF  (128*SWS)
#define MRED_STR 52
#define MSM_BYTES (MSM_BF*2 + 4*16*MRED_STR*4)   // 146432 B

// -------- mma recurrence config (3-plane, selector) --------
#define M3_W1  0
#define M3_W2  (48*SWS)
#define M3_W3  (96*SWS)
#define M3_H1  (144*SWS)
#define M3_H2  (160*SWS)
#define M3_H3  (176*SWS)
#define M3_BF  (192*SWS)
#define M3_BYTES (M3_BF*2 + 4*16*MRED_STR*4)     // 212992 B

// -------- bf16 tensor GEMM config --------
#define SAS   40
#define OPSZ  (128*SAS*2)
#define BSM_BYTES  (8*OPSZ)          // 2-plane: 2 bufs x 4 planes = 81920 B
#define BSM3_BYTES (12*OPSZ)         // 3-plane: 2 bufs x 6 planes = 122880 B

// ----------------- device scratch (statics; no cudaMalloc allowed) ----------
__device__ float g_Gi[(size_t)MALL * G3];
__device__ float g_seq0[(size_t)MALL * HH];
__device__ float g_seq1[(size_t)MALL * HH];
__device__ float g_newemb[(size_t)MALL * EE];
__device__ float g_U[(size_t)MALL * (NF*5)];
__device__ float g_h[2][BB * HH];
__device__ int   g_sel[BB * TT];
__device__ int   g_order[BB * TT];
__device__ int   g_nsel[BB];
__device__ float g_pooled[BB * 3 * NF];
__device__ unsigned g_bar4[4 * 32];
// bf16 split buffers (3rd plane used by selector path only)
__device__ __nv_bfloat16 g_Ah[(size_t)MALL * EE];
__device__ __nv_bfloat16 g_Al[(size_t)MALL * EE];
__device__ __nv_bfloat16 g_A3[(size_t)MALL * EE];
__device__ __nv_bfloat16 g_Wh[G3 * EE];
__device__ __nv_bfloat16 g_Wl[G3 * EE];
__device__ __nv_bfloat16 g_W3[G3 * EE];

// ----------------------------- sync helpers ---------------------------------
__device__ __forceinline__ unsigned ld_acq(const unsigned* p) {
    unsigned v;
    asm volatile("ld.acquire.gpu.global.u32 %0,[%1];" : "=r"(v) : "l"(p));
    return v;
}
__device__ __forceinline__ void red_rel(unsigned* p) {
    asm volatile("red.release.gpu.global.add.u32 [%0],1;" :: "l"(p));
}
// ----------------------------- mma helpers ----------------------------------
__device__ __forceinline__ void ldm4(unsigned* r, unsigned addr) {
    asm volatile("ldmatrix.sync.aligned.m8n8.x4.shared.b16 {%0,%1,%2,%3}, [%4];"
                 : "=r"(r[0]), "=r"(r[1]), "=r"(r[2]), "=r"(r[3]) : "r"(addr));
}
__device__ __forceinline__ void mma16816(float* c, const unsigned* a,
                                         unsigned b0, unsigned b1) {
    asm volatile("mma.sync.aligned.m16n8k16.row.col.f32.bf16.bf16.f32 "
                 "{%0,%1,%2,%3}, {%4,%5,%6,%7}, {%8,%9}, {%0,%1,%2,%3};"
                 : "+f"(c[0]), "+f"(c[1]), "+f"(c[2]), "+f"(c[3])
                 : "r"(a[0]), "r"(a[1]), "r"(a[2]), "r"(a[3]), "r"(b0), "r"(b1));
}

// ---------------------------------------------------------------------------
__global__ void k_reset() {
    int i = blockIdx.x * blockDim.x + threadIdx.x;
    if (i < 4 * 32) g_bar4[i] = 0u;
    if (i < 2 * BB * HH) ((float*)g_h)[i] = 0.f;
}
__global__ void k_zero_pooled() {
    int i = blockIdx.x * blockDim.x + threadIdx.x;
    if (i < BB * 3 * NF) g_pooled[i] = 0.f;
}
// split fp32 -> 2 bf16 planes
__global__ void k_split(const float* __restrict__ src,
                        __nv_bfloat16* __restrict__ p1,
                        __nv_bfloat16* __restrict__ p2, size_t n) {
    size_t i = (size_t)blockIdx.x * blockDim.x + threadIdx.x;
    if (i >= n) return;
    float x = src[i];
    __nv_bfloat16 h = __float2bfloat16(x);
    p1[i] = h;
    p2[i] = __float2bfloat16(x - __bfloat162float(h));
}
// split fp32 -> 3 bf16 planes (residual chain; combined error ~2^-24)
__global__ void k_split3(const float* __restrict__ src,
                         __nv_bfloat16* __restrict__ p1,
                         __nv_bfloat16* __restrict__ p2,
                         __nv_bfloat16* __restrict__ p3, size_t n) {
    size_t i = (size_t)blockIdx.x * blockDim.x + threadIdx.x;
    if (i >= n) return;
    float x = src[i];
    __nv_bfloat16 h1 = __float2bfloat16(x);
    float r = x - __bfloat162float(h1);
    __nv_bfloat16 h2 = __float2bfloat16(r);
    float r2 = r - __bfloat162float(h2);
    p1[i] = h1;
    p2[i] = h2;
    p3[i] = __float2bfloat16(r2);
}

// ---------------------------------------------------------------------------
// split-bf16 tensor-core GEMM, 2-plane / 3-term (layers + convs)
// ---------------------------------------------------------------------------
__global__ __launch_bounds__(256, 1)
void k_bgemm(float* __restrict__ C,
             const __nv_bfloat16* __restrict__ Ah, const __nv_bfloat16* __restrict__ Al,
             const __nv_bfloat16* __restrict__ Bh, const __nv_bfloat16* __restrict__ Bl,
             const float* __restrict__ bias,
             int M, int N, int K, const int* __restrict__ nsel, int mode) {
    extern __shared__ __nv_bfloat16 sdyn[];
    int tid = threadIdx.x;
    int bm = blockIdx.y * 128;
    int bn = blockIdx.x * 128;

    if (mode != 0) {
        int p0 = bm & 511;
        if (p0 >= nsel[bm >> 9]) {
            if (mode == 2) {
                float4 z = make_float4(0.f, 0.f, 0.f, 0.f);
                for (int i = tid; i < 128 * 32; i += 256) {
                    int row = i >> 5, c4 = (i & 31) * 4;
                    *(float4*)(C + (size_t)(bm + row) * N + bn + c4) = z;
                }
            }
            return;
        }
    }

    int wid = tid >> 5, lane = tid & 31;
    int m0 = (wid & 3) * 32, n0 = (wid >> 2) * 64;
    unsigned sbase = (unsigned)__cvta_generic_to_shared(sdyn);

    const __nv_bfloat16* gp[4];
    gp[0] = Ah; gp[1] = Al; gp[2] = Bh; gp[3] = Bl;
    int rbase[4] = {bm, bm, bn, bn};
    int id0 = tid * 2, id1 = tid * 2 + 1;
    int row0 = id0 >> 2, seg0 = (id0 & 3) * 8;
    int row1 = id1 >> 2, seg1 = (id1 & 3) * 8;

    float acc[2][8][4];
    #pragma unroll
    for (int i = 0; i < 2; i++)
        #pragma unroll
        for (int j = 0; j < 8; j++)
            #pragma unroll
            for (int c = 0; c < 4; c++) acc[i][j][c] = 0.f;

    uint4 rg[4][2];
    #pragma unroll
    for (int p = 0; p < 4; p++) {
        rg[p][0] = *(const uint4*)(gp[p] + (size_t)(rbase[p] + row0) * K + seg0);
        rg[p][1] = *(const uint4*)(gp[p] + (size_t)(rbase[p] + row1) * K + seg1);
    }
    #pragma unroll
    for (int p = 0; p < 4; p++) {
        __nv_bfloat16* sp = sdyn + (size_t)p * (128 * SAS);
        *(uint4*)&sp[row0 * SAS + seg0] = rg[p][0];
        *(uint4*)&sp[row1 * SAS + seg1] = rg[p][1];
    }
    __syncthreads();

    int alr = lane & 15, alh = (lane >> 4) * 16;
    int bro = ((lane >> 4) & 1) * 8 + (lane & 7);
    int bko = ((lane >> 3) & 1) * 16;

    int nslab = K >> 5;
    for (int sl = 0; sl < nslab; sl++) {
        int buf = sl & 1;
        if (sl + 1 < nslab) {
            int k0 = (sl + 1) * 32;
            #pragma unroll
            for (int p = 0; p < 4; p++) {
                rg[p][0] = *(const uint4*)(gp[p] + (size_t)(rbase[p] + row0) * K + k0 + seg0);
                rg[p][1] = *(const uint4*)(gp[p] + (size_t)(rbase[p] + row1) * K + k0 + seg1);
            }
        }
        unsigned base = sbase + (unsigned)buf * (4 * OPSZ);
        #pragma unroll
        for (int kk = 0; kk < 32; kk += 16) {
            unsigned ah[2][4], al[2][4], bh[4][4], bl[4][4];
            #pragma unroll
            for (int i = 0; i < 2; i++) {
                unsigned ra = base + ((m0 + 16 * i + alr) * SAS + kk) * 2 + alh;
                ldm4(ah[i], ra);
                ldm4(al[i], ra + OPSZ);
            }
            #pragma unroll
            for (int g = 0; g < 4; g++) {
                unsigned rb = base + 2 * OPSZ + ((n0 + 16 * g + bro) * SAS + kk) * 2 + bko;
                ldm4(bh[g], rb);
                ldm4(bl[g], rb + OPSZ);
            }
            #pragma unroll
            for (int i = 0; i < 2; i++)
                #pragma unroll
                for (int g = 0; g < 4; g++)
                    #pragma unroll
                    for (int h = 0; h < 2; h++) {
                        int j = 2 * g + h;
                        mma16816(acc[i][j], ah[i], bh[g][2*h], bh[g][2*h + 1]);
                        mma16816(acc[i][j], ah[i], bl[g][2*h], bl[g][2*h + 1]);
                        mma16816(acc[i][j], al[i], bh[g][2*h], bh[g][2*h + 1]);
                    }
        }
        if (sl + 1 < nslab) {
            int nb = buf ^ 1;
            #pragma unroll
            for (int p = 0; p < 4; p++) {
                __nv_bfloat16* sp = sdyn + (size_t)(nb * 4 + p) * (128 * SAS);
                *(uint4*)&sp[row0 * SAS + seg0] = rg[p][0];
                *(uint4*)&sp[row1 * SAS + seg1] = rg[p][1];
            }
            __syncthreads();
        }
    }
    #pragma unroll
    for (int i = 0; i < 2; i++) {
        int rA = bm + m0 + 16 * i + (lane >> 2);
        #pragma unroll
        for (int j = 0; j < 8; j++) {
            int col = bn + n0 + 8 * j + 2 * (lane & 3);
            float b0v = 0.f, b1v = 0.f;
            if (bias) { b0v = bias[col]; b1v = bias[col + 1]; }
            *(float2*)(C + (size_t)rA * N + col) =
                make_float2(acc[i][j][0] + b0v, acc[i][j][1] + b1v);
            *(float2*)(C + (size_t)(rA + 8) * N + col) =
                make_float2(acc[i][j][2] + b0v, acc[i][j][3] + b1v);
        }
    }
}

// ---------------------------------------------------------------------------
// split-bf16 GEMM, 3-plane / 6-term (selector; error ~2^-23, near-fp32)
// ---------------------------------------------------------------------------
__global__ __launch_bounds__(256, 1)
void k_bgemm3(float* __restrict__ C,
              const __nv_bfloat16* __restrict__ A1, const __nv_bfloat16* __restrict__ A2,
              const __nv_bfloat16* __restrict__ A3,
              const __nv_bfloat16* __restrict__ B1, const __nv_bfloat16* __restrict__ B2,
              const __nv_bfloat16* __restrict__ B3,
              const float* __restrict__ bias, int M, int N, int K) {
    extern __shared__ __nv_bfloat16 sdyn[];
    int tid = threadIdx.x;
    int bm = blockIdx.y * 128;
    int bn = blockIdx.x * 128;
    int wid = tid >> 5, lane = tid & 31;
    int m0 = (wid & 3) * 32, n0 = (wid >> 2) * 64;
    unsigned sbase = (unsigned)__cvta_generic_to_shared(sdyn);

    const __nv_bfloat16* gp[6];
    gp[0] = A1; gp[1] = A2; gp[2] = A3; gp[3] = B1; gp[4] = B2; gp[5] = B3;
    int rbase[6] = {bm, bm, bm, bn, bn, bn};
    int id0 = tid * 2, id1 = tid * 2 + 1;
    int row0 = id0 >> 2, seg0 = (id0 & 3) * 8;
    int row1 = id1 >> 2, seg1 = (id1 & 3) * 8;

    float acc[2][8][4];
    #pragma unroll
    for (int i = 0; i < 2; i++)
        #pragma unroll
        for (int j = 0; j < 8; j++)
            #pragma unroll
            for (int c = 0; c < 4; c++) acc[i][j][c] = 0.f;

    uint4 rg[6][2];
    #pragma unroll
    for (int p = 0; p < 6; p++) {
        rg[p][0] = *(const uint4*)(gp[p] + (size_t)(rbase[p] + row0) * K + seg0);
        rg[p][1] = *(const uint4*)(gp[p] + (size_t)(rbase[p] + row1) * K + seg1);
    }
    #pragma unroll
    for (int p = 0; p < 6; p++) {
        __nv_bfloat16* sp = sdyn + (size_t)p * (128 * SAS);
        *(uint4*)&sp[row0 * SAS + seg0] = rg[p][0];
        *(uint4*)&sp[row1 * SAS + seg1] = rg[p][1];
    }
    __syncthreads();

    int alr = lane & 15, alh = (lane >> 4) * 16;
    int bro = ((lane >> 4) & 1) * 8 + (lane & 7);
    int bko = ((lane >> 3) & 1) * 16;

    int nslab = K >> 5;
    for (int sl = 0; sl < nslab; sl++) {
        int buf = sl & 1;
        if (sl + 1 < nslab) {
            int k0 = (sl + 1) * 32;
            #pragma unroll
            for (int p = 0; p < 6; p++) {
                rg[p][0] = *(const uint4*)(gp[p] + (size_t)(rbase[p] + row0) * K + k0 + seg0);
                rg[p][1] = *(const uint4*)(gp[p] + (size_t)(rbase[p] + row1) * K + k0 + seg1);
            }
        }
        unsigned base = sbase + (unsigned)buf * (6 * OPSZ);
        #pragma unroll
        for (int kk = 0; kk < 32; kk += 16) {
            unsigned a1[2][4], a2[2][4], a3[2][4];
            unsigned b1[4][4], b2[4][4], b3[4][4];
            #pragma unroll
            for (int i = 0; i < 2; i++) {
                unsigned ra = base + ((m0 + 16 * i + alr) * SAS + kk) * 2 + alh;
                ldm4(a1[i], ra);
                ldm4(a2[i], ra + OPSZ);
                ldm4(a3[i], ra + 2 * OPSZ);
            }
            #pragma unroll
            for (int g = 0; g < 4; g++) {
                unsigned rb = base + 3 * OPSZ + ((n0 + 16 * g + bro) * SAS + kk) * 2 + bko;
                ldm4(b1[g], rb);
                ldm4(b2[g], rb + OPSZ);
                ldm4(b3[g], rb + 2 * OPSZ);
            }
            #pragma unroll
            for (int i = 0; i < 2; i++)
                #pragma unroll
                for (int g = 0; g < 4; g++)
                    #pragma unroll
                    for (int h = 0; h < 2; h++) {
                        int j = 2 * g + h;
                        mma16816(acc[i][j], a1[i], b1[g][2*h], b1[g][2*h + 1]);
                        mma16816(acc[i][j], a1[i], b2[g][2*h], b2[g][2*h + 1]);
                        mma16816(acc[i][j], a2[i], b1[g][2*h], b1[g][2*h + 1]);
                        mma16816(acc[i][j], a1[i], b3[g][2*h], b3[g][2*h + 1]);
                        mma16816(acc[i][j], a2[i], b2[g][2*h], b2[g][2*h + 1]);
                        mma16816(acc[i][j], a3[i], b1[g][2*h], b1[g][2*h + 1]);
                    }
        }
        if (sl + 1 < nslab) {
            int nb = buf ^ 1;
            #pragma unroll
            for (int p = 0; p < 6; p++) {
                __nv_bfloat16* sp = sdyn + (size_t)(nb * 6 + p) * (128 * SAS);
                *(uint4*)&sp[row0 * SAS + seg0] = rg[p][0];
                *(uint4*)&sp[row1 * SAS + seg1] = rg[p][1];
            }
            __syncthreads();
        }
    }
    #pragma unroll
    for (int i = 0; i < 2; i++) {
        int rA = bm + m0 + 16 * i + (lane >> 2);
        #pragma unroll
        for (int j = 0; j < 8; j++) {
            int col = bn + n0 + 8 * j + 2 * (lane & 3);
            float b0v = 0.f, b1v = 0.f;
            if (bias) { b0v = bias[col]; b1v = bias[col + 1]; }
            *(float2*)(C + (size_t)rA * N + col) =
                make_float2(acc[i][j][0] + b0v, acc[i][j][1] + b1v);
            *(float2*)(C + (size_t)(rA + 8) * N + col) =
                make_float2(acc[i][j][2] + b0v, acc[i][j][3] + b1v);
        }
    }
}

// ---------------------------------------------------------------------------
// tensor-core GRU recurrence, 2-plane / 3-term (layers 0/1), 512 threads:
// 16 warps -> 4/SMSP hides ldm/mma/barrier latency; 12 units 1/warp.
// ---------------------------------------------------------------------------
__global__ __launch_bounds__(512, 1)
void k_recur_mma(const float* __restrict__ Gi, float* __restrict__ hist,
                 const __nv_bfloat16* __restrict__ Wh,
                 const __nv_bfloat16* __restrict__ Wl,
                 const float* __restrict__ bhh, const int* __restrict__ nsel) {
    extern __shared__ __nv_bfloat16 smb[];
    float* red = (float*)(smb + MSM_BF);
    int tid = threadIdx.x;
    int bt = blockIdx.x & 3, jt = blockIdx.x >> 2;
    int b0 = bt * 16, j0 = jt * 16;
    int wid = tid >> 5, lane = tid & 31;
    int jj = tid & 15, bb2 = tid >> 4;
    bool ph2 = tid < 256;
    int j2 = j0 + jj;
    int b2 = b0 + (bb2 & 15);

    for (int idx = tid; idx < 48 * 512; idx += 512) {
        int r = idx >> 9, k = idx & 511;
        int g = r >> 4, jl = r & 15;
        size_t grow = (size_t)(g * 512 + j0 + jl) * 512 + k;
        smb[MSM_W  + r * SWS + k] = Wh[grow];
        smb[MSM_WL + r * SWS + k] = Wl[grow];
    }
    float br = bhh[j2], bz = bhh[512 + j2], bn2 = bhh[1024 + j2];
    int lim = ph2 ? nsel[b2] : TT;
    int maxlim = 0;
    #pragma unroll
    for (int b = 0; b < 16; b++) {
        int v = nsel[b0 + b];
        maxlim = v > maxlim ? v : maxlim;
    }
    unsigned* barp = &g_bar4[bt * 32];
    unsigned sbase = (unsigned)__cvta_generic_to_shared(smb);

    int alr = lane & 15, alh = (lane >> 4) * 16;
    int bro = ((lane >> 4) & 1) * 8 + (lane & 7);
    int bko = ((lane >> 3) & 1) * 16;

    __syncthreads();

    for (int t = 0; t < maxlim; t++) {
        float gir = 0.f, giz = 0.f, gin = 0.f;
        if (ph2) {
            const float* gp = Gi + ((size_t)b2 * TT + t) * G3;
            gir = __ldcg(gp + j2);
            giz = __ldcg(gp + 512 + j2);
            gin = __ldcg(gp + 1024 + j2);
        }

        if (t > 0) {
            if (tid == 0) {
                unsigned tgt = 32u * (unsigned)t;
                while (ld_acq(barp) < tgt) { }
            }
            __syncthreads();
        }

        const float* hsrc = g_h[t & 1];
        float hold = 0.f;
        if (ph2) hold = __ldcg(hsrc + (size_t)b2 * HH + j2);
        #pragma unroll
        for (int i = 0; i < 4; i++) {
            int id = tid + i * 512;
            int lb = id >> 7;
            int lk = (id & 127) * 4;
            float4 v = __ldcg((const float4*)(hsrc + (size_t)(b0 + lb) * HH + lk));
            __nv_bfloat162 h01 = __floats2bfloat162_rn(v.x, v.y);
            __nv_bfloat162 h23 = __floats2bfloat162_rn(v.z, v.w);
            __nv_bfloat162 l01 = __floats2bfloat162_rn(v.x - __low2float(h01),
                                                       v.y - __high2float(h01));
            __nv_bfloat162 l23 = __floats2bfloat162_rn(v.z - __low2float(h23),
                                                       v.w - __high2float(h23));
            int off = lb * SWS + lk;
            *(__nv_bfloat162*)&smb[MSM_HH + off]     = h01;
            *(__nv_bfloat162*)&smb[MSM_HH + off + 2] = h23;
            *(__nv_bfloat162*)&smb[MSM_HL + off]     = l01;
            *(__nv_bfloat162*)&smb[MSM_HL + off + 2] = l23;
        }
        __syncthreads();

        if (wid < 12) {
            int u = wid;
            int gt = u % 3, kq = u / 3;
            float acc0[4] = {0.f, 0.f, 0.f, 0.f};
            float acc1[4] = {0.f, 0.f, 0.f, 0.f};
            #pragma unroll
            for (int ks = 0; ks < 8; ks++) {
                int kk = kq * 128 + ks * 16;
                unsigned ah[4], al[4], bh[4], bl[4];
                unsigned ra = sbase + (unsigned)(MSM_HH + alr * SWS + kk) * 2 + alh;
                ldm4(ah, ra);
                ldm4(al, ra + (MSM_HL - MSM_HH) * 2);
                unsigned rb = sbase + (unsigned)((gt * 16 + bro) * SWS + kk) * 2 + bko;
                ldm4(bh, rb);
                ldm4(bl, rb + MSM_WL * 2);
                mma16816(acc0, ah, bh[0], bh[1]);
                mma16816(acc0, ah, bl[0], bl[1]);
                mma16816(acc0, al, bh[0], bh[1]);
                mma16816(acc1, ah, bh[2], bh[3]);
                mma16816(acc1, ah, bl[2], bl[3]);
                mma16816(acc1, al, bh[2], bh[3]);
            }
            int r = lane >> 2, c2 = 2 * (lane & 3);
            float* rp = red + (kq * 16 + r) * MRED_STR + gt * 16;
            *(float2*)(rp + c2)                    = make_float2(acc0[0], acc0[1]);
            *(float2*)(rp + 8 * MRED_STR + c2)     = make_float2(acc0[2], acc0[3]);
            *(float2*)(rp + 8 + c2)                = make_float2(acc1[0], acc1[1]);
            *(float2*)(rp + 8 * MRED_STR + 8 + c2) = make_float2(acc1[2], acc1[3]);
        }
        __syncthreads();

        if (ph2) {
            float sr = br, sz = bz, sn = bn2;
            #pragma unroll
            for (int kq = 0; kq < 4; kq++) {
                const float* rp = red + (kq * 16 + (bb2 & 15)) * MRED_STR;
                sr += rp[jj];
                sz += rp[16 + jj];
                sn += rp[32 + jj];
            }
            float r_ = 1.f / (1.f + expf(-(gir + sr)));
            float z  = 1.f / (1.f + expf(-(giz + sz)));
            float n  = tanhf(gin + r_ * sn);
            float hn = (1.f - z) * n + z * hold;
            bool valid = t < lim;
            g_h[(t + 1) & 1][b2 * HH + j2] = valid ? hn : hold;
            hist[((size_t)b2 * TT + t) * HH + j2] = valid ? hn : 0.f;
        }

        __syncthreads();
        if (tid == 0) red_rel(barp);
    }

    if (ph2)
        for (int t = maxlim; t < TT; t++)
            hist[((size_t)b2 * TT + t) * HH + j2] = 0.f;
}

// ---------------------------------------------------------------------------
// tensor-core GRU recurrence, 3-plane / 6-term (selector), 512 threads.
// ---------------------------------------------------------------------------
__global__ __launch_bounds__(512, 1)
void k_recur_mma3(const float* __restrict__ Gi, float* __restrict__ hist,
                  const __nv_bfloat16* __restrict__ W1,
                  const __nv_bfloat16* __restrict__ W2,
                  const __nv_bfloat16* __restrict__ W3,
                  const float* __restrict__ bhh) {
    extern __shared__ __nv_bfloat16 smb[];
    float* red = (float*)(smb + M3_BF);
    int tid = threadIdx.x;
    int bt = blockIdx.x & 3, jt = blockIdx.x >> 2;
    int b0 = bt * 16, j0 = jt * 16;
    int wid = tid >> 5, lane = tid & 31;
    int jj = tid & 15, bb2 = tid >> 4;
    bool ph2 = tid < 256;
    int j2 = j0 + jj;
    int b2 = b0 + (bb2 & 15);

    for (int idx = tid; idx < 48 * 512; idx += 512) {
        int r = idx >> 9, k = idx & 511;
        int g = r >> 4, jl = r & 15;
        size_t grow = (size_t)(g * 512 + j0 + jl) * 512 + k;
        smb[M3_W1 + r * SWS + k] = W1[grow];
        smb[M3_W2 + r * SWS + k] = W2[grow];
        smb[M3_W3 + r * SWS + k] = W3[grow];
    }
    float br = bhh[j2], bz = bhh[512 + j2], bn2 = bhh[1024 + j2];
    unsigned* barp = &g_bar4[bt * 32];
    unsigned sbase = (unsigned)__cvta_generic_to_shared(smb);

    int alr = lane & 15, alh = (lane >> 4) * 16;
    int bro = ((lane >> 4) & 1) * 8 + (lane & 7);
    int bko = ((lane >> 3) & 1) * 16;

    __syncthreads();

    for (int t = 0; t < TT; t++) {
        float gir = 0.f, giz = 0.f, gin = 0.f;
        if (ph2) {
            const float* gp = Gi + ((size_t)b2 * TT + t) * G3;
            gir = __ldcg(gp + j2);
            giz = __ldcg(gp + 512 + j2);
            gin = __ldcg(gp + 1024 + j2);
        }

        if (t > 0) {
            if (tid == 0) {
                unsigned tgt = 32u * (unsigned)t;
                while (ld_acq(barp) < tgt) { }
            }
            __syncthreads();
        }

        // stage h: fp32 -> 3 bf16 planes
        const float* hsrc = g_h[t & 1];
        float hold = 0.f;
        if (ph2) hold = __ldcg(hsrc + (size_t)b2 * HH + j2);
        #pragma unroll
        for (int i = 0; i < 4; i++) {
            int id = tid + i * 512;
            int lb = id >> 7;
            int lk = (id & 127) * 4;
            float4 v = __ldcg((const float4*)(hsrc + (size_t)(b0 + lb) * HH + lk));
            float xs[4] = {v.x, v.y, v.z, v.w};
            __nv_bfloat16 h1[4], h2[4], h3[4];
            #pragma unroll
            for (int c = 0; c < 4; c++) {
                h1[c] = __float2bfloat16(xs[c]);
                float r = xs[c] - __bfloat162float(h1[c]);
                h2[c] = __float2bfloat16(r);
                float r2 = r - __bfloat162float(h2[c]);
                h3[c] = __float2bfloat16(r2);
            }
            int off = lb * SWS + lk;
            *(__nv_bfloat162*)&smb[M3_H1 + off]     = *(__nv_bfloat162*)&h1[0];
            *(__nv_bfloat162*)&smb[M3_H1 + off + 2] = *(__nv_bfloat162*)&h1[2];
            *(__nv_bfloat162*)&smb[M3_H2 + off]     = *(__nv_bfloat162*)&h2[0];
            *(__nv_bfloat162*)&smb[M3_H2 + off + 2] = *(__nv_bfloat162*)&h2[2];
            *(__nv_bfloat162*)&smb[M3_H3 + off]     = *(__nv_bfloat162*)&h3[0];
            *(__nv_bfloat162*)&smb[M3_H3 + off + 2] = *(__nv_bfloat162*)&h3[2];
        }
        __syncthreads();

        if (wid < 12) {
            int u = wid;
            int gt = u % 3, kq = u / 3;
            float acc0[4] = {0.f, 0.f, 0.f, 0.f};
            float acc1[4] = {0.f, 0.f, 0.f, 0.f};
            #pragma unroll
            for (int ks = 0; ks < 8; ks++) {
                int kk = kq * 128 + ks * 16;
                unsigned a1[4], a2[4], a3[4], b1[4], b2[4], b3[4];
                unsigned ra = sbase + (unsigned)(M3_H1 + alr * SWS + kk) * 2 + alh;
                ldm4(a1, ra);
                ldm4(a2, ra + (M3_H2 - M3_H1) * 2);
                ldm4(a3, ra + (M3_H3 - M3_H1) * 2);
                unsigned rb = sbase + (unsigned)((gt * 16 + bro) * SWS + kk) * 2 + bko;
                ldm4(b1, rb);
                ldm4(b2, rb + M3_W2 * 2);
                ldm4(b3, rb + M3_W3 * 2);
                mma16816(acc0, a1, b1[0], b1[1]);
                mma16816(acc0, a1, b2[0], b2[1]);
                mma16816(acc0, a2, b1[0], b1[1]);
                mma16816(acc0, a1, b3[0], b3[1]);
                mma16816(acc0, a2, b2[0], b2[1]);
                mma16816(acc0, a3, b1[0], b1[1]);
                mma16816(acc1, a1, b1[2], b1[3]);
                mma16816(acc1, a1, b2[2], b2[3]);
                mma16816(acc1, a2, b1[2], b1[3]);
                mma16816(acc1, a1, b3[2], b3[3]);
                mma16816(acc1, a2, b2[2], b2[3]);
                mma16816(acc1, a3, b1[2], b1[3]);
            }
            int r = lane >> 2, c2 = 2 * (lane & 3);
            float* rp = red + (kq * 16 + r) * MRED_STR + gt * 16;
            *(float2*)(rp + c2)                    = make_float2(acc0[0], acc0[1]);
            *(float2*)(rp + 8 * MRED_STR + c2)     = make_float2(acc0[2], acc0[3]);
            *(float2*)(rp + 8 + c2)                = make_float2(acc1[0], acc1[1]);
            *(float2*)(rp + 8 * MRED_STR + 8 + c2) = make_float2(acc1[2], acc1[3]);
        }
        __syncthreads();

        if (ph2) {
            float sr = br, sz = bz, sn = bn2;
            #pragma unroll
            for (int kq = 0; kq < 4; kq++) {
                const float* rp = red + (kq * 16 + (bb2 & 15)) * MRED_STR;
                sr += rp[jj];
                sz += rp[16 + jj];
                sn += rp[32 + jj];
            }
            float r_ = 1.f / (1.f + expf(-(gir + sr)));
            float z  = 1.f / (1.f + expf(-(giz + sz)));
            float n  = tanhf(gin + r_ * sn);
            float hn = (1.f - z) * n + z * hold;
            g_h[(t + 1) & 1][b2 * HH + j2] = hn;
            hist[((size_t)b2 * TT + t) * HH + j2] = hn;
        }

        __syncthreads();
        if (tid == 0) red_rel(barp);
    }
}

// ---------------------------------------------------------------------------
__global__ void k_selargmax(const float* __restrict__ hist,
                            const float* __restrict__ Ws,
                            const float* __restrict__ bs) {
    int gw = (blockIdx.x * blockDim.x + threadIdx.x) >> 5;
    int lane = threadIdx.x & 31;
    if (gw >= BB * TT) return;
    const float* h = hist + (size_t)gw * HH;
    float l0 = 0.f, l1 = 0.f;
    #pragma unroll 4
    for (int jv = lane; jv < HH; jv += 32) {
        float hv = h[jv];
        l0 += hv * Ws[jv];
        l1 += hv * Ws[HH + jv];
    }
    #pragma unroll
    for (int o = 16; o; o >>= 1) {
        l0 += __shfl_down_sync(0xffffffffu, l0, o);
        l1 += __shfl_down_sync(0xffffffffu, l1, o);
    }
    if (lane == 0)
        g_sel[gw] = ((l1 + bs[1]) > (l0 + bs[0])) ? 1 : 0;
}

// ---------------------------------------------------------------------------
__global__ void k_fix(const int* __restrict__ mask) {
    int b = blockIdx.x;
    int lane = threadIdx.x;
    int len = 0;
    for (int t = lane; t < TT; t += 32) len += mask[b * TT + t];
    #pragma unroll
    for (int o = 16; o; o >>= 1) len += __shfl_down_sync(0xffffffffu, len, o);
    len = __shfl_sync(0xffffffffu, len, 0);
    int cnt = 0;
    for (int c = 0; c < TT; c += 32) {
        int t = c + lane;
        int s = g_sel[b * TT + t];
        if (t == 0) s = 1;
        if (t == len - 1) s = 1;
        if (t >= len) s = 0;
        unsigned bal = __ballot_sync(0xffffffffu, s);
        int pre = __popc(bal & ((1u << lane) - 1u));
        if (s) g_order[b * TT + cnt + pre] = t;
        cnt += __popc(bal);
    }
    if (lane == 0) g_nsel[b] = cnt;
}

// ---------------------------------------------------------------------------
__global__ void k_gather(const float* __restrict__ emb, float* __restrict__ dst) {
    int row = blockIdx.x;
    int b = row >> 9, p = row & 511;
    float4 v = make_float4(0.f, 0.f, 0.f, 0.f);
    if (p < g_nsel[b]) {
        int t = g_order[row];
        v = ((const float4*)(emb + ((size_t)b * TT + t) * EE))[threadIdx.x];
    }
    ((float4*)(dst + (size_t)row * EE))[threadIdx.x] = v;
}

// ---------------------------------------------------------------------------
// pool with nsel early-exit: windows entirely past nsel contribute relu(bc).
// ---------------------------------------------------------------------------
__global__ void k_pool(const float* __restrict__ U, const float* __restrict__ bc,
                       int kw, int Nn, int seg) {
    int b = blockIdx.x;
    int f = threadIdx.x;
    int tlim = TT - kw + 1;
    int ns = g_nsel[b];
    int tcap = ns < tlim ? ns : tlim;
    int t0 = blockIdx.y * 64;
    int t1 = t0 + 64 < tlim ? t0 + 64 : tlim;
    float bcv = bc[f];
    float m = 0.f;
    if (t1 > tcap) m = fmaxf(bcv, 0.f);       // some window in range is all-zero
    int t1c = t1 < tcap ? t1 : tcap;
    const float* Ub = U + (size_t)b * TT * Nn + (size_t)f * kw;
    for (int t = t0; t < t1c; t++) {
        float s = bcv;
        #pragma unroll 5
        for (int dt = 0; dt < kw; dt++)
            s += Ub[(size_t)(t + dt) * Nn + dt];
        m = fmaxf(m, fmaxf(s, 0.f));
    }
    atomicMax((int*)&g_pooled[b * (3 * NF) + seg + f], __float_as_int(m));
}

// ---------------------------------------------------------------------------
__global__ void k_final(const float* __restrict__ Wo, const float* __restrict__ bo,
                        float* __restrict__ out) {
    __shared__ float redf[256];
    int b = blockIdx.x, tid = threadIdx.x;
    float s = 0.f;
    for (int f = tid; f < 3 * NF; f += 256)
        s += g_pooled[b * (3 * NF) + f] * Wo[f];
    redf[tid] = s;
    __syncthreads();
    for (int o = 128; o; o >>= 1) {
        if (tid < o) redf[tid] += redf[tid + o];
        __syncthreads();
    }
    if (tid == 0) out[b] = redf[0] + bo[0];
}

// ---------------------------------------------------------------------------
extern "C" void kernel_launch(void* const* d_in, const int* in_sizes, int n_in,
                              void* d_out, int out_size) {
    const float* emb   = (const float*)d_in[0];
    const int*   mask  = (const int*)  d_in[1];
    const float* Wih_c = (const float*)d_in[2];
    const float* Whh_c = (const float*)d_in[3];
    const float* bih_c = (const float*)d_in[4];
    const float* bhh_c = (const float*)d_in[5];
    const float* Ws    = (const float*)d_in[6];
    const float* bs    = (const float*)d_in[7];
    const float* Wih0  = (const float*)d_in[8];
    const float* Whh0  = (const float*)d_in[9];
    const float* bih0  = (const float*)d_in[10];
    const float* bhh0  = (const float*)d_in[11];
    const float* Wih1  = (const float*)d_in[12];
    const float* Whh1  = (const float*)d_in[13];
    const float* bih1  = (const float*)d_in[14];
    const float* bhh1  = (const float*)d_in[15];
    const float* Wc3   = (const float*)d_in[16];
    const float* bc3   = (const float*)d_in[17];
    const float* Wc4   = (const float*)d_in[18];
    const float* bc4   = (const float*)d_in[19];
    const float* Wc5   = (const float*)d_in[20];
    const float* bc5   = (const float*)d_in[21];
    const float* Wo    = (const float*)d_in[22];
    const float* bo    = (const float*)d_in[23];
    float* out = (float*)d_out;

    cudaFuncSetAttribute(k_recur_mma, cudaFuncAttributeMaxDynamicSharedMemorySize,
                         MSM_BYTES);
    cudaFuncSetAttribute(k_recur_mma3, cudaFuncAttributeMaxDynamicSharedMemorySize,
                         M3_BYTES);
    cudaFuncSetAttribute(k_bgemm, cudaFuncAttributeMaxDynamicSharedMemorySize,
                         BSM_BYTES);
    cudaFuncSetAttribute(k_bgemm3, cudaFuncAttributeMaxDynamicSharedMemorySize,
                         BSM3_BYTES);

    float *pGi, *pS0, *pS1, *pNe, *pU;
    int* pNsel;
    __nv_bfloat16 *pAh, *pAl, *pA3, *pWh, *pWl, *pW3;
    cudaGetSymbolAddress((void**)&pGi,   g_Gi);
    cudaGetSymbolAddress((void**)&pS0,   g_seq0);
    cudaGetSymbolAddress((void**)&pS1,   g_seq1);
    cudaGetSymbolAddress((void**)&pNe,   g_newemb);
    cudaGetSymbolAddress((void**)&pU,    g_U);
    cudaGetSymbolAddress((void**)&pNsel, g_nsel);
    cudaGetSymbolAddress((void**)&pAh,   g_Ah);
    cudaGetSymbolAddress((void**)&pAl,   g_Al);
    cudaGetSymbolAddress((void**)&pA3,   g_A3);
    cudaGetSymbolAddress((void**)&pWh,   g_Wh);
    cudaGetSymbolAddress((void**)&pWl,   g_Wl);
    cudaGetSymbolAddress((void**)&pW3,   g_W3);

    const size_t nAE = (size_t)MALL * EE;
    const size_t nAH = (size_t)MALL * HH;

    // ---- selector GRU: 3-plane/6-term bf16 tensor path (near-fp32 exact) ----
    k_split3<<<(int)((nAE + 255)/256), 256>>>(emb, pAh, pAl, pA3, nAE);
    k_split3<<<(G3*EE + 255)/256, 256>>>(Wih_c, pWh, pWl, pW3, (size_t)G3*EE);
    k_bgemm3<<<dim3(G3/128, MALL/128), 256, BSM3_BYTES>>>(
        pGi, pAh, pAl, pA3, pWh, pWl, pW3, bih_c, MALL, G3, EE);
    k_split3<<<(G3*HH + 255)/256, 256>>>(Whh_c, pWh, pWl, pW3, (size_t)G3*HH);
    k_reset<<<256, 256>>>();
    k_recur_mma3<<<NBLK, 512, M3_BYTES>>>(pGi, pS0, pWh, pWl, pW3, bhh_c);
    k_selargmax<<<(BB*TT*32 + 255)/256, 256>>>(pS0, Ws, bs);
    k_fix<<<BB, 32>>>(mask);
    k_gather<<<MALL, EE/4>>>(emb, pNe);

    // ---- layer 0: 2-plane split-bf16 GEMM + mma recurrence ----
    k_split<<<(int)((nAE + 255)/256), 256>>>(pNe, pAh, pAl, nAE);
    k_split<<<(G3*EE + 255)/256, 256>>>(Wih0, pWh, pWl, (size_t)G3*EE);
    k_bgemm<<<dim3(G3/128, MALL/128), 256, BSM_BYTES>>>(
        pGi, pAh, pAl, pWh, pWl, bih0, MALL, G3, EE, pNsel, 1);
    k_split<<<(G3*HH + 255)/256, 256>>>(Whh0, pWh, pWl, (size_t)G3*HH);
    k_reset<<<256, 256>>>();
    k_recur_mma<<<NBLK, 512, MSM_BYTES>>>(pGi, pS1, pWh, pWl, bhh0, pNsel);

    // ---- layer 1 ----
    k_split<<<(int)((nAH + 255)/256), 256>>>(pS1, pAh, pAl, nAH);
    k_split<<<(G3*HH + 255)/256, 256>>>(Wih1, pWh, pWl, (size_t)G3*HH);
    k_bgemm<<<dim3(G3/128, MALL/128), 256, BSM_BYTES>>>(
        pGi, pAh, pAl, pWh, pWl, bih1, MALL, G3, HH, pNsel, 1);
    k_split<<<(G3*HH + 255)/256, 256>>>(Whh1, pWh, pWl, (size_t)G3*HH);
    k_reset<<<256, 256>>>();
    k_recur_mma<<<NBLK, 512, MSM_BYTES>>>(pGi, pS0, pWh, pWl, bhh1, pNsel);

    // ---- convs (2-plane split-bf16 GEMM + pool with nsel early-exit) ----
    k_zero_pooled<<<(BB*3*NF + 255)/256, 256>>>();
    k_split<<<(int)((nAH + 255)/256), 256>>>(pS0, pAh, pAl, nAH);

    k_split<<<(NF*3*HH + 255)/256, 256>>>(Wc3, pWh, pWl, (size_t)NF*3*HH);
    k_bgemm<<<dim3((NF*3)/128, MALL/128), 256, BSM_BYTES>>>(
        pU, pAh, pAl, pWh, pWl, nullptr, MALL, NF*3, HH, pNsel, 2);
    k_pool<<<dim3(BB, 8), NF>>>(pU, bc3, 3, NF*3, 0);

    k_split<<<(NF*4*HH + 255)/256, 256>>>(Wc4, pWh, pWl, (size_t)NF*4*HH);
    k_bgemm<<<dim3((NF*4)/128, MALL/128), 256, BSM_BYTES>>>(
        pU, pAh, pAl, pWh, pWl, nullptr, MALL, NF*4, HH, pNsel, 2);
    k_pool<<<dim3(BB, 8), NF>>>(pU, bc4, 4, NF*4, NF);

    k_split<<<(NF*5*HH + 255)/256, 256>>>(Wc5, pWh, pWl, (size_t)NF*5*HH);
    k_bgemm<<<dim3((NF*5)/128, MALL/128), 256, BSM_BYTES>>>(
        pU, pAh, pAl, pWh, pWl, nullptr, MALL, NF*5, HH, pNsel, 2);
    k_pool<<<dim3(BB, 8), NF>>>(pU, bc5, 5, NF*5, 2*NF);

    // ---- final projection ----
    k_final<<<BB, 256>>>(Wo, bo, out);
}

// round 13
// speedup vs baseline: 2.0237x; 1.0269x over previous
#include <cuda_runtime.h>
#include <cuda_bf16.h>
#include <math.h>
#include <stdint.h>
#include <stddef.h>

typedef unsigned long long u64;

// Problem dims
#define BB    64
#define TT    512
#define EE    768
#define HH    512
#define G3    1536
#define NF    256
#define MALL  (BB*TT)          // 32768

#define NBLK      128

// -------- mma recurrence config (2-plane, layers) --------
#define SWS     520
#define MSM_W   0
#define MSM_WL  (48*SWS)
#define MSM_HH  (96*SWS)
#define MSM_HL  (112*SWS)
#define MSM_BF  (128*SWS)
#define MRED_STR 52
#define MSM_BYTES (MSM_BF*2 + 4*16*MRED_STR*4)   // 146432 B

// -------- mma recurrence config (3-plane, selector) --------
#define M3_W1  0
#define M3_W2  (48*SWS)
#define M3_W3  (96*SWS)
#define M3_H1  (144*SWS)
#define M3_H2  (160*SWS)
#define M3_H3  (176*SWS)
#define M3_BF  (192*SWS)
#define M3_BYTES (M3_BF*2 + 4*16*MRED_STR*4)     // 212992 B

// -------- bf16 tensor GEMM config --------
#define SAS   40
#define OPSZ  (128*SAS*2)
#define BSM_BYTES  (8*OPSZ)          // 2-plane: 2 bufs x 4 planes = 81920 B
#define BSM3_BYTES (12*OPSZ)         // 3-plane: 2 bufs x 6 planes = 122880 B

// ----------------- device scratch (statics; no cudaMalloc allowed) ----------
__device__ float g_Gi[(size_t)MALL * G3];
__device__ float g_seq0[(size_t)MALL * HH];    // selector hist (fp32, argmax)
__device__ float g_U[(size_t)MALL * (NF*5)];
__device__ float g_h[2][BB * HH];
__device__ int   g_sel[BB * TT];
__device__ int   g_order[BB * TT];
__device__ int   g_nsel[BB];
__device__ float g_pooled[BB * 3 * NF];
__device__ unsigned g_bar4[4 * 32];
// bf16 split buffers (3rd plane used by selector path only)
__device__ __nv_bfloat16 g_Ah[(size_t)MALL * EE];
__device__ __nv_bfloat16 g_Al[(size_t)MALL * EE];
__device__ __nv_bfloat16 g_A3[(size_t)MALL * EE];
__device__ __nv_bfloat16 g_Wh[G3 * EE];
__device__ __nv_bfloat16 g_Wl[G3 * EE];
__device__ __nv_bfloat16 g_W3[G3 * EE];

// ----------------------------- sync helpers ---------------------------------
__device__ __forceinline__ unsigned ld_acq(const unsigned* p) {
    unsigned v;
    asm volatile("ld.acquire.gpu.global.u32 %0,[%1];" : "=r"(v) : "l"(p));
    return v;
}
__device__ __forceinline__ void red_rel(unsigned* p) {
    asm volatile("red.release.gpu.global.add.u32 [%0],1;" :: "l"(p));
}
// ----------------------------- mma helpers ----------------------------------
__device__ __forceinline__ void ldm4(unsigned* r, unsigned addr) {
    asm volatile("ldmatrix.sync.aligned.m8n8.x4.shared.b16 {%0,%1,%2,%3}, [%4];"
                 : "=r"(r[0]), "=r"(r[1]), "=r"(r[2]), "=r"(r[3]) : "r"(addr));
}
__device__ __forceinline__ void mma16816(float* c, const unsigned* a,
                                         unsigned b0, unsigned b1) {
    asm volatile("mma.sync.aligned.m16n8k16.row.col.f32.bf16.bf16.f32 "
                 "{%0,%1,%2,%3}, {%4,%5,%6,%7}, {%8,%9}, {%0,%1,%2,%3};"
                 : "+f"(c[0]), "+f"(c[1]), "+f"(c[2]), "+f"(c[3])
                 : "r"(a[0]), "r"(a[1]), "r"(a[2]), "r"(a[3]), "r"(b0), "r"(b1));
}

// ---------------------------------------------------------------------------
__global__ void k_reset() {
    int i = blockIdx.x * blockDim.x + threadIdx.x;
    if (i < 4 * 32) g_bar4[i] = 0u;
    if (i < 2 * BB * HH) ((float*)g_h)[i] = 0.f;
}
__global__ void k_zero_pooled() {
    int i = blockIdx.x * blockDim.x + threadIdx.x;
    if (i < BB * 3 * NF) g_pooled[i] = 0.f;
}
// split fp32 -> 2 bf16 planes
__global__ void k_split(const float* __restrict__ src,
                        __nv_bfloat16* __restrict__ p1,
                        __nv_bfloat16* __restrict__ p2, size_t n) {
    size_t i = (size_t)blockIdx.x * blockDim.x + threadIdx.x;
    if (i >= n) return;
    float x = src[i];
    __nv_bfloat16 h = __float2bfloat16(x);
    p1[i] = h;
    p2[i] = __float2bfloat16(x - __bfloat162float(h));
}
// split fp32 -> 3 bf16 planes (residual chain; combined error ~2^-24)
__global__ void k_split3(const float* __restrict__ src,
                         __nv_bfloat16* __restrict__ p1,
                         __nv_bfloat16* __restrict__ p2,
                         __nv_bfloat16* __restrict__ p3, size_t n) {
    size_t i = (size_t)blockIdx.x * blockDim.x + threadIdx.x;
    if (i >= n) return;
    float x = src[i];
    __nv_bfloat16 h1 = __float2bfloat16(x);
    float r = x - __bfloat162float(h1);
    __nv_bfloat16 h2 = __float2bfloat16(r);
    float r2 = r - __bfloat162float(h2);
    p1[i] = h1;
    p2[i] = h2;
    p3[i] = __float2bfloat16(r2);
}

// ---------------------------------------------------------------------------
// split-bf16 tensor-core GEMM, 2-plane / 3-term (layers + convs)
// mode 0 compute; mode 1 skip all-invalid 128-row tiles (no write).
// ---------------------------------------------------------------------------
__global__ __launch_bounds__(256, 1)
void k_bgemm(float* __restrict__ C,
             const __nv_bfloat16* __restrict__ Ah, const __nv_bfloat16* __restrict__ Al,
             const __nv_bfloat16* __restrict__ Bh, const __nv_bfloat16* __restrict__ Bl,
             const float* __restrict__ bias,
             int M, int N, int K, const int* __restrict__ nsel, int mode) {
    extern __shared__ __nv_bfloat16 sdyn[];
    int tid = threadIdx.x;
    int bm = blockIdx.y * 128;
    int bn = blockIdx.x * 128;

    if (mode != 0) {
        int p0 = bm & 511;
        if (p0 >= nsel[bm >> 9]) return;
    }

    int wid = tid >> 5, lane = tid & 31;
    int m0 = (wid & 3) * 32, n0 = (wid >> 2) * 64;
    unsigned sbase = (unsigned)__cvta_generic_to_shared(sdyn);

    const __nv_bfloat16* gp[4];
    gp[0] = Ah; gp[1] = Al; gp[2] = Bh; gp[3] = Bl;
    int rbase[4] = {bm, bm, bn, bn};
    int id0 = tid * 2, id1 = tid * 2 + 1;
    int row0 = id0 >> 2, seg0 = (id0 & 3) * 8;
    int row1 = id1 >> 2, seg1 = (id1 & 3) * 8;

    float acc[2][8][4];
    #pragma unroll
    for (int i = 0; i < 2; i++)
        #pragma unroll
        for (int j = 0; j < 8; j++)
            #pragma unroll
            for (int c = 0; c < 4; c++) acc[i][j][c] = 0.f;

    uint4 rg[4][2];
    #pragma unroll
    for (int p = 0; p < 4; p++) {
        rg[p][0] = *(const uint4*)(gp[p] + (size_t)(rbase[p] + row0) * K + seg0);
        rg[p][1] = *(const uint4*)(gp[p] + (size_t)(rbase[p] + row1) * K + seg1);
    }
    #pragma unroll
    for (int p = 0; p < 4; p++) {
        __nv_bfloat16* sp = sdyn + (size_t)p * (128 * SAS);
        *(uint4*)&sp[row0 * SAS + seg0] = rg[p][0];
        *(uint4*)&sp[row1 * SAS + seg1] = rg[p][1];
    }
    __syncthreads();

    int alr = lane & 15, alh = (lane >> 4) * 16;
    int bro = ((lane >> 4) & 1) * 8 + (lane & 7);
    int bko = ((lane >> 3) & 1) * 16;

    int nslab = K >> 5;
    for (int sl = 0; sl < nslab; sl++) {
        int buf = sl & 1;
        if (sl + 1 < nslab) {
            int k0 = (sl + 1) * 32;
            #pragma unroll
            for (int p = 0; p < 4; p++) {
                rg[p][0] = *(const uint4*)(gp[p] + (size_t)(rbase[p] + row0) * K + k0 + seg0);
                rg[p][1] = *(const uint4*)(gp[p] + (size_t)(rbase[p] + row1) * K + k0 + seg1);
            }
        }
        unsigned base = sbase + (unsigned)buf * (4 * OPSZ);
        #pragma unroll
        for (int kk = 0; kk < 32; kk += 16) {
            unsigned ah[2][4], al[2][4], bh[4][4], bl[4][4];
            #pragma unroll
            for (int i = 0; i < 2; i++) {
                unsigned ra = base + ((m0 + 16 * i + alr) * SAS + kk) * 2 + alh;
                ldm4(ah[i], ra);
                ldm4(al[i], ra + OPSZ);
            }
            #pragma unroll
            for (int g = 0; g < 4; g++) {
                unsigned rb = base + 2 * OPSZ + ((n0 + 16 * g + bro) * SAS + kk) * 2 + bko;
                ldm4(bh[g], rb);
                ldm4(bl[g], rb + OPSZ);
            }
            #pragma unroll
            for (int i = 0; i < 2; i++)
                #pragma unroll
                for (int g = 0; g < 4; g++)
                    #pragma unroll
                    for (int h = 0; h < 2; h++) {
                        int j = 2 * g + h;
                        mma16816(acc[i][j], ah[i], bh[g][2*h], bh[g][2*h + 1]);
                        mma16816(acc[i][j], ah[i], bl[g][2*h], bl[g][2*h + 1]);
                        mma16816(acc[i][j], al[i], bh[g][2*h], bh[g][2*h + 1]);
                    }
        }
        if (sl + 1 < nslab) {
            int nb = buf ^ 1;
            #pragma unroll
            for (int p = 0; p < 4; p++) {
                __nv_bfloat16* sp = sdyn + (size_t)(nb * 4 + p) * (128 * SAS);
                *(uint4*)&sp[row0 * SAS + seg0] = rg[p][0];
                *(uint4*)&sp[row1 * SAS + seg1] = rg[p][1];
            }
            __syncthreads();
        }
    }
    #pragma unroll
    for (int i = 0; i < 2; i++) {
        int rA = bm + m0 + 16 * i + (lane >> 2);
        #pragma unroll
        for (int j = 0; j < 8; j++) {
            int col = bn + n0 + 8 * j + 2 * (lane & 3);
            float b0v = 0.f, b1v = 0.f;
            if (bias) { b0v = bias[col]; b1v = bias[col + 1]; }
            *(float2*)(C + (size_t)rA * N + col) =
                make_float2(acc[i][j][0] + b0v, acc[i][j][1] + b1v);
            *(float2*)(C + (size_t)(rA + 8) * N + col) =
                make_float2(acc[i][j][2] + b0v, acc[i][j][3] + b1v);
        }
    }
}

// ---------------------------------------------------------------------------
// split-bf16 GEMM, 3-plane / 6-term (selector; error ~2^-23, near-fp32)
// ---------------------------------------------------------------------------
__global__ __launch_bounds__(256, 1)
void k_bgemm3(float* __restrict__ C,
              const __nv_bfloat16* __restrict__ A1, const __nv_bfloat16* __restrict__ A2,
              const __nv_bfloat16* __restrict__ A3,
              const __nv_bfloat16* __restrict__ B1, const __nv_bfloat16* __restrict__ B2,
              const __nv_bfloat16* __restrict__ B3,
              const float* __restrict__ bias, int M, int N, int K) {
    extern __shared__ __nv_bfloat16 sdyn[];
    int tid = threadIdx.x;
    int bm = blockIdx.y * 128;
    int bn = blockIdx.x * 128;
    int wid = tid >> 5, lane = tid & 31;
    int m0 = (wid & 3) * 32, n0 = (wid >> 2) * 64;
    unsigned sbase = (unsigned)__cvta_generic_to_shared(sdyn);

    const __nv_bfloat16* gp[6];
    gp[0] = A1; gp[1] = A2; gp[2] = A3; gp[3] = B1; gp[4] = B2; gp[5] = B3;
    int rbase[6] = {bm, bm, bm, bn, bn, bn};
    int id0 = tid * 2, id1 = tid * 2 + 1;
    int row0 = id0 >> 2, seg0 = (id0 & 3) * 8;
    int row1 = id1 >> 2, seg1 = (id1 & 3) * 8;

    float acc[2][8][4];
    #pragma unroll
    for (int i = 0; i < 2; i++)
        #pragma unroll
        for (int j = 0; j < 8; j++)
            #pragma unroll
            for (int c = 0; c < 4; c++) acc[i][j][c] = 0.f;

    uint4 rg[6][2];
    #pragma unroll
    for (int p = 0; p < 6; p++) {
        rg[p][0] = *(const uint4*)(gp[p] + (size_t)(rbase[p] + row0) * K + seg0);
        rg[p][1] = *(const uint4*)(gp[p] + (size_t)(rbase[p] + row1) * K + seg1);
    }
    #pragma unroll
    for (int p = 0; p < 6; p++) {
        __nv_bfloat16* sp = sdyn + (size_t)p * (128 * SAS);
        *(uint4*)&sp[row0 * SAS + seg0] = rg[p][0];
        *(uint4*)&sp[row1 * SAS + seg1] = rg[p][1];
    }
    __syncthreads();

    int alr = lane & 15, alh = (lane >> 4) * 16;
    int bro = ((lane >> 4) & 1) * 8 + (lane & 7);
    int bko = ((lane >> 3) & 1) * 16;

    int nslab = K >> 5;
    for (int sl = 0; sl < nslab; sl++) {
        int buf = sl & 1;
        if (sl + 1 < nslab) {
            int k0 = (sl + 1) * 32;
            #pragma unroll
            for (int p = 0; p < 6; p++) {
                rg[p][0] = *(const uint4*)(gp[p] + (size_t)(rbase[p] + row0) * K + k0 + seg0);
                rg[p][1] = *(const uint4*)(gp[p] + (size_t)(rbase[p] + row1) * K + k0 + seg1);
            }
        }
        unsigned base = sbase + (unsigned)buf * (6 * OPSZ);
        #pragma unroll
        for (int kk = 0; kk < 32; kk += 16) {
            unsigned a1[2][4], a2[2][4], a3[2][4];
            unsigned b1[4][4], b2[4][4], b3[4][4];
            #pragma unroll
            for (int i = 0; i < 2; i++) {
                unsigned ra = base + ((m0 + 16 * i + alr) * SAS + kk) * 2 + alh;
                ldm4(a1[i], ra);
                ldm4(a2[i], ra + OPSZ);
                ldm4(a3[i], ra + 2 * OPSZ);
            }
            #pragma unroll
            for (int g = 0; g < 4; g++) {
                unsigned rb = base + 3 * OPSZ + ((n0 + 16 * g + bro) * SAS + kk) * 2 + bko;
                ldm4(b1[g], rb);
                ldm4(b2[g], rb + OPSZ);
                ldm4(b3[g], rb + 2 * OPSZ);
            }
            #pragma unroll
            for (int i = 0; i < 2; i++)
                #pragma unroll
                for (int g = 0; g < 4; g++)
                    #pragma unroll
                    for (int h = 0; h < 2; h++) {
                        int j = 2 * g + h;
                        mma16816(acc[i][j], a1[i], b1[g][2*h], b1[g][2*h + 1]);
                        mma16816(acc[i][j], a1[i], b2[g][2*h], b2[g][2*h + 1]);
                        mma16816(acc[i][j], a2[i], b1[g][2*h], b1[g][2*h + 1]);
                        mma16816(acc[i][j], a1[i], b3[g][2*h], b3[g][2*h + 1]);
                        mma16816(acc[i][j], a2[i], b2[g][2*h], b2[g][2*h + 1]);
                        mma16816(acc[i][j], a3[i], b1[g][2*h], b1[g][2*h + 1]);
                    }
        }
        if (sl + 1 < nslab) {
            int nb = buf ^ 1;
            #pragma unroll
            for (int p = 0; p < 6; p++) {
                __nv_bfloat16* sp = sdyn + (size_t)(nb * 6 + p) * (128 * SAS);
                *(uint4*)&sp[row0 * SAS + seg0] = rg[p][0];
                *(uint4*)&sp[row1 * SAS + seg1] = rg[p][1];
            }
            __syncthreads();
        }
    }
    #pragma unroll
    for (int i = 0; i < 2; i++) {
        int rA = bm + m0 + 16 * i + (lane >> 2);
        #pragma unroll
        for (int j = 0; j < 8; j++) {
            int col = bn + n0 + 8 * j + 2 * (lane & 3);
            float b0v = 0.f, b1v = 0.f;
            if (bias) { b0v = bias[col]; b1v = bias[col + 1]; }
            *(float2*)(C + (size_t)rA * N + col) =
                make_float2(acc[i][j][0] + b0v, acc[i][j][1] + b1v);
            *(float2*)(C + (size_t)(rA + 8) * N + col) =
                make_float2(acc[i][j][2] + b0v, acc[i][j][3] + b1v);
        }
    }
}

// ---------------------------------------------------------------------------
// tensor-core GRU recurrence, 2-plane / 3-term (layers 0/1), 512 threads.
// Output written DIRECTLY as bf16 hi/lo planes (consumed only by bgemm).
// ---------------------------------------------------------------------------
__global__ __launch_bounds__(512, 1)
void k_recur_mma(const float* __restrict__ Gi,
                 __nv_bfloat16* __restrict__ outH, __nv_bfloat16* __restrict__ outL,
                 const __nv_bfloat16* __restrict__ Wh,
                 const __nv_bfloat16* __restrict__ Wl,
                 const float* __restrict__ bhh, const int* __restrict__ nsel) {
    extern __shared__ __nv_bfloat16 smb[];
    float* red = (float*)(smb + MSM_BF);
    int tid = threadIdx.x;
    int bt = blockIdx.x & 3, jt = blockIdx.x >> 2;
    int b0 = bt * 16, j0 = jt * 16;
    int wid = tid >> 5, lane = tid & 31;
    int jj = tid & 15, bb2 = tid >> 4;
    bool ph2 = tid < 256;
    int j2 = j0 + jj;
    int b2 = b0 + (bb2 & 15);

    for (int idx = tid; idx < 48 * 512; idx += 512) {
        int r = idx >> 9, k = idx & 511;
        int g = r >> 4, jl = r & 15;
        size_t grow = (size_t)(g * 512 + j0 + jl) * 512 + k;
        smb[MSM_W  + r * SWS + k] = Wh[grow];
        smb[MSM_WL + r * SWS + k] = Wl[grow];
    }
    float br = bhh[j2], bz = bhh[512 + j2], bn2 = bhh[1024 + j2];
    int lim = ph2 ? nsel[b2] : TT;
    int maxlim = 0;
    #pragma unroll
    for (int b = 0; b < 16; b++) {
        int v = nsel[b0 + b];
        maxlim = v > maxlim ? v : maxlim;
    }
    unsigned* barp = &g_bar4[bt * 32];
    unsigned sbase = (unsigned)__cvta_generic_to_shared(smb);

    int alr = lane & 15, alh = (lane >> 4) * 16;
    int bro = ((lane >> 4) & 1) * 8 + (lane & 7);
    int bko = ((lane >> 3) & 1) * 16;

    __syncthreads();

    for (int t = 0; t < maxlim; t++) {
        float gir = 0.f, giz = 0.f, gin = 0.f;
        if (ph2) {
            const float* gp = Gi + ((size_t)b2 * TT + t) * G3;
            gir = __ldcg(gp + j2);
            giz = __ldcg(gp + 512 + j2);
            gin = __ldcg(gp + 1024 + j2);
        }

        if (t > 0) {
            if (tid == 0) {
                unsigned tgt = 32u * (unsigned)t;
                while (ld_acq(barp) < tgt) { }
            }
            __syncthreads();
        }

        const float* hsrc = g_h[t & 1];
        float hold = 0.f;
        if (ph2) hold = __ldcg(hsrc + (size_t)b2 * HH + j2);
        #pragma unroll
        for (int i = 0; i < 4; i++) {
            int id = tid + i * 512;
            int lb = id >> 7;
            int lk = (id & 127) * 4;
            float4 v = __ldcg((const float4*)(hsrc + (size_t)(b0 + lb) * HH + lk));
            __nv_bfloat162 h01 = __floats2bfloat162_rn(v.x, v.y);
            __nv_bfloat162 h23 = __floats2bfloat162_rn(v.z, v.w);
            __nv_bfloat162 l01 = __floats2bfloat162_rn(v.x - __low2float(h01),
                                                       v.y - __high2float(h01));
            __nv_bfloat162 l23 = __floats2bfloat162_rn(v.z - __low2float(h23),
                                                       v.w - __high2float(h23));
            int off = lb * SWS + lk;
            *(__nv_bfloat162*)&smb[MSM_HH + off]     = h01;
            *(__nv_bfloat162*)&smb[MSM_HH + off + 2] = h23;
            *(__nv_bfloat162*)&smb[MSM_HL + off]     = l01;
            *(__nv_bfloat162*)&smb[MSM_HL + off + 2] = l23;
        }
        __syncthreads();

        if (wid < 12) {
            int gt = wid % 3, kq = wid / 3;
            float acc0[4] = {0.f, 0.f, 0.f, 0.f};
            float acc1[4] = {0.f, 0.f, 0.f, 0.f};
            #pragma unroll
            for (int ks = 0; ks < 8; ks++) {
                int kk = kq * 128 + ks * 16;
                unsigned ah[4], al[4], bh[4], bl[4];
                unsigned ra = sbase + (unsigned)(MSM_HH + alr * SWS + kk) * 2 + alh;
                ldm4(ah, ra);
                ldm4(al, ra + (MSM_HL - MSM_HH) * 2);
                unsigned rb = sbase + (unsigned)((gt * 16 + bro) * SWS + kk) * 2 + bko;
                ldm4(bh, rb);
                ldm4(bl, rb + MSM_WL * 2);
                mma16816(acc0, ah, bh[0], bh[1]);
                mma16816(acc0, ah, bl[0], bl[1]);
                mma16816(acc0, al, bh[0], bh[1]);
                mma16816(acc1, ah, bh[2], bh[3]);
                mma16816(acc1, ah, bl[2], bl[3]);
                mma16816(acc1, al, bh[2], bh[3]);
            }
            int r = lane >> 2, c2 = 2 * (lane & 3);
            float* rp = red + (kq * 16 + r) * MRED_STR + gt * 16;
            *(float2*)(rp + c2)                    = make_float2(acc0[0], acc0[1]);
            *(float2*)(rp + 8 * MRED_STR + c2)     = make_float2(acc0[2], acc0[3]);
            *(float2*)(rp + 8 + c2)                = make_float2(acc1[0], acc1[1]);
            *(float2*)(rp + 8 * MRED_STR + 8 + c2) = make_float2(acc1[2], acc1[3]);
        }
        __syncthreads();

        if (ph2) {
            float sr = br, sz = bz, sn = bn2;
            #pragma unroll
            for (int kq = 0; kq < 4; kq++) {
                const float* rp = red + (kq * 16 + (bb2 & 15)) * MRED_STR;
                sr += rp[jj];
                sz += rp[16 + jj];
                sn += rp[32 + jj];
            }
            float r_ = 1.f / (1.f + expf(-(gir + sr)));
            float z  = 1.f / (1.f + expf(-(giz + sz)));
            float n  = tanhf(gin + r_ * sn);
            float hn = (1.f - z) * n + z * hold;
            bool valid = t < lim;
            g_h[(t + 1) & 1][b2 * HH + j2] = valid ? hn : hold;
            float y = valid ? hn : 0.f;
            __nv_bfloat16 yh = __float2bfloat16(y);
            size_t oidx = ((size_t)b2 * TT + t) * HH + j2;
            outH[oidx] = yh;
            outL[oidx] = __float2bfloat16(y - __bfloat162float(yh));
        }

        __syncthreads();
        if (tid == 0) red_rel(barp);
    }

    if (ph2) {
        __nv_bfloat16 zb = __float2bfloat16(0.f);
        for (int t = maxlim; t < TT; t++) {
            size_t oidx = ((size_t)b2 * TT + t) * HH + j2;
            outH[oidx] = zb;
            outL[oidx] = zb;
        }
    }
}

// ---------------------------------------------------------------------------
// tensor-core GRU recurrence, 3-plane / 6-term (selector), 512 threads.
// ---------------------------------------------------------------------------
__global__ __launch_bounds__(512, 1)
void k_recur_mma3(const float* __restrict__ Gi, float* __restrict__ hist,
                  const __nv_bfloat16* __restrict__ W1,
                  const __nv_bfloat16* __restrict__ W2,
                  const __nv_bfloat16* __restrict__ W3,
                  const float* __restrict__ bhh) {
    extern __shared__ __nv_bfloat16 smb[];
    float* red = (float*)(smb + M3_BF);
    int tid = threadIdx.x;
    int bt = blockIdx.x & 3, jt = blockIdx.x >> 2;
    int b0 = bt * 16, j0 = jt * 16;
    int wid = tid >> 5, lane = tid & 31;
    int jj = tid & 15, bb2 = tid >> 4;
    bool ph2 = tid < 256;
    int j2 = j0 + jj;
    int b2 = b0 + (bb2 & 15);

    for (int idx = tid; idx < 48 * 512; idx += 512) {
        int r = idx >> 9, k = idx & 511;
        int g = r >> 4, jl = r & 15;
        size_t grow = (size_t)(g * 512 + j0 + jl) * 512 + k;
        smb[M3_W1 + r * SWS + k] = W1[grow];
        smb[M3_W2 + r * SWS + k] = W2[grow];
        smb[M3_W3 + r * SWS + k] = W3[grow];
    }
    float br = bhh[j2], bz = bhh[512 + j2], bn2 = bhh[1024 + j2];
    unsigned* barp = &g_bar4[bt * 32];
    unsigned sbase = (unsigned)__cvta_generic_to_shared(smb);

    int alr = lane & 15, alh = (lane >> 4) * 16;
    int bro = ((lane >> 4) & 1) * 8 + (lane & 7);
    int bko = ((lane >> 3) & 1) * 16;

    __syncthreads();

    for (int t = 0; t < TT; t++) {
        float gir = 0.f, giz = 0.f, gin = 0.f;
        if (ph2) {
            const float* gp = Gi + ((size_t)b2 * TT + t) * G3;
            gir = __ldcg(gp + j2);
            giz = __ldcg(gp + 512 + j2);
            gin = __ldcg(gp + 1024 + j2);
        }

        if (t > 0) {
            if (tid == 0) {
                unsigned tgt = 32u * (unsigned)t;
                while (ld_acq(barp) < tgt) { }
            }
            __syncthreads();
        }

        const float* hsrc = g_h[t & 1];
        float hold = 0.f;
        if (ph2) hold = __ldcg(hsrc + (size_t)b2 * HH + j2);
        #pragma unroll
        for (int i = 0; i < 4; i++) {
            int id = tid + i * 512;
            int lb = id >> 7;
            int lk = (id & 127) * 4;
            float4 v = __ldcg((const float4*)(hsrc + (size_t)(b0 + lb) * HH + lk));
            float xs[4] = {v.x, v.y, v.z, v.w};
            __nv_bfloat16 h1[4], h2[4], h3[4];
            #pragma unroll
            for (int c = 0; c < 4; c++) {
                h1[c] = __float2bfloat16(xs[c]);
                float r = xs[c] - __bfloat162float(h1[c]);
                h2[c] = __float2bfloat16(r);
                float r2 = r - __bfloat162float(h2[c]);
                h3[c] = __float2bfloat16(r2);
            }
            int off = lb * SWS + lk;
            *(__nv_bfloat162*)&smb[M3_H1 + off]     = *(__nv_bfloat162*)&h1[0];
            *(__nv_bfloat162*)&smb[M3_H1 + off + 2] = *(__nv_bfloat162*)&h1[2];
            *(__nv_bfloat162*)&smb[M3_H2 + off]     = *(__nv_bfloat162*)&h2[0];
            *(__nv_bfloat162*)&smb[M3_H2 + off + 2] = *(__nv_bfloat162*)&h2[2];
            *(__nv_bfloat162*)&smb[M3_H3 + off]     = *(__nv_bfloat162*)&h3[0];
            *(__nv_bfloat162*)&smb[M3_H3 + off + 2] = *(__nv_bfloat162*)&h3[2];
        }
        __syncthreads();

        if (wid < 12) {
            int gt = wid % 3, kq = wid / 3;
            float acc0[4] = {0.f, 0.f, 0.f, 0.f};
            float acc1[4] = {0.f, 0.f, 0.f, 0.f};
            #pragma unroll
            for (int ks = 0; ks < 8; ks++) {
                int kk = kq * 128 + ks * 16;
                unsigned a1[4], a2[4], a3[4], b1[4], b2[4], b3[4];
                unsigned ra = sbase + (unsigned)(M3_H1 + alr * SWS + kk) * 2 + alh;
                ldm4(a1, ra);
                ldm4(a2, ra + (M3_H2 - M3_H1) * 2);
                ldm4(a3, ra + (M3_H3 - M3_H1) * 2);
                unsigned rb = sbase + (unsigned)((gt * 16 + bro) * SWS + kk) * 2 + bko;
                ldm4(b1, rb);
                ldm4(b2, rb + M3_W2 * 2);
                ldm4(b3, rb + M3_W3 * 2);
                mma16816(acc0, a1, b1[0], b1[1]);
                mma16816(acc0, a1, b2[0], b2[1]);
                mma16816(acc0, a2, b1[0], b1[1]);
                mma16816(acc0, a1, b3[0], b3[1]);
                mma16816(acc0, a2, b2[0], b2[1]);
                mma16816(acc0, a3, b1[0], b1[1]);
                mma16816(acc1, a1, b1[2], b1[3]);
                mma16816(acc1, a1, b2[2], b2[3]);
                mma16816(acc1, a2, b1[2], b1[3]);
                mma16816(acc1, a1, b3[2], b3[3]);
                mma16816(acc1, a2, b2[2], b2[3]);
                mma16816(acc1, a3, b1[2], b1[3]);
            }
            int r = lane >> 2, c2 = 2 * (lane & 3);
            float* rp = red + (kq * 16 + r) * MRED_STR + gt * 16;
            *(float2*)(rp + c2)                    = make_float2(acc0[0], acc0[1]);
            *(float2*)(rp + 8 * MRED_STR + c2)     = make_float2(acc0[2], acc0[3]);
            *(float2*)(rp + 8 + c2)                = make_float2(acc1[0], acc1[1]);
            *(float2*)(rp + 8 * MRED_STR + 8 + c2) = make_float2(acc1[2], acc1[3]);
        }
        __syncthreads();

        if (ph2) {
            float sr = br, sz = bz, sn = bn2;
            #pragma unroll
            for (int kq = 0; kq < 4; kq++) {
                const float* rp = red + (kq * 16 + (bb2 & 15)) * MRED_STR;
                sr += rp[jj];
                sz += rp[16 + jj];
                sn += rp[32 + jj];
            }
            float r_ = 1.f / (1.f + expf(-(gir + sr)));
            float z  = 1.f / (1.f + expf(-(giz + sz)));
            float n  = tanhf(gin + r_ * sn);
            float hn = (1.f - z) * n + z * hold;
            g_h[(t + 1) & 1][b2 * HH + j2] = hn;
            hist[((size_t)b2 * TT + t) * HH + j2] = hn;
        }

        __syncthreads();
        if (tid == 0) red_rel(barp);
    }
}

// ---------------------------------------------------------------------------
__global__ void k_selargmax(const float* __restrict__ hist,
                            const float* __restrict__ Ws,
                            const float* __restrict__ bs) {
    int gw = (blockIdx.x * blockDim.x + threadIdx.x) >> 5;
    int lane = threadIdx.x & 31;
    if (gw >= BB * TT) return;
    const float* h = hist + (size_t)gw * HH;
    float l0 = 0.f, l1 = 0.f;
    #pragma unroll 4
    for (int jv = lane; jv < HH; jv += 32) {
        float hv = h[jv];
        l0 += hv * Ws[jv];
        l1 += hv * Ws[HH + jv];
    }
    #pragma unroll
    for (int o = 16; o; o >>= 1) {
        l0 += __shfl_down_sync(0xffffffffu, l0, o);
        l1 += __shfl_down_sync(0xffffffffu, l1, o);
    }
    if (lane == 0)
        g_sel[gw] = ((l1 + bs[1]) > (l0 + bs[0])) ? 1 : 0;
}

// ---------------------------------------------------------------------------
__global__ void k_fix(const int* __restrict__ mask) {
    int b = blockIdx.x;
    int lane = threadIdx.x;
    int len = 0;
    for (int t = lane; t < TT; t += 32) len += mask[b * TT + t];
    #pragma unroll
    for (int o = 16; o; o >>= 1) len += __shfl_down_sync(0xffffffffu, len, o);
    len = __shfl_sync(0xffffffffu, len, 0);
    int cnt = 0;
    for (int c = 0; c < TT; c += 32) {
        int t = c + lane;
        int s = g_sel[b * TT + t];
        if (t == 0) s = 1;
        if (t == len - 1) s = 1;
        if (t >= len) s = 0;
        unsigned bal = __ballot_sync(0xffffffffu, s);
        int pre = __popc(bal & ((1u << lane) - 1u));
        if (s) g_order[b * TT + cnt + pre] = t;
        cnt += __popc(bal);
    }
    if (lane == 0) g_nsel[b] = cnt;
}

// ---------------------------------------------------------------------------
// gather fused with 2-plane split: planes[b][p][:] = split(emb[b][order[p]][:])
// ---------------------------------------------------------------------------
__global__ void k_gather(const float* __restrict__ emb,
                         __nv_bfloat16* __restrict__ dH,
                         __nv_bfloat16* __restrict__ dL) {
    int row = blockIdx.x;               // b*T + p
    int b = row >> 9, p = row & 511;
    float4 v = make_float4(0.f, 0.f, 0.f, 0.f);
    if (p < g_nsel[b]) {
        int t = g_order[row];
        v = ((const float4*)(emb + ((size_t)b * TT + t) * EE))[threadIdx.x];
    }
    __nv_bfloat162 h01 = __floats2bfloat162_rn(v.x, v.y);
    __nv_bfloat162 h23 = __floats2bfloat162_rn(v.z, v.w);
    __nv_bfloat162 l01 = __floats2bfloat162_rn(v.x - __low2float(h01),
                                               v.y - __high2float(h01));
    __nv_bfloat162 l23 = __floats2bfloat162_rn(v.z - __low2float(h23),
                                               v.w - __high2float(h23));
    size_t off = (size_t)row * EE + threadIdx.x * 4;
    *(__nv_bfloat162*)(dH + off)     = h01;
    *(__nv_bfloat162*)(dH + off + 2) = h23;
    *(__nv_bfloat162*)(dL + off)     = l01;
    *(__nv_bfloat162*)(dL + off + 2) = l23;
}

// ---------------------------------------------------------------------------
// pool with exact nsel row-guard (U rows >= nsel are exact zeros; skipped
// tiles of U are never read).
// ---------------------------------------------------------------------------
__global__ void k_pool(const float* __restrict__ U, const float* __restrict__ bc,
                       int kw, int Nn, int seg) {
    int b = blockIdx.x;
    int f = threadIdx.x;
    int tlim = TT - kw + 1;
    int ns = g_nsel[b];
    int tcap = ns < tlim ? ns : tlim;
    int t0 = blockIdx.y * 64;
    int t1 = t0 + 64 < tlim ? t0 + 64 : tlim;
    float bcv = bc[f];
    float m = 0.f;
    if (t1 > tcap) m = fmaxf(bcv, 0.f);       // all-zero windows contribute relu(bc)
    int t1c = t1 < tcap ? t1 : tcap;
    const float* Ub = U + (size_t)b * TT * Nn + (size_t)f * kw;
    for (int t = t0; t < t1c; t++) {
        float s = bcv;
        int dtmax = ns - t; if (dtmax > kw) dtmax = kw;
        for (int dt = 0; dt < dtmax; dt++)
            s += Ub[(size_t)(t + dt) * Nn + dt];
        m = fmaxf(m, fmaxf(s, 0.f));
    }
    atomicMax((int*)&g_pooled[b * (3 * NF) + seg + f], __float_as_int(m));
}

// ---------------------------------------------------------------------------
__global__ void k_final(const float* __restrict__ Wo, const float* __restrict__ bo,
                        float* __restrict__ out) {
    __shared__ float redf[256];
    int b = blockIdx.x, tid = threadIdx.x;
    float s = 0.f;
    for (int f = tid; f < 3 * NF; f += 256)
        s += g_pooled[b * (3 * NF) + f] * Wo[f];
    redf[tid] = s;
    __syncthreads();
    for (int o = 128; o; o >>= 1) {
        if (tid < o) redf[tid] += redf[tid + o];
        __syncthreads();
    }
    if (tid == 0) out[b] = redf[0] + bo[0];
}

// ---------------------------------------------------------------------------
extern "C" void kernel_launch(void* const* d_in, const int* in_sizes, int n_in,
                              void* d_out, int out_size) {
    const float* emb   = (const float*)d_in[0];
    const int*   mask  = (const int*)  d_in[1];
    const float* Wih_c = (const float*)d_in[2];
    const float* Whh_c = (const float*)d_in[3];
    const float* bih_c = (const float*)d_in[4];
    const float* bhh_c = (const float*)d_in[5];
    const float* Ws    = (const float*)d_in[6];
    const float* bs    = (const float*)d_in[7];
    const float* Wih0  = (const float*)d_in[8];
    const float* Whh0  = (const float*)d_in[9];
    const float* bih0  = (const float*)d_in[10];
    const float* bhh0  = (const float*)d_in[11];
    const float* Wih1  = (const float*)d_in[12];
    const float* Whh1  = (const float*)d_in[13];
    const float* bih1  = (const float*)d_in[14];
    const float* bhh1  = (const float*)d_in[15];
    const float* Wc3   = (const float*)d_in[16];
    const float* bc3   = (const float*)d_in[17];
    const float* Wc4   = (const float*)d_in[18];
    const float* bc4   = (const float*)d_in[19];
    const float* Wc5   = (const float*)d_in[20];
    const float* bc5   = (const float*)d_in[21];
    const float* Wo    = (const float*)d_in[22];
    const float* bo    = (const float*)d_in[23];
    float* out = (float*)d_out;

    cudaFuncSetAttribute(k_recur_mma, cudaFuncAttributeMaxDynamicSharedMemorySize,
                         MSM_BYTES);
    cudaFuncSetAttribute(k_recur_mma3, cudaFuncAttributeMaxDynamicSharedMemorySize,
                         M3_BYTES);
    cudaFuncSetAttribute(k_bgemm, cudaFuncAttributeMaxDynamicSharedMemorySize,
                         BSM_BYTES);
    cudaFuncSetAttribute(k_bgemm3, cudaFuncAttributeMaxDynamicSharedMemorySize,
                         BSM3_BYTES);

    float *pGi, *pS0, *pU;
    int* pNsel;
    __nv_bfloat16 *pAh, *pAl, *pA3, *pWh, *pWl, *pW3;
    cudaGetSymbolAddress((void**)&pGi,   g_Gi);
    cudaGetSymbolAddress((void**)&pS0,   g_seq0);
    cudaGetSymbolAddress((void**)&pU,    g_U);
    cudaGetSymbolAddress((void**)&pNsel, g_nsel);
    cudaGetSymbolAddress((void**)&pAh,   g_Ah);
    cudaGetSymbolAddress((void**)&pAl,   g_Al);
    cudaGetSymbolAddress((void**)&pA3,   g_A3);
    cudaGetSymbolAddress((void**)&pWh,   g_Wh);
    cudaGetSymbolAddress((void**)&pWl,   g_Wl);
    cudaGetSymbolAddress((void**)&pW3,   g_W3);

    const size_t nAE = (size_t)MALL * EE;

    // ---- selector GRU: 3-plane/6-term bf16 tensor path (near-fp32 exact) ----
    k_split3<<<(int)((nAE + 255)/256), 256>>>(emb, pAh, pAl, pA3, nAE);
    k_split3<<<(G3*EE + 255)/256, 256>>>(Wih_c, pWh, pWl, pW3, (size_t)G3*EE);
    k_bgemm3<<<dim3(G3/128, MALL/128), 256, BSM3_BYTES>>>(
        pGi, pAh, pAl, pA3, pWh, pWl, pW3, bih_c, MALL, G3, EE);
    k_split3<<<(G3*HH + 255)/256, 256>>>(Whh_c, pWh, pWl, pW3, (size_t)G3*HH);
    k_reset<<<256, 256>>>();
    k_recur_mma3<<<NBLK, 512, M3_BYTES>>>(pGi, pS0, pWh, pWl, pW3, bhh_c);
    k_selargmax<<<(BB*TT*32 + 255)/256, 256>>>(pS0, Ws, bs);
    k_fix<<<BB, 32>>>(mask);
    // gather fused with split -> planes (overwrites selector A planes, done)
    k_gather<<<MALL, EE/4>>>(emb, pAh, pAl);

    // ---- layer 0: bgemm on gathered planes, recurrence emits planes ----
    k_split<<<(G3*EE + 255)/256, 256>>>(Wih0, pWh, pWl, (size_t)G3*EE);
    k_bgemm<<<dim3(G3/128, MALL/128), 256, BSM_BYTES>>>(
        pGi, pAh, pAl, pWh, pWl, bih0, MALL, G3, EE, pNsel, 1);
    k_split<<<(G3*HH + 255)/256, 256>>>(Whh0, pWh, pWl, (size_t)G3*HH);
    k_reset<<<256, 256>>>();
    k_recur_mma<<<NBLK, 512, MSM_BYTES>>>(pGi, pAh, pAl, pWh, pWl, bhh0, pNsel);

    // ---- layer 1 ----
    k_split<<<(G3*HH + 255)/256, 256>>>(Wih1, pWh, pWl, (size_t)G3*HH);
    k_bgemm<<<dim3(G3/128, MALL/128), 256, BSM_BYTES>>>(
        pGi, pAh, pAl, pWh, pWl, bih1, MALL, G3, HH, pNsel, 1);
    k_split<<<(G3*HH + 255)/256, 256>>>(Whh1, pWh, pWl, (size_t)G3*HH);
    k_reset<<<256, 256>>>();
    k_recur_mma<<<NBLK, 512, MSM_BYTES>>>(pGi, pAh, pAl, pWh, pWl, bhh1, pNsel);

    // ---- convs (bgemm on out1 planes, skip tiles; pool guards rows) ----
    k_zero_pooled<<<(BB*3*NF + 255)/256, 256>>>();

    k_split<<<(NF*3*HH + 255)/256, 256>>>(Wc3, pWh, pWl, (size_t)NF*3*HH);
    k_bgemm<<<dim3((NF*3)/128, MALL/128), 256, BSM_BYTES>>>(
        pU, pAh, pAl, pWh, pWl, nullptr, MALL, NF*3, HH, pNsel, 1);
    k_pool<<<dim3(BB, 8), NF>>>(pU, bc3, 3, NF*3, 0);

    k_split<<<(NF*4*HH + 255)/256, 256>>>(Wc4, pWh, pWl, (size_t)NF*4*HH);
    k_bgemm<<<dim3((NF*4)/128, MALL/128), 256, BSM_BYTES>>>(
        pU, pAh, pAl, pWh, pWl, nullptr, MALL, NF*4, HH, pNsel, 1);
    k_pool<<<dim3(BB, 8), NF>>>(pU, bc4, 4, NF*4, NF);

    k_split<<<(NF*5*HH + 255)/256, 256>>>(Wc5, pWh, pWl, (size_t)NF*5*HH);
    k_bgemm<<<dim3((NF*5)/128, MALL/128), 256, BSM_BYTES>>>(
        pU, pAh, pAl, pWh, pWl, nullptr, MALL, NF*5, HH, pNsel, 1);
    k_pool<<<dim3(BB, 8), NF>>>(pU, bc5, 5, NF*5, 2*NF);

    // ---- final projection ----
    k_final<<<BB, 256>>>(Wo, bo, out);
}